// round 5
// baseline (speedup 1.0000x reference)
#include <cuda_runtime.h>
#include <math.h>

#define NN 50000
#define EE 800000
#define DD 96
#define HIDN 128
#define OUTN 8
#define NBS 196   // scan blocks = ceil(NN/256)
#define ESTR 108  // padded smem row stride (floats) for conflict-free mma feeds
#define RSTR 97   // phase-2 reduction stride

typedef unsigned long long ull;

// ------------------------- device scratch (no allocs allowed) ----------------
__device__ float g_h[(size_t)NN * DD];
__device__ float g_hnew[(size_t)NN * DD];
__device__ float g_ABDE[(size_t)4 * NN * DD];   // A,B,D,E
__device__ float g_e[(size_t)EE * DD];          // permuted (CSR dst order)
__device__ float g_enew[(size_t)EE * DD];       // permuted
__device__ float g_num[(size_t)NN * DD];
__device__ float g_den[(size_t)NN * DD];
__device__ int   g_cnt[NN];
__device__ int   g_ptr[NN + 1];
__device__ int   g_woff[NN];
__device__ int   g_eid[EE];
__device__ int   g_srcp[EE];
__device__ int   g_dstp[EE];
__device__ int   g_bsum[256];
__device__ int   g_boff[256];
__device__ double g_esum[DD], g_esq[DD], g_hsum[DD], g_hsq[DD];
__device__ float g_escale[DD], g_eshift[DD], g_hscale[DD], g_hshift[DD];

// ------------------------- packed f32x2 helpers ------------------------------
__device__ __forceinline__ ull pk2(float lo, float hi) {
    ull r; asm("mov.b64 %0,{%1,%2};" : "=l"(r) : "f"(lo), "f"(hi)); return r;
}
__device__ __forceinline__ ull fma2(ull a, ull b, ull c) {
    ull d; asm("fma.rn.f32x2 %0,%1,%2,%3;" : "=l"(d) : "l"(a), "l"(b), "l"(c)); return d;
}
__device__ __forceinline__ float2 upk(ull v) {
    float2 f; asm("mov.b64 {%0,%1},%2;" : "=f"(f.x), "=f"(f.y) : "l"(v)); return f;
}
__device__ __forceinline__ float tf32r(float x) {
    unsigned u; asm("cvt.rna.tf32.f32 %0,%1;" : "=r"(u) : "f"(x));
    return __uint_as_float(u);
}
#define MMA_TF32(d, a, b0_, b1_) \
    asm volatile("mma.sync.aligned.m16n8k8.row.col.f32.tf32.tf32.f32 " \
        "{%0,%1,%2,%3},{%4,%5,%6,%7},{%8,%9},{%0,%1,%2,%3};" \
        : "+f"(d[0]), "+f"(d[1]), "+f"(d[2]), "+f"(d[3]) \
        : "r"(a[0]), "r"(a[1]), "r"(a[2]), "r"(a[3]), "r"(b0_), "r"(b1_))

// ------------------------- setup kernels -------------------------------------
__global__ void k_zero() {
    int i = blockIdx.x * blockDim.x + threadIdx.x;
    if (i < NN * DD) { g_num[i] = 0.f; g_den[i] = 0.f; }
    if (i < NN) g_cnt[i] = 0;
    if (i < DD) { g_esum[i] = 0.0; g_esq[i] = 0.0; g_hsum[i] = 0.0; g_hsq[i] = 0.0; }
}

__global__ void k_embed_h(const float* __restrict__ h1, const float* __restrict__ h2,
                          const float* __restrict__ z,
                          const float* __restrict__ W, const float* __restrict__ b) {
    __shared__ float Ws[26 * DD];
    int t = threadIdx.x;
    for (int i = t; i < 26 * DD; i += blockDim.x) Ws[i] = W[i];
    __syncthreads();
    int idx = blockIdx.x * blockDim.x + t;
    if (idx >= NN * DD) return;
    int r = idx / DD, c = idx - (idx / DD) * DD;
    float acc = b[c];
#pragma unroll
    for (int k = 0; k < 6; k++)  acc += h1[r * 6 + k]  * Ws[k * DD + c];
#pragma unroll
    for (int k = 0; k < 4; k++)  acc += h2[r * 4 + k]  * Ws[(6 + k) * DD + c];
#pragma unroll
    for (int k = 0; k < 16; k++) acc += z[r * 16 + k]  * Ws[(10 + k) * DD + c];
    g_h[idx] = acc;
}

// ------------------------- CSR build (deterministic, parallel scan) -----------
__global__ void k_count(const int* __restrict__ dst) {
    int i = blockIdx.x * blockDim.x + threadIdx.x;
    if (i < EE) atomicAdd(&g_cnt[dst[i]], 1);
}

__global__ void k_scan1() {
    __shared__ int sh[256];
    int t = threadIdx.x, b = blockIdx.x;
    int j = b * 256 + t;
    int v = (j < NN) ? g_cnt[j] : 0;
    sh[t] = v; __syncthreads();
    for (int off = 1; off < 256; off <<= 1) {
        int u = (t >= off) ? sh[t - off] : 0;
        __syncthreads();
        sh[t] += u;
        __syncthreads();
    }
    if (j < NN) g_ptr[j] = sh[t] - v;
    if (t == 255) g_bsum[b] = sh[t];
}

__global__ void k_scan2() {
    __shared__ int sh[256];
    int t = threadIdx.x;
    int v = (t < NBS) ? g_bsum[t] : 0;
    sh[t] = v; __syncthreads();
    for (int off = 1; off < 256; off <<= 1) {
        int u = (t >= off) ? sh[t - off] : 0;
        __syncthreads();
        sh[t] += u;
        __syncthreads();
    }
    g_boff[t] = sh[t] - v;
}

__global__ void k_scan3() {
    int j = blockIdx.x * blockDim.x + threadIdx.x;
    if (j < NN) {
        int p = g_ptr[j] + g_boff[j >> 8];
        g_ptr[j] = p; g_woff[j] = p;
    }
    if (j == 0) g_ptr[NN] = EE;
}

__global__ void k_fill(const int* __restrict__ dst) {
    int i = blockIdx.x * blockDim.x + threadIdx.x;
    if (i < EE) {
        int pos = atomicAdd(&g_woff[dst[i]], 1);
        g_eid[pos] = i;
    }
}

__global__ void k_sortseg() {
    int v = blockIdx.x * blockDim.x + threadIdx.x;
    if (v >= NN) return;
    int lo = g_ptr[v], hi = g_ptr[v + 1];
    for (int i = lo + 1; i < hi; i++) {
        int key = g_eid[i]; int j = i - 1;
        while (j >= lo && g_eid[j] > key) { g_eid[j + 1] = g_eid[j]; j--; }
        g_eid[j + 1] = key;
    }
}

// Embed edges directly into permuted (CSR) order; also build permuted src/dst.
__global__ __launch_bounds__(256) void k_embed_e_perm(const float* __restrict__ ef,
                                                      const int* __restrict__ src,
                                                      const int* __restrict__ dst,
                                                      const float* __restrict__ W,
                                                      const float* __restrict__ b) {
    __shared__ float Ws[4 * DD], bs[DD];
    int t = threadIdx.x;
    for (int i = t; i < 4 * DD; i += 256) Ws[i] = W[i];
    if (t < DD) bs[t] = b[t];
    __syncthreads();
    int w = t >> 5, ln = t & 31;
    int p = blockIdx.x * 8 + w;        // grid = EE/8 exact
    int ei = g_eid[p];
    float4 f = *(const float4*)(ef + (size_t)ei * 4);
    if (ln == 0) g_srcp[p] = src[ei];
    if (ln == 1) g_dstp[p] = dst[ei];
#pragma unroll
    for (int j = 0; j < 3; j++) {
        int c = ln + j * 32;
        g_e[(size_t)p * DD + c] = bs[c] + f.x * Ws[c] + f.y * Ws[DD + c]
                                 + f.z * Ws[2 * DD + c] + f.w * Ws[3 * DD + c];
    }
}

// ------------------------- fused node GEMM: [A|B|D|E] = h @ Wcat + bcat -------
// (Round-2 proven shape: 32 rows/block, 8x4 per-thread tile, 384 threads.)
// Lazily applies h += relu(bn(hnew)) from the previous layer (writes g_h).
__global__ __launch_bounds__(384) void k_matABDE(const float* __restrict__ WA_,
                                                 const float* __restrict__ WB_,
                                                 const float* __restrict__ WD_,
                                                 const float* __restrict__ WE_,
                                                 const float* __restrict__ bA_,
                                                 const float* __restrict__ bB_,
                                                 const float* __restrict__ bD_,
                                                 const float* __restrict__ bE_,
                                                 int apply) {
    extern __shared__ float dyn[];
    float* Ws = dyn;                    // [96][384] concat
    float* Xs = dyn + DD * 384;         // [32][96]
    float* Bs = Xs + 32 * DD;           // [384]
    int t = threadIdx.x;
    const float* wsrc[4] = {WA_, WB_, WD_, WE_};
    const float* bsrc[4] = {bA_, bB_, bD_, bE_};
#pragma unroll
    for (int m = 0; m < 4; m++) {
        for (int i = t; i < DD * DD; i += 384) {
            int k = i / DD, c = i - k * DD;
            Ws[k * 384 + m * DD + c] = wsrc[m][i];
        }
        if (t < DD) Bs[m * DD + t] = bsrc[m][t];
    }
    int row0 = blockIdx.x * 32;
    for (int i = t; i < 32 * 24; i += 384) {
        int r = i / 24, c4 = (i - (i / 24) * 24) * 4;
        int gr = row0 + r;
        float4 v = make_float4(0.f, 0.f, 0.f, 0.f);
        if (gr < NN) {
            size_t idx = (size_t)gr * DD + c4;
            v = *(const float4*)(g_h + idx);
            if (apply) {
                float4 en = *(const float4*)(g_hnew + idx);
                float4 sc = *(const float4*)(g_hscale + c4);
                float4 sh = *(const float4*)(g_hshift + c4);
                v.x += fmaxf(sc.x * en.x + sh.x, 0.f);
                v.y += fmaxf(sc.y * en.y + sh.y, 0.f);
                v.z += fmaxf(sc.z * en.z + sh.z, 0.f);
                v.w += fmaxf(sc.w * en.w + sh.w, 0.f);
                *(float4*)(g_h + idx) = v;
            }
        }
        *(float4*)(Xs + r * DD + c4) = v;
    }
    __syncthreads();
    int cg = t % 96, rg = t / 96;
    int c0 = cg * 4, r0 = rg * 8;
    ull acc[8][2];
    ull b01 = pk2(Bs[c0], Bs[c0 + 1]), b23 = pk2(Bs[c0 + 2], Bs[c0 + 3]);
#pragma unroll
    for (int r = 0; r < 8; r++) { acc[r][0] = b01; acc[r][1] = b23; }
#pragma unroll 6
    for (int k = 0; k < DD; k += 2) {
        ulonglong2 w0 = *(const ulonglong2*)(Ws + k * 384 + c0);
        ulonglong2 w1 = *(const ulonglong2*)(Ws + (k + 1) * 384 + c0);
#pragma unroll
        for (int r = 0; r < 8; r++) {
            float2 x = *(const float2*)(Xs + (r0 + r) * DD + k);
            ull x0 = pk2(x.x, x.x), x1 = pk2(x.y, x.y);
            acc[r][0] = fma2(x0, w0.x, acc[r][0]);
            acc[r][1] = fma2(x0, w0.y, acc[r][1]);
            acc[r][0] = fma2(x1, w1.x, acc[r][0]);
            acc[r][1] = fma2(x1, w1.y, acc[r][1]);
        }
    }
    int m = c0 / DD, cc = c0 - m * DD;
    float* outp = g_ABDE + (size_t)m * NN * DD;
#pragma unroll
    for (int r = 0; r < 8; r++) {
        int gr = row0 + r0 + r;
        if (gr < NN) {
            float2 a = upk(acc[r][0]), q = upk(acc[r][1]);
            *(float4*)(outp + (size_t)gr * DD + cc) = make_float4(a.x, a.y, q.x, q.y);
        }
    }
}

// ------------------------- edge kernel: tf32 MMA + fused aggregation ----------
// 128 edges/block, 8 warps; warp w owns 32 edges x 48 cols (2 m16 x 6 n8 tiles).
// e_new = tf32mma(e, WC) + bC + Dh[src] + Eh[dst]; lazy BN apply on staging;
// epilogue computes sigmoid gates and segment-reduces num/den by dst (CSR order).
__global__ __launch_bounds__(256) void k_edge(const float* __restrict__ W,
                                              const float* __restrict__ b,
                                              int apply, int write_e, int do_stats,
                                              int write_enew) {
    extern __shared__ float dyn[];
    float* Ws = dyn;                  // [96][ESTR]   (phase 1)
    float* Es = dyn + DD * ESTR;      // [128][ESTR]  (phase 1)
    float* Ssig = dyn;                // [128][RSTR]  (phase 2, aliases Ws/Es)
    float* Snb  = dyn + 128 * RSTR;   // [128][RSTR]
    __shared__ float s_sum[DD], s_sq[DD], bsh[DD];
    __shared__ int s_src[128], s_dst[128];
    int t = threadIdx.x;
    int lane = t & 31, w = t >> 5;
    if (t < DD) { s_sum[t] = 0.f; s_sq[t] = 0.f; bsh[t] = b[t]; }
    // stage W, rounded to tf32
    for (int i = t; i < DD * 24; i += 256) {
        int k = i / 24, c4 = (i - (i / 24) * 24) * 4;
        float4 v = *(const float4*)(W + k * DD + c4);
        v.x = tf32r(v.x); v.y = tf32r(v.y); v.z = tf32r(v.z); v.w = tf32r(v.w);
        *(float4*)(Ws + k * ESTR + c4) = v;
    }
    int ebase = blockIdx.x * 128;   // EE % 128 == 0
    if (t < 128) { s_src[t] = g_srcp[ebase + t]; s_dst[t] = g_dstp[ebase + t]; }
    // stage e with lazy BN apply; keep f32 in gmem, tf32-rounded copy in smem
    for (int i = t; i < 128 * 24; i += 256) {
        int r = i / 24, c4 = (i - (i / 24) * 24) * 4;
        size_t idx = (size_t)(ebase + r) * DD + c4;
        float4 v = *(const float4*)(g_e + idx);
        if (apply) {
            float4 en = *(const float4*)(g_enew + idx);
            float4 sc = *(const float4*)(g_escale + c4);
            float4 sh = *(const float4*)(g_eshift + c4);
            v.x += fmaxf(sc.x * en.x + sh.x, 0.f);
            v.y += fmaxf(sc.y * en.y + sh.y, 0.f);
            v.z += fmaxf(sc.z * en.z + sh.z, 0.f);
            v.w += fmaxf(sc.w * en.w + sh.w, 0.f);
            if (write_e) *(float4*)(g_e + idx) = v;
        }
        v.x = tf32r(v.x); v.y = tf32r(v.y); v.z = tf32r(v.z); v.w = tf32r(v.w);
        *(float4*)(Es + r * ESTR + c4) = v;
    }
    __syncthreads();

    int mg = w >> 1, ng = w & 1;
    int m0 = mg * 32, n0 = ng * 48;
    int g = lane >> 2, c4 = lane & 3;
    float acc[2][6][4];
#pragma unroll
    for (int i = 0; i < 2; i++)
#pragma unroll
        for (int j = 0; j < 6; j++)
#pragma unroll
            for (int q = 0; q < 4; q++) acc[i][j][q] = 0.f;

#pragma unroll
    for (int k0 = 0; k0 < DD; k0 += 8) {
        unsigned a[2][4];
#pragma unroll
        for (int i = 0; i < 2; i++) {
            int rr = (m0 + i * 16 + g) * ESTR;
            a[i][0] = __float_as_uint(Es[rr + k0 + c4]);
            a[i][1] = __float_as_uint(Es[rr + 8 * ESTR + k0 + c4]);
            a[i][2] = __float_as_uint(Es[rr + k0 + 4 + c4]);
            a[i][3] = __float_as_uint(Es[rr + 8 * ESTR + k0 + 4 + c4]);
        }
#pragma unroll
        for (int j = 0; j < 6; j++) {
            int col = n0 + 8 * j + g;
            unsigned b0 = __float_as_uint(Ws[(k0 + c4) * ESTR + col]);
            unsigned b1 = __float_as_uint(Ws[(k0 + 4 + c4) * ESTR + col]);
            MMA_TF32(acc[0][j], a[0], b0, b1);
            MMA_TF32(acc[1][j], a[1], b0, b1);
        }
    }
    __syncthreads();   // all warps done reading Ws/Es before phase-2 overwrite

    // epilogue: bias + gathers -> v; write enew; sigmoid -> Ssig/Snb; BN-e stats
    const float* Bh = g_ABDE + (size_t)1 * NN * DD;
    const float* Dh = g_ABDE + (size_t)2 * NN * DD;
    const float* Eh = g_ABDE + (size_t)3 * NN * DD;
    float cs[6][2], cq[6][2];
#pragma unroll
    for (int j = 0; j < 6; j++) { cs[j][0] = cs[j][1] = 0.f; cq[j][0] = cq[j][1] = 0.f; }
#pragma unroll
    for (int i = 0; i < 2; i++) {
#pragma unroll
        for (int half = 0; half < 2; half++) {
            int rl = m0 + i * 16 + half * 8 + g;
            size_t sb = (size_t)s_src[rl] * DD;
            size_t db = (size_t)s_dst[rl] * DD;
            size_t ob = (size_t)(ebase + rl) * DD;
#pragma unroll
            for (int j = 0; j < 6; j++) {
                int col = n0 + 8 * j + 2 * c4;
                float2 bh = *(const float2*)(Bh + sb + col);
                float2 dh = *(const float2*)(Dh + sb + col);
                float2 eh = *(const float2*)(Eh + db + col);
                float v0 = acc[i][j][half * 2 + 0] + bsh[col]     + dh.x + eh.x;
                float v1 = acc[i][j][half * 2 + 1] + bsh[col + 1] + dh.y + eh.y;
                if (write_enew) *(float2*)(g_enew + ob + col) = make_float2(v0, v1);
                cs[j][0] += v0; cs[j][1] += v1;
                cq[j][0] += v0 * v0; cq[j][1] += v1 * v1;
                float s0 = __fdividef(1.f, 1.f + __expf(-v0));
                float s1 = __fdividef(1.f, 1.f + __expf(-v1));
                Ssig[rl * RSTR + col] = s0;
                Ssig[rl * RSTR + col + 1] = s1;
                Snb[rl * RSTR + col] = s0 * bh.x;
                Snb[rl * RSTR + col + 1] = s1 * bh.y;
            }
        }
    }
    if (do_stats) {
#pragma unroll
        for (int off = 16; off >= 4; off >>= 1) {
#pragma unroll
            for (int j = 0; j < 6; j++) {
#pragma unroll
                for (int p = 0; p < 2; p++) {
                    cs[j][p] += __shfl_down_sync(0xffffffffu, cs[j][p], off);
                    cq[j][p] += __shfl_down_sync(0xffffffffu, cq[j][p], off);
                }
            }
        }
        if (lane < 4) {
#pragma unroll
            for (int j = 0; j < 6; j++) {
#pragma unroll
                for (int p = 0; p < 2; p++) {
                    int col = n0 + 8 * j + 2 * lane + p;
                    atomicAdd(&s_sum[col], cs[j][p]);
                    atomicAdd(&s_sq[col], cq[j][p]);
                }
            }
        }
    }
    __syncthreads();

    // phase 2: segmented reduction of num/den over the block's dst runs
    if (t < 192) {
        int c = (t < 96) ? t : t - 96;
        int r = (t < 96) ? 0 : 64;
        int rend = r + 64;
        int cur = s_dst[r];
        float an = 0.f, ad = 0.f;
        for (; r < rend; r++) {
            int d = s_dst[r];
            if (d != cur) {
                atomicAdd(&g_num[(size_t)cur * DD + c], an);
                atomicAdd(&g_den[(size_t)cur * DD + c], ad);
                an = 0.f; ad = 0.f; cur = d;
            }
            an += Snb[r * RSTR + c];
            ad += Ssig[r * RSTR + c];
        }
        atomicAdd(&g_num[(size_t)cur * DD + c], an);
        atomicAdd(&g_den[(size_t)cur * DD + c], ad);
    }
    if (do_stats && t < DD) {
        atomicAdd(&g_esum[t], (double)s_sum[t]);
        atomicAdd(&g_esq[t], (double)s_sq[t]);
    }
}

// ------------------------- node update: h_new = Ah + num/den, BN-h stats ------
__global__ __launch_bounds__(256) void k_nodeupd() {
    __shared__ float ssum[DD], ssq[DD];
    int t = threadIdx.x;
    if (t < DD) { ssum[t] = 0.f; ssq[t] = 0.f; }
    __syncthreads();
    int idx = blockIdx.x * 256 + t;      // NN*DD divisible by 256
    int c = idx % DD;
    float num = g_num[idx], den = g_den[idx];
    float h = g_ABDE[idx] + __fdividef(num, den + 1e-6f);
    g_hnew[idx] = h;
    g_num[idx] = 0.f; g_den[idx] = 0.f;   // ready for next layer
    atomicAdd(&ssum[c], h);
    atomicAdd(&ssq[c], h * h);
    __syncthreads();
    if (t < DD) {
        atomicAdd(&g_hsum[t], (double)ssum[t]);
        atomicAdd(&g_hsq[t], (double)ssq[t]);
    }
}

// ------------------------- BN finalize ----------------------------------------
__global__ void k_finalize(const float* __restrict__ gamma, const float* __restrict__ beta,
                           double count, int which) {
    int c = threadIdx.x;
    if (c >= DD) return;
    double s, q;
    if (which == 0) { s = g_esum[c]; q = g_esq[c]; g_esum[c] = 0.0; g_esq[c] = 0.0; }
    else            { s = g_hsum[c]; q = g_hsq[c]; g_hsum[c] = 0.0; g_hsq[c] = 0.0; }
    double m = s / count;
    double var = q / count - m * m;
    float sc = gamma[c] * rsqrtf((float)var + 1e-5f);
    float sh = beta[c] - (float)m * sc;
    if (which == 0) { g_escale[c] = sc; g_eshift[c] = sh; }
    else            { g_hscale[c] = sc; g_hshift[c] = sh; }
}

// ------------------------- head: relu(h@W1+b1)@W2+b2, tanh, scale -------------
__global__ __launch_bounds__(256) void k_head(const float* __restrict__ W1,
                                              const float* __restrict__ b1,
                                              const float* __restrict__ W2,
                                              const float* __restrict__ b2,
                                              const float* __restrict__ maxa,
                                              float* __restrict__ out) {
    extern __shared__ float dyn[];
    float* W1s = dyn;                 // 96*128
    float* Hs  = W1s + DD * HIDN;     // 32*96
    float* His = Hs + 32 * DD;        // 32*132 (padded)
    float* W2s = His + 32 * 132;      // 128*8
    int t = threadIdx.x;
    for (int i = t; i < DD * HIDN; i += 256) W1s[i] = W1[i];
    for (int i = t; i < HIDN * OUTN; i += 256) W2s[i] = W2[i];
    int row0 = blockIdx.x * 32;
    for (int i = t; i < 32 * 24; i += 256) {
        int r = i / 24, c4 = (i - (i / 24) * 24) * 4;
        int gr = row0 + r;
        float4 v = make_float4(0.f, 0.f, 0.f, 0.f);
        if (gr < NN) {
            size_t idx = (size_t)gr * DD + c4;
            v = *(const float4*)(g_h + idx);
            float4 en = *(const float4*)(g_hnew + idx);
            float4 sc = *(const float4*)(g_hscale + c4);
            float4 sh = *(const float4*)(g_hshift + c4);
            v.x += fmaxf(sc.x * en.x + sh.x, 0.f);
            v.y += fmaxf(sc.y * en.y + sh.y, 0.f);
            v.z += fmaxf(sc.z * en.z + sh.z, 0.f);
            v.w += fmaxf(sc.w * en.w + sh.w, 0.f);
        }
        *(float4*)(Hs + r * DD + c4) = v;
    }
    __syncthreads();
    {
        int ng = t >> 5, hg = t & 31;
        int r0 = ng * 4, c0 = hg * 4;
        ull acc[4][2];
        float4 bv = *(const float4*)(b1 + c0);
        ull b01 = pk2(bv.x, bv.y), b23 = pk2(bv.z, bv.w);
#pragma unroll
        for (int r = 0; r < 4; r++) { acc[r][0] = b01; acc[r][1] = b23; }
#pragma unroll 4
        for (int k = 0; k < DD; k++) {
            ulonglong2 wv = *(const ulonglong2*)(W1s + k * HIDN + c0);
#pragma unroll
            for (int r = 0; r < 4; r++) {
                float x = Hs[(r0 + r) * DD + k];
                ull xx = pk2(x, x);
                acc[r][0] = fma2(xx, wv.x, acc[r][0]);
                acc[r][1] = fma2(xx, wv.y, acc[r][1]);
            }
        }
#pragma unroll
        for (int r = 0; r < 4; r++) {
            float2 a = upk(acc[r][0]), q = upk(acc[r][1]);
            His[(r0 + r) * 132 + c0 + 0] = fmaxf(a.x, 0.f);
            His[(r0 + r) * 132 + c0 + 1] = fmaxf(a.y, 0.f);
            His[(r0 + r) * 132 + c0 + 2] = fmaxf(q.x, 0.f);
            His[(r0 + r) * 132 + c0 + 3] = fmaxf(q.y, 0.f);
        }
    }
    __syncthreads();
    {
        int node = t >> 3, oc = t & 7;
        int gn = row0 + node;
        if (gn < NN) {
            float acc = b2[oc];
#pragma unroll 8
            for (int k = 0; k < HIDN; k++) acc += His[node * 132 + k] * W2s[k * OUTN + oc];
            out[(size_t)gn * OUTN + oc] = maxa[gn] * tanhf(acc);
        }
    }
}

// ------------------------- launch ---------------------------------------------
extern "C" void kernel_launch(void* const* d_in, const int* in_sizes, int n_in,
                              void* d_out, int out_size) {
    const float* h1      = (const float*)d_in[0];
    const float* h2      = (const float*)d_in[1];
    const float* z       = (const float*)d_in[2];
    const float* efeat   = (const float*)d_in[3];
    const float* maxa    = (const float*)d_in[4];
    const float* Wh_emb  = (const float*)d_in[5];
    const float* bh_emb  = (const float*)d_in[6];
    const float* We_emb  = (const float*)d_in[7];
    const float* be_emb  = (const float*)d_in[8];
    const float* WA      = (const float*)d_in[9];
    const float* bA      = (const float*)d_in[10];
    const float* WB      = (const float*)d_in[11];
    const float* bB      = (const float*)d_in[12];
    const float* WC      = (const float*)d_in[13];
    const float* bC      = (const float*)d_in[14];
    const float* WD      = (const float*)d_in[15];
    const float* bD      = (const float*)d_in[16];
    const float* WE      = (const float*)d_in[17];
    const float* bE      = (const float*)d_in[18];
    const float* bn_h_g  = (const float*)d_in[19];
    const float* bn_h_b  = (const float*)d_in[20];
    const float* bn_e_g  = (const float*)d_in[21];
    const float* bn_e_b  = (const float*)d_in[22];
    const float* W1      = (const float*)d_in[23];
    const float* b1      = (const float*)d_in[24];
    const float* W2      = (const float*)d_in[25];
    const float* b2      = (const float*)d_in[26];
    const int*   src     = (const int*)d_in[27];
    const int*   dst     = (const int*)d_in[28];
    float* out = (float*)d_out;

    cudaFuncSetAttribute(k_matABDE, cudaFuncAttributeMaxDynamicSharedMemorySize, 192 * 1024);
    cudaFuncSetAttribute(k_edge,    cudaFuncAttributeMaxDynamicSharedMemorySize, 100 * 1024);
    cudaFuncSetAttribute(k_head,    cudaFuncAttributeMaxDynamicSharedMemorySize, 96 * 1024);

    const int smem_abde = (DD * 384 + 32 * DD + 384) * 4;                       // 161280
    int smem_edge = (DD + 128) * ESTR * 4;                                      // 96768 (phase 1)
    int smem_p2   = 2 * 128 * RSTR * 4;                                         // 99328 (phase 2)
    if (smem_p2 > smem_edge) smem_edge = smem_p2;
    const int smem_head = (DD * HIDN + 32 * DD + 32 * 132 + HIDN * OUTN) * 4;   // 82432

    k_zero<<<(NN * DD + 255) / 256, 256>>>();
    k_embed_h<<<(NN * DD + 255) / 256, 256>>>(h1, h2, z, Wh_emb, bh_emb);

    k_count<<<EE / 256, 256>>>(dst);
    k_scan1<<<NBS, 256>>>();
    k_scan2<<<1, 256>>>();
    k_scan3<<<NBS, 256>>>();
    k_fill<<<EE / 256, 256>>>(dst);
    k_sortseg<<<(NN + 127) / 128, 128>>>();
    k_embed_e_perm<<<EE / 8, 256>>>(efeat, src, dst, We_emb, be_emb);

    const int ablk = (NN + 31) / 32;   // 1563
    const int eblk = EE / 128;         // 6250

    for (int l = 0; l < 4; l++) {
        k_matABDE<<<ablk, 384, smem_abde>>>(WA + l * DD * DD, WB + l * DD * DD,
                                            WD + l * DD * DD, WE + l * DD * DD,
                                            bA + l * DD, bB + l * DD,
                                            bD + l * DD, bE + l * DD,
                                            l >= 1 ? 1 : 0);

        int apply = (l >= 1) ? 1 : 0;
        int write_e = (l >= 1 && l < 3) ? 1 : 0;
        int do_stats = (l < 3) ? 1 : 0;
        int write_enew = (l < 3) ? 1 : 0;
        k_edge<<<eblk, 256, smem_edge>>>(WC + l * DD * DD, bC + l * DD,
                                         apply, write_e, do_stats, write_enew);
        if (l < 3)
            k_finalize<<<1, DD>>>(bn_e_g + l * DD, bn_e_b + l * DD, (double)EE, 0);

        k_nodeupd<<<NN * DD / 256, 256>>>();
        k_finalize<<<1, DD>>>(bn_h_g + l * DD, bn_h_b + l * DD, (double)NN, 1);
    }

    k_head<<<ablk, 256, smem_head>>>(W1, b1, W2, b2, maxa, out);
}

// round 6
// speedup vs baseline: 1.3862x; 1.3862x over previous
#include <cuda_runtime.h>
#include <math.h>

#define NN 50000
#define EE 800000
#define DD 96
#define HIDN 128
#define OUTN 8
#define NBS 196   // scan blocks = ceil(NN/256)
#define ESTR 108  // padded smem row stride (floats) for conflict-free mma feeds

typedef unsigned long long ull;

// ------------------------- device scratch (no allocs allowed) ----------------
__device__ float g_h[(size_t)NN * DD];
__device__ float g_hnew[(size_t)NN * DD];
__device__ float g_ABDE[(size_t)4 * NN * DD];   // A,B,D,E
__device__ float g_e[(size_t)EE * DD];          // permuted (CSR dst order)
__device__ float g_enew[(size_t)EE * DD];       // permuted
__device__ int   g_cnt[NN];
__device__ int   g_ptr[NN + 1];
__device__ int   g_woff[NN];
__device__ int   g_eid[EE];
__device__ int   g_srcp[EE];
__device__ int   g_dstp[EE];
__device__ int   g_bsum[256];
__device__ int   g_boff[256];
__device__ double g_esum[DD], g_esq[DD], g_hsum[DD], g_hsq[DD];
__device__ float g_escale[DD], g_eshift[DD], g_hscale[DD], g_hshift[DD];

// ------------------------- packed f32x2 helpers ------------------------------
__device__ __forceinline__ ull pk2(float lo, float hi) {
    ull r; asm("mov.b64 %0,{%1,%2};" : "=l"(r) : "f"(lo), "f"(hi)); return r;
}
__device__ __forceinline__ ull fma2(ull a, ull b, ull c) {
    ull d; asm("fma.rn.f32x2 %0,%1,%2,%3;" : "=l"(d) : "l"(a), "l"(b), "l"(c)); return d;
}
__device__ __forceinline__ float2 upk(ull v) {
    float2 f; asm("mov.b64 {%0,%1},%2;" : "=f"(f.x), "=f"(f.y) : "l"(v)); return f;
}
__device__ __forceinline__ float tf32r(float x) {
    unsigned u; asm("cvt.rna.tf32.f32 %0,%1;" : "=r"(u) : "f"(x));
    return __uint_as_float(u);
}
#define MMA_TF32(d, a, b0_, b1_) \
    asm volatile("mma.sync.aligned.m16n8k8.row.col.f32.tf32.tf32.f32 " \
        "{%0,%1,%2,%3},{%4,%5,%6,%7},{%8,%9},{%0,%1,%2,%3};" \
        : "+f"(d[0]), "+f"(d[1]), "+f"(d[2]), "+f"(d[3]) \
        : "r"(a[0]), "r"(a[1]), "r"(a[2]), "r"(a[3]), "r"(b0_), "r"(b1_))

// ------------------------- setup kernels -------------------------------------
__global__ void k_zero() {
    int i = blockIdx.x * blockDim.x + threadIdx.x;
    if (i < NN) g_cnt[i] = 0;
    if (i < DD) { g_esum[i] = 0.0; g_esq[i] = 0.0; g_hsum[i] = 0.0; g_hsq[i] = 0.0; }
}

__global__ void k_embed_h(const float* __restrict__ h1, const float* __restrict__ h2,
                          const float* __restrict__ z,
                          const float* __restrict__ W, const float* __restrict__ b) {
    __shared__ float Ws[26 * DD];
    int t = threadIdx.x;
    for (int i = t; i < 26 * DD; i += blockDim.x) Ws[i] = W[i];
    __syncthreads();
    int idx = blockIdx.x * blockDim.x + t;
    if (idx >= NN * DD) return;
    int r = idx / DD, c = idx - (idx / DD) * DD;
    float acc = b[c];
#pragma unroll
    for (int k = 0; k < 6; k++)  acc += h1[r * 6 + k]  * Ws[k * DD + c];
#pragma unroll
    for (int k = 0; k < 4; k++)  acc += h2[r * 4 + k]  * Ws[(6 + k) * DD + c];
#pragma unroll
    for (int k = 0; k < 16; k++) acc += z[r * 16 + k]  * Ws[(10 + k) * DD + c];
    g_h[idx] = acc;
}

// ------------------------- CSR build (deterministic, parallel scan) -----------
__global__ void k_count(const int* __restrict__ dst) {
    int i = blockIdx.x * blockDim.x + threadIdx.x;
    if (i < EE) atomicAdd(&g_cnt[dst[i]], 1);
}

__global__ void k_scan1() {
    __shared__ int sh[256];
    int t = threadIdx.x, b = blockIdx.x;
    int j = b * 256 + t;
    int v = (j < NN) ? g_cnt[j] : 0;
    sh[t] = v; __syncthreads();
    for (int off = 1; off < 256; off <<= 1) {
        int u = (t >= off) ? sh[t - off] : 0;
        __syncthreads();
        sh[t] += u;
        __syncthreads();
    }
    if (j < NN) g_ptr[j] = sh[t] - v;
    if (t == 255) g_bsum[b] = sh[t];
}

__global__ void k_scan2() {
    __shared__ int sh[256];
    int t = threadIdx.x;
    int v = (t < NBS) ? g_bsum[t] : 0;
    sh[t] = v; __syncthreads();
    for (int off = 1; off < 256; off <<= 1) {
        int u = (t >= off) ? sh[t - off] : 0;
        __syncthreads();
        sh[t] += u;
        __syncthreads();
    }
    g_boff[t] = sh[t] - v;
}

__global__ void k_scan3() {
    int j = blockIdx.x * blockDim.x + threadIdx.x;
    if (j < NN) {
        int p = g_ptr[j] + g_boff[j >> 8];
        g_ptr[j] = p; g_woff[j] = p;
    }
    if (j == 0) g_ptr[NN] = EE;
}

__global__ void k_fill(const int* __restrict__ dst) {
    int i = blockIdx.x * blockDim.x + threadIdx.x;
    if (i < EE) {
        int pos = atomicAdd(&g_woff[dst[i]], 1);
        g_eid[pos] = i;
    }
}

__global__ void k_sortseg() {
    int v = blockIdx.x * blockDim.x + threadIdx.x;
    if (v >= NN) return;
    int lo = g_ptr[v], hi = g_ptr[v + 1];
    for (int i = lo + 1; i < hi; i++) {
        int key = g_eid[i]; int j = i - 1;
        while (j >= lo && g_eid[j] > key) { g_eid[j + 1] = g_eid[j]; j--; }
        g_eid[j + 1] = key;
    }
}

__global__ void k_permidx(const int* __restrict__ src, const int* __restrict__ dst) {
    int p = blockIdx.x * blockDim.x + threadIdx.x;
    if (p < EE) {
        int ei = g_eid[p];
        g_srcp[p] = src[ei];
        g_dstp[p] = dst[ei];
    }
}

// ------------------------- fused node GEMM: [A|B|D|E] = h @ Wcat + bcat -------
// 64 rows/block, 768 threads, 8x4 per-thread tile (two row-waves of R2 shape).
// Lazily applies h += relu(bn(hnew)) from the previous layer (writes g_h).
__global__ __launch_bounds__(768) void k_matABDE(const float* __restrict__ WA_,
                                                 const float* __restrict__ WB_,
                                                 const float* __restrict__ WD_,
                                                 const float* __restrict__ WE_,
                                                 const float* __restrict__ bA_,
                                                 const float* __restrict__ bB_,
                                                 const float* __restrict__ bD_,
                                                 const float* __restrict__ bE_,
                                                 int apply) {
    extern __shared__ float dyn[];
    float* Ws = dyn;                    // [96][384] concat
    float* Xs = dyn + DD * 384;         // [64][96]
    float* Bs = Xs + 64 * DD;           // [384]
    int t = threadIdx.x;
    const float* wsrc[4] = {WA_, WB_, WD_, WE_};
    const float* bsrc[4] = {bA_, bB_, bD_, bE_};
#pragma unroll
    for (int m = 0; m < 4; m++) {
        for (int i = t; i < DD * DD; i += 768) {
            int k = i / DD, c = i - (i / DD) * DD;
            Ws[k * 384 + m * DD + c] = wsrc[m][i];
        }
        if (t < DD) Bs[m * DD + t] = bsrc[m][t];
    }
    int row0 = blockIdx.x * 64;
    for (int i = t; i < 64 * 24; i += 768) {
        int r = i / 24, c4 = (i - (i / 24) * 24) * 4;
        int gr = row0 + r;
        float4 v = make_float4(0.f, 0.f, 0.f, 0.f);
        if (gr < NN) {
            size_t idx = (size_t)gr * DD + c4;
            v = *(const float4*)(g_h + idx);
            if (apply) {
                float4 en = *(const float4*)(g_hnew + idx);
                float4 sc = *(const float4*)(g_hscale + c4);
                float4 sh = *(const float4*)(g_hshift + c4);
                v.x += fmaxf(sc.x * en.x + sh.x, 0.f);
                v.y += fmaxf(sc.y * en.y + sh.y, 0.f);
                v.z += fmaxf(sc.z * en.z + sh.z, 0.f);
                v.w += fmaxf(sc.w * en.w + sh.w, 0.f);
                *(float4*)(g_h + idx) = v;
            }
        }
        *(float4*)(Xs + r * DD + c4) = v;
    }
    __syncthreads();
    int cg = t % 96, rg = t / 96;       // 96 col-groups x 8 row-groups
    int c0 = cg * 4, r0 = rg * 8;
    ull acc[8][2];
    ull b01 = pk2(Bs[c0], Bs[c0 + 1]), b23 = pk2(Bs[c0 + 2], Bs[c0 + 3]);
#pragma unroll
    for (int r = 0; r < 8; r++) { acc[r][0] = b01; acc[r][1] = b23; }
#pragma unroll 6
    for (int k = 0; k < DD; k += 2) {
        ulonglong2 w0 = *(const ulonglong2*)(Ws + k * 384 + c0);
        ulonglong2 w1 = *(const ulonglong2*)(Ws + (k + 1) * 384 + c0);
#pragma unroll
        for (int r = 0; r < 8; r++) {
            float2 x = *(const float2*)(Xs + (r0 + r) * DD + k);
            ull x0 = pk2(x.x, x.x), x1 = pk2(x.y, x.y);
            acc[r][0] = fma2(x0, w0.x, acc[r][0]);
            acc[r][1] = fma2(x0, w0.y, acc[r][1]);
            acc[r][0] = fma2(x1, w1.x, acc[r][0]);
            acc[r][1] = fma2(x1, w1.y, acc[r][1]);
        }
    }
    int m = c0 / DD, cc = c0 - m * DD;
    float* outp = g_ABDE + (size_t)m * NN * DD;
#pragma unroll
    for (int r = 0; r < 8; r++) {
        int gr = row0 + r0 + r;
        if (gr < NN) {
            float2 a = upk(acc[r][0]), q = upk(acc[r][1]);
            *(float4*)(outp + (size_t)gr * DD + cc) = make_float4(a.x, a.y, q.x, q.y);
        }
    }
}

// ------------------------- edge kernel: tf32 tensor-core GEMM -----------------
// 128 edges/block, 8 warps; warp w owns 32 edges x 48 cols (2 m16 x 6 n8 tiles).
// embed mode (l0): builds e from efeat@We_emb+be inline and writes g_e.
__global__ __launch_bounds__(256) void k_edge(const float* __restrict__ W,
                                              const float* __restrict__ b,
                                              const float* __restrict__ efeat,
                                              const float* __restrict__ Wemb,
                                              const float* __restrict__ bemb,
                                              int embed, int apply, int write_e,
                                              int do_stats) {
    extern __shared__ float dyn[];
    float* Ws = dyn;                  // [96][ESTR]
    float* Es = dyn + DD * ESTR;      // [128][ESTR]
    __shared__ float s_sum[DD], s_sq[DD], bsh[DD];
    __shared__ int s_src[128], s_dst[128];
    __shared__ float s_ef[128 * 4];
    __shared__ float s_wemb[4 * DD];
    __shared__ float s_bemb[DD];
    int t = threadIdx.x;
    int lane = t & 31, w = t >> 5;
    if (t < DD) { s_sum[t] = 0.f; s_sq[t] = 0.f; bsh[t] = b[t]; }
    // stage W, rounded to tf32
    for (int i = t; i < DD * 24; i += 256) {
        int k = i / 24, c4 = (i - (i / 24) * 24) * 4;
        float4 v = *(const float4*)(W + k * DD + c4);
        v.x = tf32r(v.x); v.y = tf32r(v.y); v.z = tf32r(v.z); v.w = tf32r(v.w);
        *(float4*)(Ws + k * ESTR + c4) = v;
    }
    int ebase = blockIdx.x * 128;   // EE % 128 == 0
    if (t < 128) { s_src[t] = g_srcp[ebase + t]; s_dst[t] = g_dstp[ebase + t]; }
    if (embed) {
        for (int i = t; i < 4 * DD; i += 256) s_wemb[i] = Wemb[i];
        if (t < DD) s_bemb[t] = bemb[t];
        if (t < 128) {
            int ei = g_eid[ebase + t];
            *(float4*)(s_ef + t * 4) = *(const float4*)(efeat + (size_t)ei * 4);
        }
        __syncthreads();
        for (int i = t; i < 128 * 24; i += 256) {
            int r = i / 24, c4 = (i - (i / 24) * 24) * 4;
            size_t idx = (size_t)(ebase + r) * DD + c4;
            float4 f = *(const float4*)(s_ef + r * 4);
            float4 v;
            v.x = s_bemb[c4 + 0] + f.x * s_wemb[c4 + 0] + f.y * s_wemb[DD + c4 + 0]
                + f.z * s_wemb[2 * DD + c4 + 0] + f.w * s_wemb[3 * DD + c4 + 0];
            v.y = s_bemb[c4 + 1] + f.x * s_wemb[c4 + 1] + f.y * s_wemb[DD + c4 + 1]
                + f.z * s_wemb[2 * DD + c4 + 1] + f.w * s_wemb[3 * DD + c4 + 1];
            v.z = s_bemb[c4 + 2] + f.x * s_wemb[c4 + 2] + f.y * s_wemb[DD + c4 + 2]
                + f.z * s_wemb[2 * DD + c4 + 2] + f.w * s_wemb[3 * DD + c4 + 2];
            v.w = s_bemb[c4 + 3] + f.x * s_wemb[c4 + 3] + f.y * s_wemb[DD + c4 + 3]
                + f.z * s_wemb[2 * DD + c4 + 3] + f.w * s_wemb[3 * DD + c4 + 3];
            *(float4*)(g_e + idx) = v;    // l1 needs f32 e
            v.x = tf32r(v.x); v.y = tf32r(v.y); v.z = tf32r(v.z); v.w = tf32r(v.w);
            *(float4*)(Es + r * ESTR + c4) = v;
        }
    } else {
        for (int i = t; i < 128 * 24; i += 256) {
            int r = i / 24, c4 = (i - (i / 24) * 24) * 4;
            size_t idx = (size_t)(ebase + r) * DD + c4;
            float4 v = *(const float4*)(g_e + idx);
            if (apply) {
                float4 en = *(const float4*)(g_enew + idx);
                float4 sc = *(const float4*)(g_escale + c4);
                float4 sh = *(const float4*)(g_eshift + c4);
                v.x += fmaxf(sc.x * en.x + sh.x, 0.f);
                v.y += fmaxf(sc.y * en.y + sh.y, 0.f);
                v.z += fmaxf(sc.z * en.z + sh.z, 0.f);
                v.w += fmaxf(sc.w * en.w + sh.w, 0.f);
                if (write_e) *(float4*)(g_e + idx) = v;
            }
            v.x = tf32r(v.x); v.y = tf32r(v.y); v.z = tf32r(v.z); v.w = tf32r(v.w);
            *(float4*)(Es + r * ESTR + c4) = v;
        }
    }
    __syncthreads();

    int mg = w >> 1, ng = w & 1;
    int m0 = mg * 32, n0 = ng * 48;
    int g = lane >> 2, c4 = lane & 3;
    float acc[2][6][4];
#pragma unroll
    for (int i = 0; i < 2; i++)
#pragma unroll
        for (int j = 0; j < 6; j++)
#pragma unroll
            for (int q = 0; q < 4; q++) acc[i][j][q] = 0.f;

#pragma unroll
    for (int k0 = 0; k0 < DD; k0 += 8) {
        unsigned a[2][4];
#pragma unroll
        for (int i = 0; i < 2; i++) {
            int rr = (m0 + i * 16 + g) * ESTR;
            a[i][0] = __float_as_uint(Es[rr + k0 + c4]);
            a[i][1] = __float_as_uint(Es[rr + 8 * ESTR + k0 + c4]);
            a[i][2] = __float_as_uint(Es[rr + k0 + 4 + c4]);
            a[i][3] = __float_as_uint(Es[rr + 8 * ESTR + k0 + 4 + c4]);
        }
#pragma unroll
        for (int j = 0; j < 6; j++) {
            int col = n0 + 8 * j + g;
            unsigned b0 = __float_as_uint(Ws[(k0 + c4) * ESTR + col]);
            unsigned b1 = __float_as_uint(Ws[(k0 + 4 + c4) * ESTR + col]);
            MMA_TF32(acc[0][j], a[0], b0, b1);
            MMA_TF32(acc[1][j], a[1], b0, b1);
        }
    }

    // epilogue: add bias + gathers, write enew, accumulate stats
    const float* Dh = g_ABDE + (size_t)2 * NN * DD;
    const float* Eh = g_ABDE + (size_t)3 * NN * DD;
    float cs[6][2], cq[6][2];
#pragma unroll
    for (int j = 0; j < 6; j++) { cs[j][0] = cs[j][1] = 0.f; cq[j][0] = cq[j][1] = 0.f; }
#pragma unroll
    for (int i = 0; i < 2; i++) {
#pragma unroll
        for (int half = 0; half < 2; half++) {
            int rl = m0 + i * 16 + half * 8 + g;
            size_t sb = (size_t)s_src[rl] * DD;
            size_t db = (size_t)s_dst[rl] * DD;
            size_t ob = (size_t)(ebase + rl) * DD;
#pragma unroll
            for (int j = 0; j < 6; j++) {
                int col = n0 + 8 * j + 2 * c4;
                float2 dh = *(const float2*)(Dh + sb + col);
                float2 eh = *(const float2*)(Eh + db + col);
                float v0 = acc[i][j][half * 2 + 0] + bsh[col]     + dh.x + eh.x;
                float v1 = acc[i][j][half * 2 + 1] + bsh[col + 1] + dh.y + eh.y;
                *(float2*)(g_enew + ob + col) = make_float2(v0, v1);
                cs[j][0] += v0; cs[j][1] += v1;
                cq[j][0] += v0 * v0; cq[j][1] += v1 * v1;
            }
        }
    }
    if (do_stats) {
#pragma unroll
        for (int off = 16; off >= 4; off >>= 1) {
#pragma unroll
            for (int j = 0; j < 6; j++) {
#pragma unroll
                for (int p = 0; p < 2; p++) {
                    cs[j][p] += __shfl_down_sync(0xffffffffu, cs[j][p], off);
                    cq[j][p] += __shfl_down_sync(0xffffffffu, cq[j][p], off);
                }
            }
        }
        if (lane < 4) {
#pragma unroll
            for (int j = 0; j < 6; j++) {
#pragma unroll
                for (int p = 0; p < 2; p++) {
                    int col = n0 + 8 * j + 2 * lane + p;
                    atomicAdd(&s_sum[col], cs[j][p]);
                    atomicAdd(&s_sq[col], cq[j][p]);
                }
            }
        }
        __syncthreads();
        if (t < DD) {
            atomicAdd(&g_esum[t], (double)s_sum[t]);
            atomicAdd(&g_esq[t], (double)s_sq[t]);
        }
    }
}

// ------------------------- aggregation (CSR, sequential enew) -----------------
__global__ __launch_bounds__(256) void k_agg() {
    __shared__ float ssum[DD], ssq[DD];
    int t = threadIdx.x;
    if (t < DD) { ssum[t] = 0.f; ssq[t] = 0.f; }
    __syncthreads();
    int w = t >> 5, ln = t & 31;
    int v = blockIdx.x * 8 + w;      // grid = NN/8 exact
    const float* Ah = g_ABDE;
    const float* Bh = g_ABDE + (size_t)NN * DD;
    float n0 = 0, n1 = 0, n2 = 0, d0 = 0, d1 = 0, d2 = 0;
    int p0 = g_ptr[v], p1 = g_ptr[v + 1];
    for (int p = p0; p < p1; p++) {
        int s = g_srcp[p];
        size_t eb = (size_t)p * DD;
        size_t sb = (size_t)s * DD;
        float x0 = g_enew[eb + ln], x1 = g_enew[eb + ln + 32], x2 = g_enew[eb + ln + 64];
        float s0 = __fdividef(1.f, 1.f + __expf(-x0));
        float s1 = __fdividef(1.f, 1.f + __expf(-x1));
        float s2 = __fdividef(1.f, 1.f + __expf(-x2));
        n0 += s0 * Bh[sb + ln]; n1 += s1 * Bh[sb + ln + 32]; n2 += s2 * Bh[sb + ln + 64];
        d0 += s0; d1 += s1; d2 += s2;
    }
    size_t vb = (size_t)v * DD;
    float h0 = Ah[vb + ln]      + __fdividef(n0, d0 + 1e-6f);
    float h1 = Ah[vb + ln + 32] + __fdividef(n1, d1 + 1e-6f);
    float h2 = Ah[vb + ln + 64] + __fdividef(n2, d2 + 1e-6f);
    g_hnew[vb + ln] = h0; g_hnew[vb + ln + 32] = h1; g_hnew[vb + ln + 64] = h2;
    atomicAdd(&ssum[ln], h0);      atomicAdd(&ssum[ln + 32], h1); atomicAdd(&ssum[ln + 64], h2);
    atomicAdd(&ssq[ln], h0 * h0);  atomicAdd(&ssq[ln + 32], h1 * h1); atomicAdd(&ssq[ln + 64], h2 * h2);
    __syncthreads();
    if (t < DD) {
        atomicAdd(&g_hsum[t], (double)ssum[t]);
        atomicAdd(&g_hsq[t], (double)ssq[t]);
    }
}

// ------------------------- BN finalize ----------------------------------------
__global__ void k_finalize(const float* __restrict__ gamma, const float* __restrict__ beta,
                           double count, int which) {
    int c = threadIdx.x;
    if (c >= DD) return;
    double s, q;
    if (which == 0) { s = g_esum[c]; q = g_esq[c]; g_esum[c] = 0.0; g_esq[c] = 0.0; }
    else            { s = g_hsum[c]; q = g_hsq[c]; g_hsum[c] = 0.0; g_hsq[c] = 0.0; }
    double m = s / count;
    double var = q / count - m * m;
    float sc = gamma[c] * rsqrtf((float)var + 1e-5f);
    float sh = beta[c] - (float)m * sc;
    if (which == 0) { g_escale[c] = sc; g_eshift[c] = sh; }
    else            { g_hscale[c] = sc; g_hshift[c] = sh; }
}

// ------------------------- head: relu(h@W1+b1)@W2+b2, tanh, scale -------------
__global__ __launch_bounds__(256) void k_head(const float* __restrict__ W1,
                                              const float* __restrict__ b1,
                                              const float* __restrict__ W2,
                                              const float* __restrict__ b2,
                                              const float* __restrict__ maxa,
                                              float* __restrict__ out) {
    extern __shared__ float dyn[];
    float* W1s = dyn;                 // 96*128
    float* Hs  = W1s + DD * HIDN;     // 32*96
    float* His = Hs + 32 * DD;        // 32*132 (padded)
    float* W2s = His + 32 * 132;      // 128*8
    int t = threadIdx.x;
    for (int i = t; i < DD * HIDN; i += 256) W1s[i] = W1[i];
    for (int i = t; i < HIDN * OUTN; i += 256) W2s[i] = W2[i];
    int row0 = blockIdx.x * 32;
    for (int i = t; i < 32 * 24; i += 256) {
        int r = i / 24, c4 = (i - (i / 24) * 24) * 4;
        int gr = row0 + r;
        float4 v = make_float4(0.f, 0.f, 0.f, 0.f);
        if (gr < NN) {
            size_t idx = (size_t)gr * DD + c4;
            v = *(const float4*)(g_h + idx);
            float4 en = *(const float4*)(g_hnew + idx);
            float4 sc = *(const float4*)(g_hscale + c4);
            float4 sh = *(const float4*)(g_hshift + c4);
            v.x += fmaxf(sc.x * en.x + sh.x, 0.f);
            v.y += fmaxf(sc.y * en.y + sh.y, 0.f);
            v.z += fmaxf(sc.z * en.z + sh.z, 0.f);
            v.w += fmaxf(sc.w * en.w + sh.w, 0.f);
        }
        *(float4*)(Hs + r * DD + c4) = v;
    }
    __syncthreads();
    {
        int ng = t >> 5, hg = t & 31;
        int r0 = ng * 4, c0 = hg * 4;
        ull acc[4][2];
        float4 bv = *(const float4*)(b1 + c0);
        ull b01 = pk2(bv.x, bv.y), b23 = pk2(bv.z, bv.w);
#pragma unroll
        for (int r = 0; r < 4; r++) { acc[r][0] = b01; acc[r][1] = b23; }
#pragma unroll 4
        for (int k = 0; k < DD; k++) {
            ulonglong2 wv = *(const ulonglong2*)(W1s + k * HIDN + c0);
#pragma unroll
            for (int r = 0; r < 4; r++) {
                float x = Hs[(r0 + r) * DD + k];
                ull xx = pk2(x, x);
                acc[r][0] = fma2(xx, wv.x, acc[r][0]);
                acc[r][1] = fma2(xx, wv.y, acc[r][1]);
            }
        }
#pragma unroll
        for (int r = 0; r < 4; r++) {
            float2 a = upk(acc[r][0]), q = upk(acc[r][1]);
            His[(r0 + r) * 132 + c0 + 0] = fmaxf(a.x, 0.f);
            His[(r0 + r) * 132 + c0 + 1] = fmaxf(a.y, 0.f);
            His[(r0 + r) * 132 + c0 + 2] = fmaxf(q.x, 0.f);
            His[(r0 + r) * 132 + c0 + 3] = fmaxf(q.y, 0.f);
        }
    }
    __syncthreads();
    {
        int node = t >> 3, oc = t & 7;
        int gn = row0 + node;
        if (gn < NN) {
            float acc = b2[oc];
#pragma unroll 8
            for (int k = 0; k < HIDN; k++) acc += His[node * 132 + k] * W2s[k * OUTN + oc];
            out[(size_t)gn * OUTN + oc] = maxa[gn] * tanhf(acc);
        }
    }
}

// ------------------------- launch ---------------------------------------------
extern "C" void kernel_launch(void* const* d_in, const int* in_sizes, int n_in,
                              void* d_out, int out_size) {
    const float* h1      = (const float*)d_in[0];
    const float* h2      = (const float*)d_in[1];
    const float* z       = (const float*)d_in[2];
    const float* efeat   = (const float*)d_in[3];
    const float* maxa    = (const float*)d_in[4];
    const float* Wh_emb  = (const float*)d_in[5];
    const float* bh_emb  = (const float*)d_in[6];
    const float* We_emb  = (const float*)d_in[7];
    const float* be_emb  = (const float*)d_in[8];
    const float* WA      = (const float*)d_in[9];
    const float* bA      = (const float*)d_in[10];
    const float* WB      = (const float*)d_in[11];
    const float* bB      = (const float*)d_in[12];
    const float* WC      = (const float*)d_in[13];
    const float* bC      = (const float*)d_in[14];
    const float* WD      = (const float*)d_in[15];
    const float* bD      = (const float*)d_in[16];
    const float* WE      = (const float*)d_in[17];
    const float* bE      = (const float*)d_in[18];
    const float* bn_h_g  = (const float*)d_in[19];
    const float* bn_h_b  = (const float*)d_in[20];
    const float* bn_e_g  = (const float*)d_in[21];
    const float* bn_e_b  = (const float*)d_in[22];
    const float* W1      = (const float*)d_in[23];
    const float* b1      = (const float*)d_in[24];
    const float* W2      = (const float*)d_in[25];
    const float* b2      = (const float*)d_in[26];
    const int*   src     = (const int*)d_in[27];
    const int*   dst     = (const int*)d_in[28];
    float* out = (float*)d_out;

    cudaFuncSetAttribute(k_matABDE, cudaFuncAttributeMaxDynamicSharedMemorySize, 200 * 1024);
    cudaFuncSetAttribute(k_edge,    cudaFuncAttributeMaxDynamicSharedMemorySize, 100 * 1024);
    cudaFuncSetAttribute(k_head,    cudaFuncAttributeMaxDynamicSharedMemorySize, 96 * 1024);

    const int smem_abde = (DD * 384 + 64 * DD + 384) * 4;                       // ~173 KB
    const int smem_edge = (DD + 128) * ESTR * 4;                                // 96768
    const int smem_head = (DD * HIDN + 32 * DD + 32 * 132 + HIDN * OUTN) * 4;   // 82432

    k_zero<<<(NN + 255) / 256, 256>>>();
    k_embed_h<<<(NN * DD + 255) / 256, 256>>>(h1, h2, z, Wh_emb, bh_emb);

    k_count<<<EE / 256, 256>>>(dst);
    k_scan1<<<NBS, 256>>>();
    k_scan2<<<1, 256>>>();
    k_scan3<<<NBS, 256>>>();
    k_fill<<<EE / 256, 256>>>(dst);
    k_sortseg<<<(NN + 127) / 128, 128>>>();
    k_permidx<<<EE / 256, 256>>>(src, dst);

    const int ablk = (NN + 63) / 64;   // 782
    const int eblk = EE / 128;         // 6250

    for (int l = 0; l < 4; l++) {
        k_matABDE<<<ablk, 768, smem_abde>>>(WA + l * DD * DD, WB + l * DD * DD,
                                            WD + l * DD * DD, WE + l * DD * DD,
                                            bA + l * DD, bB + l * DD,
                                            bD + l * DD, bE + l * DD,
                                            l >= 1 ? 1 : 0);

        int embed = (l == 0) ? 1 : 0;
        int apply = (l >= 1) ? 1 : 0;
        int write_e = (l >= 1 && l < 3) ? 1 : 0;
        int do_stats = (l < 3) ? 1 : 0;
        k_edge<<<eblk, 256, smem_edge>>>(WC + l * DD * DD, bC + l * DD,
                                         efeat, We_emb, be_emb,
                                         embed, apply, write_e, do_stats);
        if (l < 3)
            k_finalize<<<1, DD>>>(bn_e_g + l * DD, bn_e_b + l * DD, (double)EE, 0);

        k_agg<<<NN / 8, 256>>>();
        k_finalize<<<1, DD>>>(bn_h_g + l * DD, bn_h_b + l * DD, (double)NN, 1);
    }

    k_head<<<(NN + 31) / 32, 256, smem_head>>>(W1, b1, W2, b2, maxa, out);
}

// round 7
// speedup vs baseline: 1.4676x; 1.0587x over previous
#include <cuda_runtime.h>
#include <cuda_bf16.h>
#include <math.h>

#define NN 50000
#define EE 800000
#define DD 96
#define HIDN 128
#define OUTN 8
#define NBS 196   // scan blocks = ceil(NN/256)
#define ESTR 108  // padded smem row stride (floats) for conflict-free mma feeds

typedef unsigned long long ull;

// ------------------------- device scratch (no allocs allowed) ----------------
__device__ float g_h[(size_t)NN * DD];
__device__ float g_hnew[(size_t)NN * DD];
__device__ float g_ABDE[(size_t)4 * NN * DD];   // A,B,D,E
__device__ __nv_bfloat16 g_e[(size_t)EE * DD];     // permuted (CSR dst order)
__device__ __nv_bfloat16 g_enew[(size_t)EE * DD];  // permuted
__device__ int   g_cnt[NN];
__device__ int   g_ptr[NN + 1];
__device__ int   g_woff[NN];
__device__ int   g_eid[EE];
__device__ int   g_srcp[EE];
__device__ int   g_dstp[EE];
__device__ int   g_bsum[256];
__device__ int   g_boff[256];
__device__ double g_esum[DD], g_esq[DD], g_hsum[DD], g_hsq[DD];
__device__ float g_escale[DD], g_eshift[DD], g_hscale[DD], g_hshift[DD];

// ------------------------- packed f32x2 helpers ------------------------------
__device__ __forceinline__ ull pk2(float lo, float hi) {
    ull r; asm("mov.b64 %0,{%1,%2};" : "=l"(r) : "f"(lo), "f"(hi)); return r;
}
__device__ __forceinline__ ull fma2(ull a, ull b, ull c) {
    ull d; asm("fma.rn.f32x2 %0,%1,%2,%3;" : "=l"(d) : "l"(a), "l"(b), "l"(c)); return d;
}
__device__ __forceinline__ float2 upk(ull v) {
    float2 f; asm("mov.b64 {%0,%1},%2;" : "=f"(f.x), "=f"(f.y) : "l"(v)); return f;
}
__device__ __forceinline__ float tf32r(float x) {
    unsigned u; asm("cvt.rna.tf32.f32 %0,%1;" : "=r"(u) : "f"(x));
    return __uint_as_float(u);
}
#define MMA_TF32(d, a, b0_, b1_) \
    asm volatile("mma.sync.aligned.m16n8k8.row.col.f32.tf32.tf32.f32 " \
        "{%0,%1,%2,%3},{%4,%5,%6,%7},{%8,%9},{%0,%1,%2,%3};" \
        : "+f"(d[0]), "+f"(d[1]), "+f"(d[2]), "+f"(d[3]) \
        : "r"(a[0]), "r"(a[1]), "r"(a[2]), "r"(a[3]), "r"(b0_), "r"(b1_))

// unpack 8 bf16 (in a uint4) -> 8 floats
__device__ __forceinline__ void bf8_to_f(const uint4& u, float* f) {
    const __nv_bfloat162* p = (const __nv_bfloat162*)&u;
#pragma unroll
    for (int j = 0; j < 4; j++) {
        float2 t = __bfloat1622float2(p[j]);
        f[2 * j] = t.x; f[2 * j + 1] = t.y;
    }
}
__device__ __forceinline__ uint4 f_to_bf8(const float* f) {
    uint4 u;
    __nv_bfloat162* p = (__nv_bfloat162*)&u;
#pragma unroll
    for (int j = 0; j < 4; j++)
        p[j] = __float22bfloat162_rn(make_float2(f[2 * j], f[2 * j + 1]));
    return u;
}

// ------------------------- setup kernels -------------------------------------
__global__ void k_zero() {
    int i = blockIdx.x * blockDim.x + threadIdx.x;
    if (i < NN) g_cnt[i] = 0;
    if (i < DD) { g_esum[i] = 0.0; g_esq[i] = 0.0; g_hsum[i] = 0.0; g_hsq[i] = 0.0; }
}

__global__ void k_embed_h(const float* __restrict__ h1, const float* __restrict__ h2,
                          const float* __restrict__ z,
                          const float* __restrict__ W, const float* __restrict__ b) {
    __shared__ float Ws[26 * DD];
    int t = threadIdx.x;
    for (int i = t; i < 26 * DD; i += blockDim.x) Ws[i] = W[i];
    __syncthreads();
    int idx = blockIdx.x * blockDim.x + t;
    if (idx >= NN * DD) return;
    int r = idx / DD, c = idx - (idx / DD) * DD;
    float acc = b[c];
#pragma unroll
    for (int k = 0; k < 6; k++)  acc += h1[r * 6 + k]  * Ws[k * DD + c];
#pragma unroll
    for (int k = 0; k < 4; k++)  acc += h2[r * 4 + k]  * Ws[(6 + k) * DD + c];
#pragma unroll
    for (int k = 0; k < 16; k++) acc += z[r * 16 + k]  * Ws[(10 + k) * DD + c];
    g_h[idx] = acc;
}

// ------------------------- CSR build (deterministic, parallel scan) -----------
__global__ void k_count(const int* __restrict__ dst) {
    int i = blockIdx.x * blockDim.x + threadIdx.x;
    if (i < EE) atomicAdd(&g_cnt[dst[i]], 1);
}

__global__ void k_scan1() {
    __shared__ int sh[256];
    int t = threadIdx.x, b = blockIdx.x;
    int j = b * 256 + t;
    int v = (j < NN) ? g_cnt[j] : 0;
    sh[t] = v; __syncthreads();
    for (int off = 1; off < 256; off <<= 1) {
        int u = (t >= off) ? sh[t - off] : 0;
        __syncthreads();
        sh[t] += u;
        __syncthreads();
    }
    if (j < NN) g_ptr[j] = sh[t] - v;
    if (t == 255) g_bsum[b] = sh[t];
}

__global__ void k_scan2() {
    __shared__ int sh[256];
    int t = threadIdx.x;
    int v = (t < NBS) ? g_bsum[t] : 0;
    sh[t] = v; __syncthreads();
    for (int off = 1; off < 256; off <<= 1) {
        int u = (t >= off) ? sh[t - off] : 0;
        __syncthreads();
        sh[t] += u;
        __syncthreads();
    }
    g_boff[t] = sh[t] - v;
}

__global__ void k_scan3() {
    int j = blockIdx.x * blockDim.x + threadIdx.x;
    if (j < NN) {
        int p = g_ptr[j] + g_boff[j >> 8];
        g_ptr[j] = p; g_woff[j] = p;
    }
    if (j == 0) g_ptr[NN] = EE;
}

__global__ void k_fill(const int* __restrict__ dst) {
    int i = blockIdx.x * blockDim.x + threadIdx.x;
    if (i < EE) {
        int pos = atomicAdd(&g_woff[dst[i]], 1);
        g_eid[pos] = i;
    }
}

__global__ void k_sortseg() {
    int v = blockIdx.x * blockDim.x + threadIdx.x;
    if (v >= NN) return;
    int lo = g_ptr[v], hi = g_ptr[v + 1];
    for (int i = lo + 1; i < hi; i++) {
        int key = g_eid[i]; int j = i - 1;
        while (j >= lo && g_eid[j] > key) { g_eid[j + 1] = g_eid[j]; j--; }
        g_eid[j + 1] = key;
    }
}

__global__ void k_permidx(const int* __restrict__ src, const int* __restrict__ dst) {
    int p = blockIdx.x * blockDim.x + threadIdx.x;
    if (p < EE) {
        int ei = g_eid[p];
        g_srcp[p] = src[ei];
        g_dstp[p] = dst[ei];
    }
}

// ------------------------- fused node GEMM: [A|B|D|E] = h @ Wcat + bcat -------
// 64 rows/block, 768 threads, 8x4 per-thread tile.
// Lazily applies h += relu(bn(hnew)) from the previous layer (writes g_h).
__global__ __launch_bounds__(768) void k_matABDE(const float* __restrict__ WA_,
                                                 const float* __restrict__ WB_,
                                                 const float* __restrict__ WD_,
                                                 const float* __restrict__ WE_,
                                                 const float* __restrict__ bA_,
                                                 const float* __restrict__ bB_,
                                                 const float* __restrict__ bD_,
                                                 const float* __restrict__ bE_,
                                                 int apply) {
    extern __shared__ float dyn[];
    float* Ws = dyn;                    // [96][384] concat
    float* Xs = dyn + DD * 384;         // [64][96]
    float* Bs = Xs + 64 * DD;           // [384]
    int t = threadIdx.x;
    const float* wsrc[4] = {WA_, WB_, WD_, WE_};
    const float* bsrc[4] = {bA_, bB_, bD_, bE_};
#pragma unroll
    for (int m = 0; m < 4; m++) {
        for (int i = t; i < DD * DD; i += 768) {
            int k = i / DD, c = i - (i / DD) * DD;
            Ws[k * 384 + m * DD + c] = wsrc[m][i];
        }
        if (t < DD) Bs[m * DD + t] = bsrc[m][t];
    }
    int row0 = blockIdx.x * 64;
    for (int i = t; i < 64 * 24; i += 768) {
        int r = i / 24, c4 = (i - (i / 24) * 24) * 4;
        int gr = row0 + r;
        float4 v = make_float4(0.f, 0.f, 0.f, 0.f);
        if (gr < NN) {
            size_t idx = (size_t)gr * DD + c4;
            v = *(const float4*)(g_h + idx);
            if (apply) {
                float4 en = *(const float4*)(g_hnew + idx);
                float4 sc = *(const float4*)(g_hscale + c4);
                float4 sh = *(const float4*)(g_hshift + c4);
                v.x += fmaxf(sc.x * en.x + sh.x, 0.f);
                v.y += fmaxf(sc.y * en.y + sh.y, 0.f);
                v.z += fmaxf(sc.z * en.z + sh.z, 0.f);
                v.w += fmaxf(sc.w * en.w + sh.w, 0.f);
                *(float4*)(g_h + idx) = v;
            }
        }
        *(float4*)(Xs + r * DD + c4) = v;
    }
    __syncthreads();
    int cg = t % 96, rg = t / 96;
    int c0 = cg * 4, r0 = rg * 8;
    ull acc[8][2];
    ull b01 = pk2(Bs[c0], Bs[c0 + 1]), b23 = pk2(Bs[c0 + 2], Bs[c0 + 3]);
#pragma unroll
    for (int r = 0; r < 8; r++) { acc[r][0] = b01; acc[r][1] = b23; }
#pragma unroll 6
    for (int k = 0; k < DD; k += 2) {
        ulonglong2 w0 = *(const ulonglong2*)(Ws + k * 384 + c0);
        ulonglong2 w1 = *(const ulonglong2*)(Ws + (k + 1) * 384 + c0);
#pragma unroll
        for (int r = 0; r < 8; r++) {
            float2 x = *(const float2*)(Xs + (r0 + r) * DD + k);
            ull x0 = pk2(x.x, x.x), x1 = pk2(x.y, x.y);
            acc[r][0] = fma2(x0, w0.x, acc[r][0]);
            acc[r][1] = fma2(x0, w0.y, acc[r][1]);
            acc[r][0] = fma2(x1, w1.x, acc[r][0]);
            acc[r][1] = fma2(x1, w1.y, acc[r][1]);
        }
    }
    int m = c0 / DD, cc = c0 - m * DD;
    float* outp = g_ABDE + (size_t)m * NN * DD;
#pragma unroll
    for (int r = 0; r < 8; r++) {
        int gr = row0 + r0 + r;
        if (gr < NN) {
            float2 a = upk(acc[r][0]), q = upk(acc[r][1]);
            *(float4*)(outp + (size_t)gr * DD + cc) = make_float4(a.x, a.y, q.x, q.y);
        }
    }
}

// ------------------------- edge kernel: tf32 tensor-core GEMM, bf16 state -----
// 128 edges/block, 8 warps; warp w owns 32 edges x 48 cols (2 m16 x 6 n8 tiles).
// embed mode (l0): builds e from efeat@We_emb+be inline and writes g_e (bf16).
__global__ __launch_bounds__(256) void k_edge(const float* __restrict__ W,
                                              const float* __restrict__ b,
                                              const float* __restrict__ efeat,
                                              const float* __restrict__ Wemb,
                                              const float* __restrict__ bemb,
                                              int embed, int apply, int write_e,
                                              int do_stats) {
    extern __shared__ float dyn[];
    float* Ws = dyn;                  // [96][ESTR]
    float* Es = dyn + DD * ESTR;      // [128][ESTR]
    __shared__ float s_sum[DD], s_sq[DD], bsh[DD];
    __shared__ int s_src[128], s_dst[128];
    __shared__ float s_ef[128 * 4];
    __shared__ float s_wemb[4 * DD];
    __shared__ float s_bemb[DD];
    int t = threadIdx.x;
    int lane = t & 31, w = t >> 5;
    if (t < DD) { s_sum[t] = 0.f; s_sq[t] = 0.f; bsh[t] = b[t]; }
    // stage W, rounded to tf32
    for (int i = t; i < DD * 24; i += 256) {
        int k = i / 24, c4 = (i - (i / 24) * 24) * 4;
        float4 v = *(const float4*)(W + k * DD + c4);
        v.x = tf32r(v.x); v.y = tf32r(v.y); v.z = tf32r(v.z); v.w = tf32r(v.w);
        *(float4*)(Ws + k * ESTR + c4) = v;
    }
    int ebase = blockIdx.x * 128;   // EE % 128 == 0
    if (t < 128) { s_src[t] = g_srcp[ebase + t]; s_dst[t] = g_dstp[ebase + t]; }
    if (embed) {
        for (int i = t; i < 4 * DD; i += 256) s_wemb[i] = Wemb[i];
        if (t < DD) s_bemb[t] = bemb[t];
        if (t < 128) {
            int ei = g_eid[ebase + t];
            *(float4*)(s_ef + t * 4) = *(const float4*)(efeat + (size_t)ei * 4);
        }
        __syncthreads();
        for (int i = t; i < 128 * 12; i += 256) {
            int r = i / 12, c8 = (i - (i / 12) * 12) * 8;
            size_t idx = (size_t)(ebase + r) * DD + c8;
            float4 f = *(const float4*)(s_ef + r * 4);
            float v[8];
#pragma unroll
            for (int j = 0; j < 8; j++) {
                int c = c8 + j;
                v[j] = s_bemb[c] + f.x * s_wemb[c] + f.y * s_wemb[DD + c]
                     + f.z * s_wemb[2 * DD + c] + f.w * s_wemb[3 * DD + c];
            }
            *(uint4*)(g_e + idx) = f_to_bf8(v);
#pragma unroll
            for (int j = 0; j < 8; j++) v[j] = tf32r(v[j]);
            *(float4*)(Es + r * ESTR + c8)     = make_float4(v[0], v[1], v[2], v[3]);
            *(float4*)(Es + r * ESTR + c8 + 4) = make_float4(v[4], v[5], v[6], v[7]);
        }
    } else {
        for (int i = t; i < 128 * 12; i += 256) {
            int r = i / 12, c8 = (i - (i / 12) * 12) * 8;
            size_t idx = (size_t)(ebase + r) * DD + c8;
            uint4 ue = *(const uint4*)(g_e + idx);
            float v[8];
            bf8_to_f(ue, v);
            if (apply) {
                uint4 un = *(const uint4*)(g_enew + idx);
                float en[8];
                bf8_to_f(un, en);
                float4 sca = *(const float4*)(g_escale + c8);
                float4 scb = *(const float4*)(g_escale + c8 + 4);
                float4 sha = *(const float4*)(g_eshift + c8);
                float4 shb = *(const float4*)(g_eshift + c8 + 4);
                v[0] += fmaxf(sca.x * en[0] + sha.x, 0.f);
                v[1] += fmaxf(sca.y * en[1] + sha.y, 0.f);
                v[2] += fmaxf(sca.z * en[2] + sha.z, 0.f);
                v[3] += fmaxf(sca.w * en[3] + sha.w, 0.f);
                v[4] += fmaxf(scb.x * en[4] + shb.x, 0.f);
                v[5] += fmaxf(scb.y * en[5] + shb.y, 0.f);
                v[6] += fmaxf(scb.z * en[6] + shb.z, 0.f);
                v[7] += fmaxf(scb.w * en[7] + shb.w, 0.f);
                if (write_e) *(uint4*)(g_e + idx) = f_to_bf8(v);
            }
#pragma unroll
            for (int j = 0; j < 8; j++) v[j] = tf32r(v[j]);
            *(float4*)(Es + r * ESTR + c8)     = make_float4(v[0], v[1], v[2], v[3]);
            *(float4*)(Es + r * ESTR + c8 + 4) = make_float4(v[4], v[5], v[6], v[7]);
        }
    }
    __syncthreads();

    int mg = w >> 1, ng = w & 1;
    int m0 = mg * 32, n0 = ng * 48;
    int g = lane >> 2, c4 = lane & 3;
    float acc[2][6][4];
#pragma unroll
    for (int i = 0; i < 2; i++)
#pragma unroll
        for (int j = 0; j < 6; j++)
#pragma unroll
            for (int q = 0; q < 4; q++) acc[i][j][q] = 0.f;

#pragma unroll
    for (int k0 = 0; k0 < DD; k0 += 8) {
        unsigned a[2][4];
#pragma unroll
        for (int i = 0; i < 2; i++) {
            int rr = (m0 + i * 16 + g) * ESTR;
            a[i][0] = __float_as_uint(Es[rr + k0 + c4]);
            a[i][1] = __float_as_uint(Es[rr + 8 * ESTR + k0 + c4]);
            a[i][2] = __float_as_uint(Es[rr + k0 + 4 + c4]);
            a[i][3] = __float_as_uint(Es[rr + 8 * ESTR + k0 + 4 + c4]);
        }
#pragma unroll
        for (int j = 0; j < 6; j++) {
            int col = n0 + 8 * j + g;
            unsigned b0 = __float_as_uint(Ws[(k0 + c4) * ESTR + col]);
            unsigned b1 = __float_as_uint(Ws[(k0 + 4 + c4) * ESTR + col]);
            MMA_TF32(acc[0][j], a[0], b0, b1);
            MMA_TF32(acc[1][j], a[1], b0, b1);
        }
    }

    // epilogue: add bias + gathers, write enew (bf16), accumulate stats
    const float* Dh = g_ABDE + (size_t)2 * NN * DD;
    const float* Eh = g_ABDE + (size_t)3 * NN * DD;
    float cs[6][2], cq[6][2];
#pragma unroll
    for (int j = 0; j < 6; j++) { cs[j][0] = cs[j][1] = 0.f; cq[j][0] = cq[j][1] = 0.f; }
#pragma unroll
    for (int i = 0; i < 2; i++) {
#pragma unroll
        for (int half = 0; half < 2; half++) {
            int rl = m0 + i * 16 + half * 8 + g;
            size_t sb = (size_t)s_src[rl] * DD;
            size_t db = (size_t)s_dst[rl] * DD;
            size_t ob = (size_t)(ebase + rl) * DD;
#pragma unroll
            for (int j = 0; j < 6; j++) {
                int col = n0 + 8 * j + 2 * c4;
                float2 dh = *(const float2*)(Dh + sb + col);
                float2 eh = *(const float2*)(Eh + db + col);
                float v0 = acc[i][j][half * 2 + 0] + bsh[col]     + dh.x + eh.x;
                float v1 = acc[i][j][half * 2 + 1] + bsh[col + 1] + dh.y + eh.y;
                *(__nv_bfloat162*)(g_enew + ob + col) =
                    __float22bfloat162_rn(make_float2(v0, v1));
                cs[j][0] += v0; cs[j][1] += v1;
                cq[j][0] += v0 * v0; cq[j][1] += v1 * v1;
            }
        }
    }
    if (do_stats) {
#pragma unroll
        for (int off = 16; off >= 4; off >>= 1) {
#pragma unroll
            for (int j = 0; j < 6; j++) {
#pragma unroll
                for (int p = 0; p < 2; p++) {
                    cs[j][p] += __shfl_down_sync(0xffffffffu, cs[j][p], off);
                    cq[j][p] += __shfl_down_sync(0xffffffffu, cq[j][p], off);
                }
            }
        }
        if (lane < 4) {
#pragma unroll
            for (int j = 0; j < 6; j++) {
#pragma unroll
                for (int p = 0; p < 2; p++) {
                    int col = n0 + 8 * j + 2 * lane + p;
                    atomicAdd(&s_sum[col], cs[j][p]);
                    atomicAdd(&s_sq[col], cq[j][p]);
                }
            }
        }
        __syncthreads();
        if (t < DD) {
            atomicAdd(&g_esum[t], (double)s_sum[t]);
            atomicAdd(&g_esq[t], (double)s_sq[t]);
        }
    }
}

// ------------------------- aggregation (CSR, sequential bf16 enew) ------------
__global__ __launch_bounds__(256) void k_agg() {
    __shared__ float ssum[DD], ssq[DD];
    int t = threadIdx.x;
    if (t < DD) { ssum[t] = 0.f; ssq[t] = 0.f; }
    __syncthreads();
    int w = t >> 5, ln = t & 31;
    int v = blockIdx.x * 8 + w;      // grid = NN/8 exact
    const float* Ah = g_ABDE;
    const float* Bh = g_ABDE + (size_t)NN * DD;
    float n0 = 0, n1 = 0, n2 = 0, d0 = 0, d1 = 0, d2 = 0;
    int p0 = g_ptr[v], p1 = g_ptr[v + 1];
    for (int p = p0; p < p1; p++) {
        int s = g_srcp[p];
        size_t eb = (size_t)p * DD;
        size_t sb = (size_t)s * DD;
        float x0 = __bfloat162float(g_enew[eb + ln]);
        float x1 = __bfloat162float(g_enew[eb + ln + 32]);
        float x2 = __bfloat162float(g_enew[eb + ln + 64]);
        float s0 = __fdividef(1.f, 1.f + __expf(-x0));
        float s1 = __fdividef(1.f, 1.f + __expf(-x1));
        float s2 = __fdividef(1.f, 1.f + __expf(-x2));
        n0 += s0 * Bh[sb + ln]; n1 += s1 * Bh[sb + ln + 32]; n2 += s2 * Bh[sb + ln + 64];
        d0 += s0; d1 += s1; d2 += s2;
    }
    size_t vb = (size_t)v * DD;
    float h0 = Ah[vb + ln]      + __fdividef(n0, d0 + 1e-6f);
    float h1 = Ah[vb + ln + 32] + __fdividef(n1, d1 + 1e-6f);
    float h2 = Ah[vb + ln + 64] + __fdividef(n2, d2 + 1e-6f);
    g_hnew[vb + ln] = h0; g_hnew[vb + ln + 32] = h1; g_hnew[vb + ln + 64] = h2;
    atomicAdd(&ssum[ln], h0);      atomicAdd(&ssum[ln + 32], h1); atomicAdd(&ssum[ln + 64], h2);
    atomicAdd(&ssq[ln], h0 * h0);  atomicAdd(&ssq[ln + 32], h1 * h1); atomicAdd(&ssq[ln + 64], h2 * h2);
    __syncthreads();
    if (t < DD) {
        atomicAdd(&g_hsum[t], (double)ssum[t]);
        atomicAdd(&g_hsq[t], (double)ssq[t]);
    }
}

// ------------------------- BN finalize ----------------------------------------
__global__ void k_finalize(const float* __restrict__ gamma, const float* __restrict__ beta,
                           double count, int which) {
    int c = threadIdx.x;
    if (c >= DD) return;
    double s, q;
    if (which == 0) { s = g_esum[c]; q = g_esq[c]; g_esum[c] = 0.0; g_esq[c] = 0.0; }
    else            { s = g_hsum[c]; q = g_hsq[c]; g_hsum[c] = 0.0; g_hsq[c] = 0.0; }
    double m = s / count;
    double var = q / count - m * m;
    float sc = gamma[c] * rsqrtf((float)var + 1e-5f);
    float sh = beta[c] - (float)m * sc;
    if (which == 0) { g_escale[c] = sc; g_eshift[c] = sh; }
    else            { g_hscale[c] = sc; g_hshift[c] = sh; }
}

// ------------------------- head: relu(h@W1+b1)@W2+b2, tanh, scale -------------
__global__ __launch_bounds__(256) void k_head(const float* __restrict__ W1,
                                              const float* __restrict__ b1,
                                              const float* __restrict__ W2,
                                              const float* __restrict__ b2,
                                              const float* __restrict__ maxa,
                                              float* __restrict__ out) {
    extern __shared__ float dyn[];
    float* W1s = dyn;                 // 96*128
    float* Hs  = W1s + DD * HIDN;     // 32*96
    float* His = Hs + 32 * DD;        // 32*132 (padded)
    float* W2s = His + 32 * 132;      // 128*8
    int t = threadIdx.x;
    for (int i = t; i < DD * HIDN; i += 256) W1s[i] = W1[i];
    for (int i = t; i < HIDN * OUTN; i += 256) W2s[i] = W2[i];
    int row0 = blockIdx.x * 32;
    for (int i = t; i < 32 * 24; i += 256) {
        int r = i / 24, c4 = (i - (i / 24) * 24) * 4;
        int gr = row0 + r;
        float4 v = make_float4(0.f, 0.f, 0.f, 0.f);
        if (gr < NN) {
            size_t idx = (size_t)gr * DD + c4;
            v = *(const float4*)(g_h + idx);
            float4 en = *(const float4*)(g_hnew + idx);
            float4 sc = *(const float4*)(g_hscale + c4);
            float4 sh = *(const float4*)(g_hshift + c4);
            v.x += fmaxf(sc.x * en.x + sh.x, 0.f);
            v.y += fmaxf(sc.y * en.y + sh.y, 0.f);
            v.z += fmaxf(sc.z * en.z + sh.z, 0.f);
            v.w += fmaxf(sc.w * en.w + sh.w, 0.f);
        }
        *(float4*)(Hs + r * DD + c4) = v;
    }
    __syncthreads();
    {
        int ng = t >> 5, hg = t & 31;
        int r0 = ng * 4, c0 = hg * 4;
        ull acc[4][2];
        float4 bv = *(const float4*)(b1 + c0);
        ull b01 = pk2(bv.x, bv.y), b23 = pk2(bv.z, bv.w);
#pragma unroll
        for (int r = 0; r < 4; r++) { acc[r][0] = b01; acc[r][1] = b23; }
#pragma unroll 4
        for (int k = 0; k < DD; k++) {
            ulonglong2 wv = *(const ulonglong2*)(W1s + k * HIDN + c0);
#pragma unroll
            for (int r = 0; r < 4; r++) {
                float x = Hs[(r0 + r) * DD + k];
                ull xx = pk2(x, x);
                acc[r][0] = fma2(xx, wv.x, acc[r][0]);
                acc[r][1] = fma2(xx, wv.y, acc[r][1]);
            }
        }
#pragma unroll
        for (int r = 0; r < 4; r++) {
            float2 a = upk(acc[r][0]), q = upk(acc[r][1]);
            His[(r0 + r) * 132 + c0 + 0] = fmaxf(a.x, 0.f);
            His[(r0 + r) * 132 + c0 + 1] = fmaxf(a.y, 0.f);
            His[(r0 + r) * 132 + c0 + 2] = fmaxf(q.x, 0.f);
            His[(r0 + r) * 132 + c0 + 3] = fmaxf(q.y, 0.f);
        }
    }
    __syncthreads();
    {
        int node = t >> 3, oc = t & 7;
        int gn = row0 + node;
        if (gn < NN) {
            float acc = b2[oc];
#pragma unroll 8
            for (int k = 0; k < HIDN; k++) acc += His[node * 132 + k] * W2s[k * OUTN + oc];
            out[(size_t)gn * OUTN + oc] = maxa[gn] * tanhf(acc);
        }
    }
}

// ------------------------- launch ---------------------------------------------
extern "C" void kernel_launch(void* const* d_in, const int* in_sizes, int n_in,
                              void* d_out, int out_size) {
    const float* h1      = (const float*)d_in[0];
    const float* h2      = (const float*)d_in[1];
    const float* z       = (const float*)d_in[2];
    const float* efeat   = (const float*)d_in[3];
    const float* maxa    = (const float*)d_in[4];
    const float* Wh_emb  = (const float*)d_in[5];
    const float* bh_emb  = (const float*)d_in[6];
    const float* We_emb  = (const float*)d_in[7];
    const float* be_emb  = (const float*)d_in[8];
    const float* WA      = (const float*)d_in[9];
    const float* bA      = (const float*)d_in[10];
    const float* WB      = (const float*)d_in[11];
    const float* bB      = (const float*)d_in[12];
    const float* WC      = (const float*)d_in[13];
    const float* bC      = (const float*)d_in[14];
    const float* WD      = (const float*)d_in[15];
    const float* bD      = (const float*)d_in[16];
    const float* WE      = (const float*)d_in[17];
    const float* bE      = (const float*)d_in[18];
    const float* bn_h_g  = (const float*)d_in[19];
    const float* bn_h_b  = (const float*)d_in[20];
    const float* bn_e_g  = (const float*)d_in[21];
    const float* bn_e_b  = (const float*)d_in[22];
    const float* W1      = (const float*)d_in[23];
    const float* b1      = (const float*)d_in[24];
    const float* W2      = (const float*)d_in[25];
    const float* b2      = (const float*)d_in[26];
    const int*   src     = (const int*)d_in[27];
    const int*   dst     = (const int*)d_in[28];
    float* out = (float*)d_out;

    cudaFuncSetAttribute(k_matABDE, cudaFuncAttributeMaxDynamicSharedMemorySize, 200 * 1024);
    cudaFuncSetAttribute(k_edge,    cudaFuncAttributeMaxDynamicSharedMemorySize, 100 * 1024);
    cudaFuncSetAttribute(k_head,    cudaFuncAttributeMaxDynamicSharedMemorySize, 96 * 1024);

    const int smem_abde = (DD * 384 + 64 * DD + 384) * 4;                       // ~173 KB
    const int smem_edge = (DD + 128) * ESTR * 4;                                // 96768
    const int smem_head = (DD * HIDN + 32 * DD + 32 * 132 + HIDN * OUTN) * 4;   // 82432

    k_zero<<<(NN + 255) / 256, 256>>>();
    k_embed_h<<<(NN * DD + 255) / 256, 256>>>(h1, h2, z, Wh_emb, bh_emb);

    k_count<<<EE / 256, 256>>>(dst);
    k_scan1<<<NBS, 256>>>();
    k_scan2<<<1, 256>>>();
    k_scan3<<<NBS, 256>>>();
    k_fill<<<EE / 256, 256>>>(dst);
    k_sortseg<<<(NN + 127) / 128, 128>>>();
    k_permidx<<<EE / 256, 256>>>(src, dst);

    const int ablk = (NN + 63) / 64;   // 782
    const int eblk = EE / 128;         // 6250

    for (int l = 0; l < 4; l++) {
        k_matABDE<<<ablk, 768, smem_abde>>>(WA + l * DD * DD, WB + l * DD * DD,
                                            WD + l * DD * DD, WE + l * DD * DD,
                                            bA + l * DD, bB + l * DD,
                                            bD + l * DD, bE + l * DD,
                                            l >= 1 ? 1 : 0);

        int embed = (l == 0) ? 1 : 0;
        int apply = (l >= 1) ? 1 : 0;
        int write_e = (l >= 1 && l < 3) ? 1 : 0;
        int do_stats = (l < 3) ? 1 : 0;
        k_edge<<<eblk, 256, smem_edge>>>(WC + l * DD * DD, bC + l * DD,
                                         efeat, We_emb, be_emb,
                                         embed, apply, write_e, do_stats);
        if (l < 3)
            k_finalize<<<1, DD>>>(bn_e_g + l * DD, bn_e_b + l * DD, (double)EE, 0);

        k_agg<<<NN / 8, 256>>>();
        k_finalize<<<1, DD>>>(bn_h_g + l * DD, bn_h_b + l * DD, (double)NN, 1);
    }

    k_head<<<(NN + 31) / 32, 256, smem_head>>>(W1, b1, W2, b2, maxa, out);
}

// round 8
// speedup vs baseline: 1.6337x; 1.1132x over previous
#include <cuda_runtime.h>
#include <cuda_bf16.h>
#include <math.h>

#define NN 50000
#define EE 800000
#define DD 96
#define HIDN 128
#define OUTN 8
#define NBS 196    // scan blocks = ceil(NN/256)
#define WSTR 104   // bf16 smem stride (elements) for W^T  — conflict-free
#define ESTRB 104  // bf16 smem stride (elements) for E tile

typedef unsigned long long ull;

// ------------------------- device scratch (no allocs allowed) ----------------
__device__ float g_h[(size_t)NN * DD];
__device__ float g_hnew[(size_t)NN * DD];
__device__ float g_ABDE[(size_t)4 * NN * DD];   // A,B,D,E
__device__ __nv_bfloat16 g_e[(size_t)EE * DD];     // permuted (CSR dst order)
__device__ __nv_bfloat16 g_enew[(size_t)EE * DD];  // permuted
__device__ int   g_cnt[NN];
__device__ int   g_ptr[NN + 1];
__device__ int   g_woff[NN];
__device__ int   g_eid[EE];
__device__ int   g_srcp[EE];
__device__ int   g_dstp[EE];
__device__ int   g_bsum[256];
__device__ int   g_boff[256];
__device__ double g_esum[DD], g_esq[DD], g_hsum[DD], g_hsq[DD];
__device__ float g_escale[DD], g_eshift[DD], g_hscale[DD], g_hshift[DD];

// ------------------------- packed f32x2 helpers ------------------------------
__device__ __forceinline__ ull pk2(float lo, float hi) {
    ull r; asm("mov.b64 %0,{%1,%2};" : "=l"(r) : "f"(lo), "f"(hi)); return r;
}
__device__ __forceinline__ ull fma2(ull a, ull b, ull c) {
    ull d; asm("fma.rn.f32x2 %0,%1,%2,%3;" : "=l"(d) : "l"(a), "l"(b), "l"(c)); return d;
}
__device__ __forceinline__ float2 upk(ull v) {
    float2 f; asm("mov.b64 {%0,%1},%2;" : "=f"(f.x), "=f"(f.y) : "l"(v)); return f;
}
#define MMA_BF16(d, a, b0_, b1_) \
    asm volatile("mma.sync.aligned.m16n8k16.row.col.f32.bf16.bf16.f32 " \
        "{%0,%1,%2,%3},{%4,%5,%6,%7},{%8,%9},{%0,%1,%2,%3};" \
        : "+f"(d[0]), "+f"(d[1]), "+f"(d[2]), "+f"(d[3]) \
        : "r"(a[0]), "r"(a[1]), "r"(a[2]), "r"(a[3]), "r"(b0_), "r"(b1_))

// unpack 8 bf16 (in a uint4) -> 8 floats
__device__ __forceinline__ void bf8_to_f(const uint4& u, float* f) {
    const __nv_bfloat162* p = (const __nv_bfloat162*)&u;
#pragma unroll
    for (int j = 0; j < 4; j++) {
        float2 t = __bfloat1622float2(p[j]);
        f[2 * j] = t.x; f[2 * j + 1] = t.y;
    }
}
__device__ __forceinline__ uint4 f_to_bf8(const float* f) {
    uint4 u;
    __nv_bfloat162* p = (__nv_bfloat162*)&u;
#pragma unroll
    for (int j = 0; j < 4; j++)
        p[j] = __float22bfloat162_rn(make_float2(f[2 * j], f[2 * j + 1]));
    return u;
}

// ------------------------- setup kernels -------------------------------------
__global__ void k_zero() {
    int i = blockIdx.x * blockDim.x + threadIdx.x;
    if (i < NN) g_cnt[i] = 0;
    if (i < DD) { g_esum[i] = 0.0; g_esq[i] = 0.0; g_hsum[i] = 0.0; g_hsq[i] = 0.0; }
}

__global__ void k_embed_h(const float* __restrict__ h1, const float* __restrict__ h2,
                          const float* __restrict__ z,
                          const float* __restrict__ W, const float* __restrict__ b) {
    __shared__ float Ws[26 * DD];
    int t = threadIdx.x;
    for (int i = t; i < 26 * DD; i += blockDim.x) Ws[i] = W[i];
    __syncthreads();
    int idx = blockIdx.x * blockDim.x + t;
    if (idx >= NN * DD) return;
    int r = idx / DD, c = idx - (idx / DD) * DD;
    float acc = b[c];
#pragma unroll
    for (int k = 0; k < 6; k++)  acc += h1[r * 6 + k]  * Ws[k * DD + c];
#pragma unroll
    for (int k = 0; k < 4; k++)  acc += h2[r * 4 + k]  * Ws[(6 + k) * DD + c];
#pragma unroll
    for (int k = 0; k < 16; k++) acc += z[r * 16 + k]  * Ws[(10 + k) * DD + c];
    g_h[idx] = acc;
}

// ------------------------- CSR build (deterministic, parallel scan) -----------
__global__ void k_count(const int* __restrict__ dst) {
    int i = blockIdx.x * blockDim.x + threadIdx.x;
    if (i < EE) atomicAdd(&g_cnt[dst[i]], 1);
}

__global__ void k_scan1() {
    __shared__ int sh[256];
    int t = threadIdx.x, b = blockIdx.x;
    int j = b * 256 + t;
    int v = (j < NN) ? g_cnt[j] : 0;
    sh[t] = v; __syncthreads();
    for (int off = 1; off < 256; off <<= 1) {
        int u = (t >= off) ? sh[t - off] : 0;
        __syncthreads();
        sh[t] += u;
        __syncthreads();
    }
    if (j < NN) g_ptr[j] = sh[t] - v;
    if (t == 255) g_bsum[b] = sh[t];
}

__global__ void k_scan2() {
    __shared__ int sh[256];
    int t = threadIdx.x;
    int v = (t < NBS) ? g_bsum[t] : 0;
    sh[t] = v; __syncthreads();
    for (int off = 1; off < 256; off <<= 1) {
        int u = (t >= off) ? sh[t - off] : 0;
        __syncthreads();
        sh[t] += u;
        __syncthreads();
    }
    g_boff[t] = sh[t] - v;
}

__global__ void k_scan3() {
    int j = blockIdx.x * blockDim.x + threadIdx.x;
    if (j < NN) {
        int p = g_ptr[j] + g_boff[j >> 8];
        g_ptr[j] = p; g_woff[j] = p;
    }
    if (j == 0) g_ptr[NN] = EE;
}

__global__ void k_fill(const int* __restrict__ dst) {
    int i = blockIdx.x * blockDim.x + threadIdx.x;
    if (i < EE) {
        int pos = atomicAdd(&g_woff[dst[i]], 1);
        g_eid[pos] = i;
    }
}

__global__ void k_sortseg() {
    int v = blockIdx.x * blockDim.x + threadIdx.x;
    if (v >= NN) return;
    int lo = g_ptr[v], hi = g_ptr[v + 1];
    for (int i = lo + 1; i < hi; i++) {
        int key = g_eid[i]; int j = i - 1;
        while (j >= lo && g_eid[j] > key) { g_eid[j + 1] = g_eid[j]; j--; }
        g_eid[j + 1] = key;
    }
}

__global__ void k_permidx(const int* __restrict__ src, const int* __restrict__ dst) {
    int p = blockIdx.x * blockDim.x + threadIdx.x;
    if (p < EE) {
        int ei = g_eid[p];
        g_srcp[p] = src[ei];
        g_dstp[p] = dst[ei];
    }
}

// ------------------------- fused node GEMM: [A|B|D|E] = h @ Wcat + bcat -------
// 64 rows/block, 768 threads, 8x4 per-thread tile.
// Lazily applies h += relu(bn(hnew)) from the previous layer (writes g_h).
__global__ __launch_bounds__(768) void k_matABDE(const float* __restrict__ WA_,
                                                 const float* __restrict__ WB_,
                                                 const float* __restrict__ WD_,
                                                 const float* __restrict__ WE_,
                                                 const float* __restrict__ bA_,
                                                 const float* __restrict__ bB_,
                                                 const float* __restrict__ bD_,
                                                 const float* __restrict__ bE_,
                                                 int apply) {
    extern __shared__ float dyn[];
    float* Ws = dyn;                    // [96][384] concat
    float* Xs = dyn + DD * 384;         // [64][96]
    float* Bs = Xs + 64 * DD;           // [384]
    int t = threadIdx.x;
    const float* wsrc[4] = {WA_, WB_, WD_, WE_};
    const float* bsrc[4] = {bA_, bB_, bD_, bE_};
#pragma unroll
    for (int m = 0; m < 4; m++) {
        for (int i = t; i < DD * DD; i += 768) {
            int k = i / DD, c = i - (i / DD) * DD;
            Ws[k * 384 + m * DD + c] = wsrc[m][i];
        }
        if (t < DD) Bs[m * DD + t] = bsrc[m][t];
    }
    int row0 = blockIdx.x * 64;
    for (int i = t; i < 64 * 24; i += 768) {
        int r = i / 24, c4 = (i - (i / 24) * 24) * 4;
        int gr = row0 + r;
        float4 v = make_float4(0.f, 0.f, 0.f, 0.f);
        if (gr < NN) {
            size_t idx = (size_t)gr * DD + c4;
            v = *(const float4*)(g_h + idx);
            if (apply) {
                float4 en = *(const float4*)(g_hnew + idx);
                float4 sc = *(const float4*)(g_hscale + c4);
                float4 sh = *(const float4*)(g_hshift + c4);
                v.x += fmaxf(sc.x * en.x + sh.x, 0.f);
                v.y += fmaxf(sc.y * en.y + sh.y, 0.f);
                v.z += fmaxf(sc.z * en.z + sh.z, 0.f);
                v.w += fmaxf(sc.w * en.w + sh.w, 0.f);
                *(float4*)(g_h + idx) = v;
            }
        }
        *(float4*)(Xs + r * DD + c4) = v;
    }
    __syncthreads();
    int cg = t % 96, rg = t / 96;
    int c0 = cg * 4, r0 = rg * 8;
    ull acc[8][2];
    ull b01 = pk2(Bs[c0], Bs[c0 + 1]), b23 = pk2(Bs[c0 + 2], Bs[c0 + 3]);
#pragma unroll
    for (int r = 0; r < 8; r++) { acc[r][0] = b01; acc[r][1] = b23; }
#pragma unroll 6
    for (int k = 0; k < DD; k += 2) {
        ulonglong2 w0 = *(const ulonglong2*)(Ws + k * 384 + c0);
        ulonglong2 w1 = *(const ulonglong2*)(Ws + (k + 1) * 384 + c0);
#pragma unroll
        for (int r = 0; r < 8; r++) {
            float2 x = *(const float2*)(Xs + (r0 + r) * DD + k);
            ull x0 = pk2(x.x, x.x), x1 = pk2(x.y, x.y);
            acc[r][0] = fma2(x0, w0.x, acc[r][0]);
            acc[r][1] = fma2(x0, w0.y, acc[r][1]);
            acc[r][0] = fma2(x1, w1.x, acc[r][0]);
            acc[r][1] = fma2(x1, w1.y, acc[r][1]);
        }
    }
    int m = c0 / DD, cc = c0 - m * DD;
    float* outp = g_ABDE + (size_t)m * NN * DD;
#pragma unroll
    for (int r = 0; r < 8; r++) {
        int gr = row0 + r0 + r;
        if (gr < NN) {
            float2 a = upk(acc[r][0]), q = upk(acc[r][1]);
            *(float4*)(outp + (size_t)gr * DD + cc) = make_float4(a.x, a.y, q.x, q.y);
        }
    }
}

// ------------------------- edge kernel: bf16 tensor-core GEMM -----------------
// 128 edges/block, 8 warps; warp w owns 32 edges x 48 cols (2 m16 x 6 n8 tiles).
// bf16 operands in smem (45.5 KB total -> 4 CTAs/SM), m16n8k16 MMA, f32 accum.
__global__ __launch_bounds__(256) void k_edge(const float* __restrict__ W,
                                              const float* __restrict__ b,
                                              const float* __restrict__ efeat,
                                              const float* __restrict__ Wemb,
                                              const float* __restrict__ bemb,
                                              int embed, int apply, int write_e,
                                              int do_stats) {
    extern __shared__ char dync[];
    __nv_bfloat16* Wt = (__nv_bfloat16*)dync;        // [96 cols][WSTR k]
    __nv_bfloat16* Es = Wt + DD * WSTR;              // [128 rows][ESTRB k]
    __shared__ float s_sum[DD], s_sq[DD], bsh[DD];
    __shared__ int s_src[128], s_dst[128];
    __shared__ float s_ef[128 * 4];
    __shared__ float s_wemb[4 * DD];
    __shared__ float s_bemb[DD];
    int t = threadIdx.x;
    int lane = t & 31, w = t >> 5;
    if (t < DD) { s_sum[t] = 0.f; s_sq[t] = 0.f; bsh[t] = b[t]; }
    // stage W transposed into bf16: Wt[n][k] = bf16(W[k][n])
    for (int i = t; i < DD * 24; i += 256) {
        int k = i / 24, c4 = (i - (i / 24) * 24) * 4;
        float4 v = *(const float4*)(W + k * DD + c4);
        Wt[(c4 + 0) * WSTR + k] = __float2bfloat16(v.x);
        Wt[(c4 + 1) * WSTR + k] = __float2bfloat16(v.y);
        Wt[(c4 + 2) * WSTR + k] = __float2bfloat16(v.z);
        Wt[(c4 + 3) * WSTR + k] = __float2bfloat16(v.w);
    }
    int ebase = blockIdx.x * 128;   // EE % 128 == 0
    if (t < 128) { s_src[t] = g_srcp[ebase + t]; s_dst[t] = g_dstp[ebase + t]; }
    if (embed) {
        for (int i = t; i < 4 * DD; i += 256) s_wemb[i] = Wemb[i];
        if (t < DD) s_bemb[t] = bemb[t];
        if (t < 128) {
            int ei = g_eid[ebase + t];
            *(float4*)(s_ef + t * 4) = *(const float4*)(efeat + (size_t)ei * 4);
        }
        __syncthreads();
        for (int i = t; i < 128 * 12; i += 256) {
            int r = i / 12, c8 = (i - (i / 12) * 12) * 8;
            size_t idx = (size_t)(ebase + r) * DD + c8;
            float4 f = *(const float4*)(s_ef + r * 4);
            float v[8];
#pragma unroll
            for (int j = 0; j < 8; j++) {
                int c = c8 + j;
                v[j] = s_bemb[c] + f.x * s_wemb[c] + f.y * s_wemb[DD + c]
                     + f.z * s_wemb[2 * DD + c] + f.w * s_wemb[3 * DD + c];
            }
            uint4 packed = f_to_bf8(v);
            *(uint4*)(g_e + idx) = packed;
            *(uint4*)(Es + r * ESTRB + c8) = packed;
        }
    } else {
        for (int i = t; i < 128 * 12; i += 256) {
            int r = i / 12, c8 = (i - (i / 12) * 12) * 8;
            size_t idx = (size_t)(ebase + r) * DD + c8;
            uint4 ue = *(const uint4*)(g_e + idx);
            float v[8];
            bf8_to_f(ue, v);
            if (apply) {
                uint4 un = *(const uint4*)(g_enew + idx);
                float en[8];
                bf8_to_f(un, en);
                float4 sca = *(const float4*)(g_escale + c8);
                float4 scb = *(const float4*)(g_escale + c8 + 4);
                float4 sha = *(const float4*)(g_eshift + c8);
                float4 shb = *(const float4*)(g_eshift + c8 + 4);
                v[0] += fmaxf(sca.x * en[0] + sha.x, 0.f);
                v[1] += fmaxf(sca.y * en[1] + sha.y, 0.f);
                v[2] += fmaxf(sca.z * en[2] + sha.z, 0.f);
                v[3] += fmaxf(sca.w * en[3] + sha.w, 0.f);
                v[4] += fmaxf(scb.x * en[4] + shb.x, 0.f);
                v[5] += fmaxf(scb.y * en[5] + shb.y, 0.f);
                v[6] += fmaxf(scb.z * en[6] + shb.z, 0.f);
                v[7] += fmaxf(scb.w * en[7] + shb.w, 0.f);
                uint4 packed = f_to_bf8(v);
                if (write_e) *(uint4*)(g_e + idx) = packed;
                *(uint4*)(Es + r * ESTRB + c8) = packed;
            } else {
                *(uint4*)(Es + r * ESTRB + c8) = ue;
            }
        }
    }
    __syncthreads();

    int mg = w >> 1, ng = w & 1;
    int m0 = mg * 32, n0 = ng * 48;
    int g = lane >> 2, c4 = lane & 3;
    float acc[2][6][4];
#pragma unroll
    for (int i = 0; i < 2; i++)
#pragma unroll
        for (int j = 0; j < 6; j++)
#pragma unroll
            for (int q = 0; q < 4; q++) acc[i][j][q] = 0.f;

#pragma unroll
    for (int k0 = 0; k0 < DD; k0 += 16) {
        unsigned a[2][4];
#pragma unroll
        for (int i = 0; i < 2; i++) {
            int rr = (m0 + i * 16 + g) * ESTRB;
            a[i][0] = *(const unsigned*)(Es + rr + k0 + 2 * c4);
            a[i][1] = *(const unsigned*)(Es + rr + 8 * ESTRB + k0 + 2 * c4);
            a[i][2] = *(const unsigned*)(Es + rr + k0 + 8 + 2 * c4);
            a[i][3] = *(const unsigned*)(Es + rr + 8 * ESTRB + k0 + 8 + 2 * c4);
        }
#pragma unroll
        for (int j = 0; j < 6; j++) {
            int col = n0 + 8 * j + g;
            unsigned b0 = *(const unsigned*)(Wt + col * WSTR + k0 + 2 * c4);
            unsigned b1 = *(const unsigned*)(Wt + col * WSTR + k0 + 8 + 2 * c4);
            MMA_BF16(acc[0][j], a[0], b0, b1);
            MMA_BF16(acc[1][j], a[1], b0, b1);
        }
    }

    // epilogue: add bias + gathers, write enew (bf16), accumulate stats
    const float* Dh = g_ABDE + (size_t)2 * NN * DD;
    const float* Eh = g_ABDE + (size_t)3 * NN * DD;
    float cs[6][2], cq[6][2];
#pragma unroll
    for (int j = 0; j < 6; j++) { cs[j][0] = cs[j][1] = 0.f; cq[j][0] = cq[j][1] = 0.f; }
#pragma unroll
    for (int i = 0; i < 2; i++) {
#pragma unroll
        for (int half = 0; half < 2; half++) {
            int rl = m0 + i * 16 + half * 8 + g;
            size_t sb = (size_t)s_src[rl] * DD;
            size_t db = (size_t)s_dst[rl] * DD;
            size_t ob = (size_t)(ebase + rl) * DD;
#pragma unroll
            for (int j = 0; j < 6; j++) {
                int col = n0 + 8 * j + 2 * c4;
                float2 dh = *(const float2*)(Dh + sb + col);
                float2 eh = *(const float2*)(Eh + db + col);
                float v0 = acc[i][j][half * 2 + 0] + bsh[col]     + dh.x + eh.x;
                float v1 = acc[i][j][half * 2 + 1] + bsh[col + 1] + dh.y + eh.y;
                *(__nv_bfloat162*)(g_enew + ob + col) =
                    __float22bfloat162_rn(make_float2(v0, v1));
                cs[j][0] += v0; cs[j][1] += v1;
                cq[j][0] += v0 * v0; cq[j][1] += v1 * v1;
            }
        }
    }
    if (do_stats) {
#pragma unroll
        for (int off = 16; off >= 4; off >>= 1) {
#pragma unroll
            for (int j = 0; j < 6; j++) {
#pragma unroll
                for (int p = 0; p < 2; p++) {
                    cs[j][p] += __shfl_down_sync(0xffffffffu, cs[j][p], off);
                    cq[j][p] += __shfl_down_sync(0xffffffffu, cq[j][p], off);
                }
            }
        }
        if (lane < 4) {
#pragma unroll
            for (int j = 0; j < 6; j++) {
#pragma unroll
                for (int p = 0; p < 2; p++) {
                    int col = n0 + 8 * j + 2 * lane + p;
                    atomicAdd(&s_sum[col], cs[j][p]);
                    atomicAdd(&s_sq[col], cq[j][p]);
                }
            }
        }
        __syncthreads();
        if (t < DD) {
            atomicAdd(&g_esum[t], (double)s_sum[t]);
            atomicAdd(&g_esq[t], (double)s_sq[t]);
        }
    }
}

// ------------------------- aggregation (CSR, sequential bf16 enew) ------------
__global__ __launch_bounds__(256) void k_agg() {
    __shared__ float ssum[DD], ssq[DD];
    int t = threadIdx.x;
    if (t < DD) { ssum[t] = 0.f; ssq[t] = 0.f; }
    __syncthreads();
    int w = t >> 5, ln = t & 31;
    int v = blockIdx.x * 8 + w;      // grid = NN/8 exact
    const float* Ah = g_ABDE;
    const float* Bh = g_ABDE + (size_t)NN * DD;
    float n0 = 0, n1 = 0, n2 = 0, d0 = 0, d1 = 0, d2 = 0;
    int p0 = g_ptr[v], p1 = g_ptr[v + 1];
    for (int p = p0; p < p1; p++) {
        int s = g_srcp[p];
        size_t eb = (size_t)p * DD;
        size_t sb = (size_t)s * DD;
        float x0 = __bfloat162float(g_enew[eb + ln]);
        float x1 = __bfloat162float(g_enew[eb + ln + 32]);
        float x2 = __bfloat162float(g_enew[eb + ln + 64]);
        float s0 = __fdividef(1.f, 1.f + __expf(-x0));
        float s1 = __fdividef(1.f, 1.f + __expf(-x1));
        float s2 = __fdividef(1.f, 1.f + __expf(-x2));
        n0 += s0 * Bh[sb + ln]; n1 += s1 * Bh[sb + ln + 32]; n2 += s2 * Bh[sb + ln + 64];
        d0 += s0; d1 += s1; d2 += s2;
    }
    size_t vb = (size_t)v * DD;
    float h0 = Ah[vb + ln]      + __fdividef(n0, d0 + 1e-6f);
    float h1 = Ah[vb + ln + 32] + __fdividef(n1, d1 + 1e-6f);
    float h2 = Ah[vb + ln + 64] + __fdividef(n2, d2 + 1e-6f);
    g_hnew[vb + ln] = h0; g_hnew[vb + ln + 32] = h1; g_hnew[vb + ln + 64] = h2;
    atomicAdd(&ssum[ln], h0);      atomicAdd(&ssum[ln + 32], h1); atomicAdd(&ssum[ln + 64], h2);
    atomicAdd(&ssq[ln], h0 * h0);  atomicAdd(&ssq[ln + 32], h1 * h1); atomicAdd(&ssq[ln + 64], h2 * h2);
    __syncthreads();
    if (t < DD) {
        atomicAdd(&g_hsum[t], (double)ssum[t]);
        atomicAdd(&g_hsq[t], (double)ssq[t]);
    }
}

// ------------------------- BN finalize ----------------------------------------
__global__ void k_finalize(const float* __restrict__ gamma, const float* __restrict__ beta,
                           double count, int which) {
    int c = threadIdx.x;
    if (c >= DD) return;
    double s, q;
    if (which == 0) { s = g_esum[c]; q = g_esq[c]; g_esum[c] = 0.0; g_esq[c] = 0.0; }
    else            { s = g_hsum[c]; q = g_hsq[c]; g_hsum[c] = 0.0; g_hsq[c] = 0.0; }
    double m = s / count;
    double var = q / count - m * m;
    float sc = gamma[c] * rsqrtf((float)var + 1e-5f);
    float sh = beta[c] - (float)m * sc;
    if (which == 0) { g_escale[c] = sc; g_eshift[c] = sh; }
    else            { g_hscale[c] = sc; g_hshift[c] = sh; }
}

// ------------------------- head: relu(h@W1+b1)@W2+b2, tanh, scale -------------
__global__ __launch_bounds__(256) void k_head(const float* __restrict__ W1,
                                              const float* __restrict__ b1,
                                              const float* __restrict__ W2,
                                              const float* __restrict__ b2,
                                              const float* __restrict__ maxa,
                                              float* __restrict__ out) {
    extern __shared__ float dyn[];
    float* W1s = dyn;                 // 96*128
    float* Hs  = W1s + DD * HIDN;     // 32*96
    float* His = Hs + 32 * DD;        // 32*132 (padded)
    float* W2s = His + 32 * 132;      // 128*8
    int t = threadIdx.x;
    for (int i = t; i < DD * HIDN; i += 256) W1s[i] = W1[i];
    for (int i = t; i < HIDN * OUTN; i += 256) W2s[i] = W2[i];
    int row0 = blockIdx.x * 32;
    for (int i = t; i < 32 * 24; i += 256) {
        int r = i / 24, c4 = (i - (i / 24) * 24) * 4;
        int gr = row0 + r;
        float4 v = make_float4(0.f, 0.f, 0.f, 0.f);
        if (gr < NN) {
            size_t idx = (size_t)gr * DD + c4;
            v = *(const float4*)(g_h + idx);
            float4 en = *(const float4*)(g_hnew + idx);
            float4 sc = *(const float4*)(g_hscale + c4);
            float4 sh = *(const float4*)(g_hshift + c4);
            v.x += fmaxf(sc.x * en.x + sh.x, 0.f);
            v.y += fmaxf(sc.y * en.y + sh.y, 0.f);
            v.z += fmaxf(sc.z * en.z + sh.z, 0.f);
            v.w += fmaxf(sc.w * en.w + sh.w, 0.f);
        }
        *(float4*)(Hs + r * DD + c4) = v;
    }
    __syncthreads();
    {
        int ng = t >> 5, hg = t & 31;
        int r0 = ng * 4, c0 = hg * 4;
        ull acc[4][2];
        float4 bv = *(const float4*)(b1 + c0);
        ull b01 = pk2(bv.x, bv.y), b23 = pk2(bv.z, bv.w);
#pragma unroll
        for (int r = 0; r < 4; r++) { acc[r][0] = b01; acc[r][1] = b23; }
#pragma unroll 4
        for (int k = 0; k < DD; k++) {
            ulonglong2 wv = *(const ulonglong2*)(W1s + k * HIDN + c0);
#pragma unroll
            for (int r = 0; r < 4; r++) {
                float x = Hs[(r0 + r) * DD + k];
                ull xx = pk2(x, x);
                acc[r][0] = fma2(xx, wv.x, acc[r][0]);
                acc[r][1] = fma2(xx, wv.y, acc[r][1]);
            }
        }
#pragma unroll
        for (int r = 0; r < 4; r++) {
            float2 a = upk(acc[r][0]), q = upk(acc[r][1]);
            His[(r0 + r) * 132 + c0 + 0] = fmaxf(a.x, 0.f);
            His[(r0 + r) * 132 + c0 + 1] = fmaxf(a.y, 0.f);
            His[(r0 + r) * 132 + c0 + 2] = fmaxf(q.x, 0.f);
            His[(r0 + r) * 132 + c0 + 3] = fmaxf(q.y, 0.f);
        }
    }
    __syncthreads();
    {
        int node = t >> 3, oc = t & 7;
        int gn = row0 + node;
        if (gn < NN) {
            float acc = b2[oc];
#pragma unroll 8
            for (int k = 0; k < HIDN; k++) acc += His[node * 132 + k] * W2s[k * OUTN + oc];
            out[(size_t)gn * OUTN + oc] = maxa[gn] * tanhf(acc);
        }
    }
}

// ------------------------- launch ---------------------------------------------
extern "C" void kernel_launch(void* const* d_in, const int* in_sizes, int n_in,
                              void* d_out, int out_size) {
    const float* h1      = (const float*)d_in[0];
    const float* h2      = (const float*)d_in[1];
    const float* z       = (const float*)d_in[2];
    const float* efeat   = (const float*)d_in[3];
    const float* maxa    = (const float*)d_in[4];
    const float* Wh_emb  = (const float*)d_in[5];
    const float* bh_emb  = (const float*)d_in[6];
    const float* We_emb  = (const float*)d_in[7];
    const float* be_emb  = (const float*)d_in[8];
    const float* WA      = (const float*)d_in[9];
    const float* bA      = (const float*)d_in[10];
    const float* WB      = (const float*)d_in[11];
    const float* bB      = (const float*)d_in[12];
    const float* WC      = (const float*)d_in[13];
    const float* bC      = (const float*)d_in[14];
    const float* WD      = (const float*)d_in[15];
    const float* bD      = (const float*)d_in[16];
    const float* WE      = (const float*)d_in[17];
    const float* bE      = (const float*)d_in[18];
    const float* bn_h_g  = (const float*)d_in[19];
    const float* bn_h_b  = (const float*)d_in[20];
    const float* bn_e_g  = (const float*)d_in[21];
    const float* bn_e_b  = (const float*)d_in[22];
    const float* W1      = (const float*)d_in[23];
    const float* b1      = (const float*)d_in[24];
    const float* W2      = (const float*)d_in[25];
    const float* b2      = (const float*)d_in[26];
    const int*   src     = (const int*)d_in[27];
    const int*   dst     = (const int*)d_in[28];
    float* out = (float*)d_out;

    cudaFuncSetAttribute(k_matABDE, cudaFuncAttributeMaxDynamicSharedMemorySize, 200 * 1024);
    cudaFuncSetAttribute(k_edge,    cudaFuncAttributeMaxDynamicSharedMemorySize, 64 * 1024);
    cudaFuncSetAttribute(k_head,    cudaFuncAttributeMaxDynamicSharedMemorySize, 96 * 1024);

    const int smem_abde = (DD * 384 + 64 * DD + 384) * 4;                       // ~173 KB
    const int smem_edge = (DD * WSTR + 128 * ESTRB) * 2;                        // 46592
    const int smem_head = (DD * HIDN + 32 * DD + 32 * 132 + HIDN * OUTN) * 4;   // 82432

    k_zero<<<(NN + 255) / 256, 256>>>();
    k_embed_h<<<(NN * DD + 255) / 256, 256>>>(h1, h2, z, Wh_emb, bh_emb);

    k_count<<<EE / 256, 256>>>(dst);
    k_scan1<<<NBS, 256>>>();
    k_scan2<<<1, 256>>>();
    k_scan3<<<NBS, 256>>>();
    k_fill<<<EE / 256, 256>>>(dst);
    k_sortseg<<<(NN + 127) / 128, 128>>>();
    k_permidx<<<EE / 256, 256>>>(src, dst);

    const int ablk = (NN + 63) / 64;   // 782
    const int eblk = EE / 128;         // 6250

    for (int l = 0; l < 4; l++) {
        k_matABDE<<<ablk, 768, smem_abde>>>(WA + l * DD * DD, WB + l * DD * DD,
                                            WD + l * DD * DD, WE + l * DD * DD,
                                            bA + l * DD, bB + l * DD,
                                            bD + l * DD, bE + l * DD,
                                            l >= 1 ? 1 : 0);

        int embed = (l == 0) ? 1 : 0;
        int apply = (l >= 1) ? 1 : 0;
        int write_e = (l >= 1 && l < 3) ? 1 : 0;
        int do_stats = (l < 3) ? 1 : 0;
        k_edge<<<eblk, 256, smem_edge>>>(WC + l * DD * DD, bC + l * DD,
                                         efeat, We_emb, be_emb,
                                         embed, apply, write_e, do_stats);
        if (l < 3)
            k_finalize<<<1, DD>>>(bn_e_g + l * DD, bn_e_b + l * DD, (double)EE, 0);

        k_agg<<<NN / 8, 256>>>();
        k_finalize<<<1, DD>>>(bn_h_g + l * DD, bn_h_b + l * DD, (double)NN, 1);
    }

    k_head<<<(NN + 31) / 32, 256, smem_head>>>(W1, b1, W2, b2, maxa, out);
}

// round 9
// speedup vs baseline: 1.7965x; 1.0996x over previous
#include <cuda_runtime.h>
#include <cuda_bf16.h>
#include <math.h>

#define NN 50000
#define EE 800000
#define DD 96
#define HIDN 128
#define OUTN 8
#define NBS 196    // scan blocks = ceil(NN/256)
#define WSTR 104   // bf16 smem stride (elements) for W^T  — conflict-free
#define ESTRB 104  // bf16 smem stride (elements) for E tile

typedef unsigned long long ull;

// ------------------------- device scratch (no allocs allowed) ----------------
__device__ float g_h[(size_t)NN * DD];
__device__ float g_hnew[(size_t)NN * DD];
__device__ float g_A[(size_t)NN * DD];             // f32 (residual-critical)
__device__ __nv_bfloat16 g_B[(size_t)NN * DD];     // gathered tables in bf16
__device__ __nv_bfloat16 g_D[(size_t)NN * DD];
__device__ __nv_bfloat16 g_E[(size_t)NN * DD];
__device__ __nv_bfloat16 g_e[(size_t)EE * DD];     // permuted (CSR dst order)
__device__ __nv_bfloat16 g_enew[(size_t)EE * DD];  // permuted
__device__ int   g_cnt[NN];
__device__ int   g_ptr[NN + 1];
__device__ int   g_woff[NN];
__device__ int   g_eid[EE];
__device__ int   g_srcp[EE];
__device__ int   g_dstp[EE];
__device__ int   g_bsum[256];
__device__ int   g_boff[256];
__device__ double g_esum[DD], g_esq[DD], g_hsum[DD], g_hsq[DD];
__device__ float g_escale[DD], g_eshift[DD], g_hscale[DD], g_hshift[DD];

// ------------------------- packed f32x2 helpers ------------------------------
__device__ __forceinline__ ull pk2(float lo, float hi) {
    ull r; asm("mov.b64 %0,{%1,%2};" : "=l"(r) : "f"(lo), "f"(hi)); return r;
}
__device__ __forceinline__ ull fma2(ull a, ull b, ull c) {
    ull d; asm("fma.rn.f32x2 %0,%1,%2,%3;" : "=l"(d) : "l"(a), "l"(b), "l"(c)); return d;
}
__device__ __forceinline__ float2 upk(ull v) {
    float2 f; asm("mov.b64 {%0,%1},%2;" : "=f"(f.x), "=f"(f.y) : "l"(v)); return f;
}
#define MMA_BF16(d, a, b0_, b1_) \
    asm volatile("mma.sync.aligned.m16n8k16.row.col.f32.bf16.bf16.f32 " \
        "{%0,%1,%2,%3},{%4,%5,%6,%7},{%8,%9},{%0,%1,%2,%3};" \
        : "+f"(d[0]), "+f"(d[1]), "+f"(d[2]), "+f"(d[3]) \
        : "r"(a[0]), "r"(a[1]), "r"(a[2]), "r"(a[3]), "r"(b0_), "r"(b1_))

// unpack 8 bf16 (in a uint4) -> 8 floats
__device__ __forceinline__ void bf8_to_f(const uint4& u, float* f) {
    const __nv_bfloat162* p = (const __nv_bfloat162*)&u;
#pragma unroll
    for (int j = 0; j < 4; j++) {
        float2 t = __bfloat1622float2(p[j]);
        f[2 * j] = t.x; f[2 * j + 1] = t.y;
    }
}
__device__ __forceinline__ uint4 f_to_bf8(const float* f) {
    uint4 u;
    __nv_bfloat162* p = (__nv_bfloat162*)&u;
#pragma unroll
    for (int j = 0; j < 4; j++)
        p[j] = __float22bfloat162_rn(make_float2(f[2 * j], f[2 * j + 1]));
    return u;
}

// ------------------------- setup kernels -------------------------------------
__global__ void k_zero() {
    int i = blockIdx.x * blockDim.x + threadIdx.x;
    if (i < NN) g_cnt[i] = 0;
    if (i < DD) { g_esum[i] = 0.0; g_esq[i] = 0.0; g_hsum[i] = 0.0; g_hsq[i] = 0.0; }
}

__global__ void k_embed_h(const float* __restrict__ h1, const float* __restrict__ h2,
                          const float* __restrict__ z,
                          const float* __restrict__ W, const float* __restrict__ b) {
    __shared__ float Ws[26 * DD];
    int t = threadIdx.x;
    for (int i = t; i < 26 * DD; i += blockDim.x) Ws[i] = W[i];
    __syncthreads();
    int idx = blockIdx.x * blockDim.x + t;
    if (idx >= NN * DD) return;
    int r = idx / DD, c = idx - (idx / DD) * DD;
    float acc = b[c];
#pragma unroll
    for (int k = 0; k < 6; k++)  acc += h1[r * 6 + k]  * Ws[k * DD + c];
#pragma unroll
    for (int k = 0; k < 4; k++)  acc += h2[r * 4 + k]  * Ws[(6 + k) * DD + c];
#pragma unroll
    for (int k = 0; k < 16; k++) acc += z[r * 16 + k]  * Ws[(10 + k) * DD + c];
    g_h[idx] = acc;
}

// ------------------------- CSR build (deterministic, parallel scan) -----------
__global__ void k_count(const int* __restrict__ dst) {
    int i = blockIdx.x * blockDim.x + threadIdx.x;
    if (i < EE) atomicAdd(&g_cnt[dst[i]], 1);
}

__global__ void k_scan1() {
    __shared__ int sh[256];
    int t = threadIdx.x, b = blockIdx.x;
    int j = b * 256 + t;
    int v = (j < NN) ? g_cnt[j] : 0;
    sh[t] = v; __syncthreads();
    for (int off = 1; off < 256; off <<= 1) {
        int u = (t >= off) ? sh[t - off] : 0;
        __syncthreads();
        sh[t] += u;
        __syncthreads();
    }
    if (j < NN) g_ptr[j] = sh[t] - v;
    if (t == 255) g_bsum[b] = sh[t];
}

__global__ void k_scan2() {
    __shared__ int sh[256];
    int t = threadIdx.x;
    int v = (t < NBS) ? g_bsum[t] : 0;
    sh[t] = v; __syncthreads();
    for (int off = 1; off < 256; off <<= 1) {
        int u = (t >= off) ? sh[t - off] : 0;
        __syncthreads();
        sh[t] += u;
        __syncthreads();
    }
    g_boff[t] = sh[t] - v;
}

__global__ void k_scan3() {
    int j = blockIdx.x * blockDim.x + threadIdx.x;
    if (j < NN) {
        int p = g_ptr[j] + g_boff[j >> 8];
        g_ptr[j] = p; g_woff[j] = p;
    }
    if (j == 0) g_ptr[NN] = EE;
}

__global__ void k_fill(const int* __restrict__ dst) {
    int i = blockIdx.x * blockDim.x + threadIdx.x;
    if (i < EE) {
        int pos = atomicAdd(&g_woff[dst[i]], 1);
        g_eid[pos] = i;
    }
}

__global__ void k_sortseg() {
    int v = blockIdx.x * blockDim.x + threadIdx.x;
    if (v >= NN) return;
    int lo = g_ptr[v], hi = g_ptr[v + 1];
    for (int i = lo + 1; i < hi; i++) {
        int key = g_eid[i]; int j = i - 1;
        while (j >= lo && g_eid[j] > key) { g_eid[j + 1] = g_eid[j]; j--; }
        g_eid[j + 1] = key;
    }
}

__global__ void k_permidx(const int* __restrict__ src, const int* __restrict__ dst) {
    int p = blockIdx.x * blockDim.x + threadIdx.x;
    if (p < EE) {
        int ei = g_eid[p];
        g_srcp[p] = src[ei];
        g_dstp[p] = dst[ei];
    }
}

// ------------------------- fused node GEMM: [A|B|D|E] = h @ Wcat + bcat -------
// 64 rows/block, 768 threads, 8x4 per-thread tile.
// A written f32; B/D/E written bf16. Lazy h += relu(bn(hnew)) on staging.
__global__ __launch_bounds__(768) void k_matABDE(const float* __restrict__ WA_,
                                                 const float* __restrict__ WB_,
                                                 const float* __restrict__ WD_,
                                                 const float* __restrict__ WE_,
                                                 const float* __restrict__ bA_,
                                                 const float* __restrict__ bB_,
                                                 const float* __restrict__ bD_,
                                                 const float* __restrict__ bE_,
                                                 int apply) {
    extern __shared__ float dyn[];
    float* Ws = dyn;                    // [96][384] concat
    float* Xs = dyn + DD * 384;         // [64][96]
    float* Bs = Xs + 64 * DD;           // [384]
    int t = threadIdx.x;
    const float* wsrc[4] = {WA_, WB_, WD_, WE_};
    const float* bsrc[4] = {bA_, bB_, bD_, bE_};
#pragma unroll
    for (int m = 0; m < 4; m++) {
        for (int i = t; i < DD * DD; i += 768) {
            int k = i / DD, c = i - (i / DD) * DD;
            Ws[k * 384 + m * DD + c] = wsrc[m][i];
        }
        if (t < DD) Bs[m * DD + t] = bsrc[m][t];
    }
    int row0 = blockIdx.x * 64;
    for (int i = t; i < 64 * 24; i += 768) {
        int r = i / 24, c4 = (i - (i / 24) * 24) * 4;
        int gr = row0 + r;
        float4 v = make_float4(0.f, 0.f, 0.f, 0.f);
        if (gr < NN) {
            size_t idx = (size_t)gr * DD + c4;
            v = *(const float4*)(g_h + idx);
            if (apply) {
                float4 en = *(const float4*)(g_hnew + idx);
                float4 sc = *(const float4*)(g_hscale + c4);
                float4 sh = *(const float4*)(g_hshift + c4);
                v.x += fmaxf(sc.x * en.x + sh.x, 0.f);
                v.y += fmaxf(sc.y * en.y + sh.y, 0.f);
                v.z += fmaxf(sc.z * en.z + sh.z, 0.f);
                v.w += fmaxf(sc.w * en.w + sh.w, 0.f);
                *(float4*)(g_h + idx) = v;
            }
        }
        *(float4*)(Xs + r * DD + c4) = v;
    }
    __syncthreads();
    int cg = t % 96, rg = t / 96;
    int c0 = cg * 4, r0 = rg * 8;
    ull acc[8][2];
    ull b01 = pk2(Bs[c0], Bs[c0 + 1]), b23 = pk2(Bs[c0 + 2], Bs[c0 + 3]);
#pragma unroll
    for (int r = 0; r < 8; r++) { acc[r][0] = b01; acc[r][1] = b23; }
#pragma unroll 6
    for (int k = 0; k < DD; k += 2) {
        ulonglong2 w0 = *(const ulonglong2*)(Ws + k * 384 + c0);
        ulonglong2 w1 = *(const ulonglong2*)(Ws + (k + 1) * 384 + c0);
#pragma unroll
        for (int r = 0; r < 8; r++) {
            float2 x = *(const float2*)(Xs + (r0 + r) * DD + k);
            ull x0 = pk2(x.x, x.x), x1 = pk2(x.y, x.y);
            acc[r][0] = fma2(x0, w0.x, acc[r][0]);
            acc[r][1] = fma2(x0, w0.y, acc[r][1]);
            acc[r][0] = fma2(x1, w1.x, acc[r][0]);
            acc[r][1] = fma2(x1, w1.y, acc[r][1]);
        }
    }
    int m = c0 / DD, cc = c0 - m * DD;
    __nv_bfloat16* outb = (m == 1) ? g_B : (m == 2) ? g_D : g_E;
#pragma unroll
    for (int r = 0; r < 8; r++) {
        int gr = row0 + r0 + r;
        if (gr < NN) {
            float2 a = upk(acc[r][0]), q = upk(acc[r][1]);
            if (m == 0) {
                *(float4*)(g_A + (size_t)gr * DD + cc) = make_float4(a.x, a.y, q.x, q.y);
            } else {
                uint2 pb;
                __nv_bfloat162* pp = (__nv_bfloat162*)&pb;
                pp[0] = __float22bfloat162_rn(a);
                pp[1] = __float22bfloat162_rn(q);
                *(uint2*)(outb + (size_t)gr * DD + cc) = pb;
            }
        }
    }
}

// ------------------------- edge kernel: bf16 tensor-core GEMM -----------------
// 128 edges/block, 8 warps; warp w owns 32 edges x 48 cols (2 m16 x 6 n8 tiles).
// bf16 operands in smem (45.5 KB total -> 4 CTAs/SM), m16n8k16 MMA, f32 accum.
__global__ __launch_bounds__(256) void k_edge(const float* __restrict__ W,
                                              const float* __restrict__ b,
                                              const float* __restrict__ efeat,
                                              const float* __restrict__ Wemb,
                                              const float* __restrict__ bemb,
                                              int embed, int apply, int write_e,
                                              int do_stats) {
    extern __shared__ char dync[];
    __nv_bfloat16* Wt = (__nv_bfloat16*)dync;        // [96 cols][WSTR k]
    __nv_bfloat16* Es = Wt + DD * WSTR;              // [128 rows][ESTRB k]
    __shared__ float s_sum[DD], s_sq[DD], bsh[DD];
    __shared__ int s_src[128], s_dst[128];
    __shared__ float s_ef[128 * 4];
    __shared__ float s_wemb[4 * DD];
    __shared__ float s_bemb[DD];
    int t = threadIdx.x;
    int lane = t & 31, w = t >> 5;
    if (t < DD) { s_sum[t] = 0.f; s_sq[t] = 0.f; bsh[t] = b[t]; }
    // stage W transposed into bf16: Wt[n][k] = bf16(W[k][n])
    for (int i = t; i < DD * 24; i += 256) {
        int k = i / 24, c4 = (i - (i / 24) * 24) * 4;
        float4 v = *(const float4*)(W + k * DD + c4);
        Wt[(c4 + 0) * WSTR + k] = __float2bfloat16(v.x);
        Wt[(c4 + 1) * WSTR + k] = __float2bfloat16(v.y);
        Wt[(c4 + 2) * WSTR + k] = __float2bfloat16(v.z);
        Wt[(c4 + 3) * WSTR + k] = __float2bfloat16(v.w);
    }
    int ebase = blockIdx.x * 128;   // EE % 128 == 0
    if (t < 128) { s_src[t] = g_srcp[ebase + t]; s_dst[t] = g_dstp[ebase + t]; }
    if (embed) {
        for (int i = t; i < 4 * DD; i += 256) s_wemb[i] = Wemb[i];
        if (t < DD) s_bemb[t] = bemb[t];
        if (t < 128) {
            int ei = g_eid[ebase + t];
            *(float4*)(s_ef + t * 4) = *(const float4*)(efeat + (size_t)ei * 4);
        }
        __syncthreads();
        for (int i = t; i < 128 * 12; i += 256) {
            int r = i / 12, c8 = (i - (i / 12) * 12) * 8;
            size_t idx = (size_t)(ebase + r) * DD + c8;
            float4 f = *(const float4*)(s_ef + r * 4);
            float v[8];
#pragma unroll
            for (int j = 0; j < 8; j++) {
                int c = c8 + j;
                v[j] = s_bemb[c] + f.x * s_wemb[c] + f.y * s_wemb[DD + c]
                     + f.z * s_wemb[2 * DD + c] + f.w * s_wemb[3 * DD + c];
            }
            uint4 packed = f_to_bf8(v);
            *(uint4*)(g_e + idx) = packed;
            *(uint4*)(Es + r * ESTRB + c8) = packed;
        }
    } else {
        for (int i = t; i < 128 * 12; i += 256) {
            int r = i / 12, c8 = (i - (i / 12) * 12) * 8;
            size_t idx = (size_t)(ebase + r) * DD + c8;
            uint4 ue = *(const uint4*)(g_e + idx);
            float v[8];
            bf8_to_f(ue, v);
            if (apply) {
                uint4 un = *(const uint4*)(g_enew + idx);
                float en[8];
                bf8_to_f(un, en);
                float4 sca = *(const float4*)(g_escale + c8);
                float4 scb = *(const float4*)(g_escale + c8 + 4);
                float4 sha = *(const float4*)(g_eshift + c8);
                float4 shb = *(const float4*)(g_eshift + c8 + 4);
                v[0] += fmaxf(sca.x * en[0] + sha.x, 0.f);
                v[1] += fmaxf(sca.y * en[1] + sha.y, 0.f);
                v[2] += fmaxf(sca.z * en[2] + sha.z, 0.f);
                v[3] += fmaxf(sca.w * en[3] + sha.w, 0.f);
                v[4] += fmaxf(scb.x * en[4] + shb.x, 0.f);
                v[5] += fmaxf(scb.y * en[5] + shb.y, 0.f);
                v[6] += fmaxf(scb.z * en[6] + shb.z, 0.f);
                v[7] += fmaxf(scb.w * en[7] + shb.w, 0.f);
                uint4 packed = f_to_bf8(v);
                if (write_e) *(uint4*)(g_e + idx) = packed;
                *(uint4*)(Es + r * ESTRB + c8) = packed;
            } else {
                *(uint4*)(Es + r * ESTRB + c8) = ue;
            }
        }
    }
    __syncthreads();

    int mg = w >> 1, ng = w & 1;
    int m0 = mg * 32, n0 = ng * 48;
    int g = lane >> 2, c4 = lane & 3;
    float acc[2][6][4];
#pragma unroll
    for (int i = 0; i < 2; i++)
#pragma unroll
        for (int j = 0; j < 6; j++)
#pragma unroll
            for (int q = 0; q < 4; q++) acc[i][j][q] = 0.f;

#pragma unroll
    for (int k0 = 0; k0 < DD; k0 += 16) {
        unsigned a[2][4];
#pragma unroll
        for (int i = 0; i < 2; i++) {
            int rr = (m0 + i * 16 + g) * ESTRB;
            a[i][0] = *(const unsigned*)(Es + rr + k0 + 2 * c4);
            a[i][1] = *(const unsigned*)(Es + rr + 8 * ESTRB + k0 + 2 * c4);
            a[i][2] = *(const unsigned*)(Es + rr + k0 + 8 + 2 * c4);
            a[i][3] = *(const unsigned*)(Es + rr + 8 * ESTRB + k0 + 8 + 2 * c4);
        }
#pragma unroll
        for (int j = 0; j < 6; j++) {
            int col = n0 + 8 * j + g;
            unsigned b0 = *(const unsigned*)(Wt + col * WSTR + k0 + 2 * c4);
            unsigned b1 = *(const unsigned*)(Wt + col * WSTR + k0 + 8 + 2 * c4);
            MMA_BF16(acc[0][j], a[0], b0, b1);
            MMA_BF16(acc[1][j], a[1], b0, b1);
        }
    }

    // epilogue: add bias + bf16 gathers, write enew (bf16), accumulate stats
    float cs[6][2], cq[6][2];
#pragma unroll
    for (int j = 0; j < 6; j++) { cs[j][0] = cs[j][1] = 0.f; cq[j][0] = cq[j][1] = 0.f; }
#pragma unroll
    for (int i = 0; i < 2; i++) {
#pragma unroll
        for (int half = 0; half < 2; half++) {
            int rl = m0 + i * 16 + half * 8 + g;
            size_t sb = (size_t)s_src[rl] * DD;
            size_t db = (size_t)s_dst[rl] * DD;
            size_t ob = (size_t)(ebase + rl) * DD;
#pragma unroll
            for (int j = 0; j < 6; j++) {
                int col = n0 + 8 * j + 2 * c4;
                float2 dh = __bfloat1622float2(*(const __nv_bfloat162*)(g_D + sb + col));
                float2 eh = __bfloat1622float2(*(const __nv_bfloat162*)(g_E + db + col));
                float v0 = acc[i][j][half * 2 + 0] + bsh[col]     + dh.x + eh.x;
                float v1 = acc[i][j][half * 2 + 1] + bsh[col + 1] + dh.y + eh.y;
                *(__nv_bfloat162*)(g_enew + ob + col) =
                    __float22bfloat162_rn(make_float2(v0, v1));
                cs[j][0] += v0; cs[j][1] += v1;
                cq[j][0] += v0 * v0; cq[j][1] += v1 * v1;
            }
        }
    }
    if (do_stats) {
#pragma unroll
        for (int off = 16; off >= 4; off >>= 1) {
#pragma unroll
            for (int j = 0; j < 6; j++) {
#pragma unroll
                for (int p = 0; p < 2; p++) {
                    cs[j][p] += __shfl_down_sync(0xffffffffu, cs[j][p], off);
                    cq[j][p] += __shfl_down_sync(0xffffffffu, cq[j][p], off);
                }
            }
        }
        if (lane < 4) {
#pragma unroll
            for (int j = 0; j < 6; j++) {
#pragma unroll
                for (int p = 0; p < 2; p++) {
                    int col = n0 + 8 * j + 2 * lane + p;
                    atomicAdd(&s_sum[col], cs[j][p]);
                    atomicAdd(&s_sq[col], cq[j][p]);
                }
            }
        }
        __syncthreads();
        if (t < DD) {
            atomicAdd(&g_esum[t], (double)s_sum[t]);
            atomicAdd(&g_esq[t], (double)s_sq[t]);
        }
    }
}

// ------------------------- aggregation (CSR, bf16 enew + bf16 Bh) -------------
__global__ __launch_bounds__(256) void k_agg() {
    __shared__ float ssum[DD], ssq[DD];
    int t = threadIdx.x;
    if (t < DD) { ssum[t] = 0.f; ssq[t] = 0.f; }
    __syncthreads();
    int w = t >> 5, ln = t & 31;
    int v = blockIdx.x * 8 + w;      // grid = NN/8 exact
    float n0 = 0, n1 = 0, n2 = 0, d0 = 0, d1 = 0, d2 = 0;
    int p0 = g_ptr[v], p1 = g_ptr[v + 1];
    for (int p = p0; p < p1; p++) {
        int s = g_srcp[p];
        size_t eb = (size_t)p * DD;
        size_t sb = (size_t)s * DD;
        float x0 = __bfloat162float(g_enew[eb + ln]);
        float x1 = __bfloat162float(g_enew[eb + ln + 32]);
        float x2 = __bfloat162float(g_enew[eb + ln + 64]);
        float s0 = __fdividef(1.f, 1.f + __expf(-x0));
        float s1 = __fdividef(1.f, 1.f + __expf(-x1));
        float s2 = __fdividef(1.f, 1.f + __expf(-x2));
        n0 += s0 * __bfloat162float(g_B[sb + ln]);
        n1 += s1 * __bfloat162float(g_B[sb + ln + 32]);
        n2 += s2 * __bfloat162float(g_B[sb + ln + 64]);
        d0 += s0; d1 += s1; d2 += s2;
    }
    size_t vb = (size_t)v * DD;
    float h0 = g_A[vb + ln]      + __fdividef(n0, d0 + 1e-6f);
    float h1 = g_A[vb + ln + 32] + __fdividef(n1, d1 + 1e-6f);
    float h2 = g_A[vb + ln + 64] + __fdividef(n2, d2 + 1e-6f);
    g_hnew[vb + ln] = h0; g_hnew[vb + ln + 32] = h1; g_hnew[vb + ln + 64] = h2;
    atomicAdd(&ssum[ln], h0);      atomicAdd(&ssum[ln + 32], h1); atomicAdd(&ssum[ln + 64], h2);
    atomicAdd(&ssq[ln], h0 * h0);  atomicAdd(&ssq[ln + 32], h1 * h1); atomicAdd(&ssq[ln + 64], h2 * h2);
    __syncthreads();
    if (t < DD) {
        atomicAdd(&g_hsum[t], (double)ssum[t]);
        atomicAdd(&g_hsq[t], (double)ssq[t]);
    }
}

// ------------------------- BN finalize ----------------------------------------
__global__ void k_finalize(const float* __restrict__ gamma, const float* __restrict__ beta,
                           double count, int which) {
    int c = threadIdx.x;
    if (c >= DD) return;
    double s, q;
    if (which == 0) { s = g_esum[c]; q = g_esq[c]; g_esum[c] = 0.0; g_esq[c] = 0.0; }
    else            { s = g_hsum[c]; q = g_hsq[c]; g_hsum[c] = 0.0; g_hsq[c] = 0.0; }
    double m = s / count;
    double var = q / count - m * m;
    float sc = gamma[c] * rsqrtf((float)var + 1e-5f);
    float sh = beta[c] - (float)m * sc;
    if (which == 0) { g_escale[c] = sc; g_eshift[c] = sh; }
    else            { g_hscale[c] = sc; g_hshift[c] = sh; }
}

// ------------------------- head: relu(h@W1+b1)@W2+b2, tanh, scale -------------
__global__ __launch_bounds__(256) void k_head(const float* __restrict__ W1,
                                              const float* __restrict__ b1,
                                              const float* __restrict__ W2,
                                              const float* __restrict__ b2,
                                              const float* __restrict__ maxa,
                                              float* __restrict__ out) {
    extern __shared__ float dyn[];
    float* W1s = dyn;                 // 96*128
    float* Hs  = W1s + DD * HIDN;     // 32*96
    float* His = Hs + 32 * DD;        // 32*132 (padded)
    float* W2s = His + 32 * 132;      // 128*8
    int t = threadIdx.x;
    for (int i = t; i < DD * HIDN; i += 256) W1s[i] = W1[i];
    for (int i = t; i < HIDN * OUTN; i += 256) W2s[i] = W2[i];
    int row0 = blockIdx.x * 32;
    for (int i = t; i < 32 * 24; i += 256) {
        int r = i / 24, c4 = (i - (i / 24) * 24) * 4;
        int gr = row0 + r;
        float4 v = make_float4(0.f, 0.f, 0.f, 0.f);
        if (gr < NN) {
            size_t idx = (size_t)gr * DD + c4;
            v = *(const float4*)(g_h + idx);
            float4 en = *(const float4*)(g_hnew + idx);
            float4 sc = *(const float4*)(g_hscale + c4);
            float4 sh = *(const float4*)(g_hshift + c4);
            v.x += fmaxf(sc.x * en.x + sh.x, 0.f);
            v.y += fmaxf(sc.y * en.y + sh.y, 0.f);
            v.z += fmaxf(sc.z * en.z + sh.z, 0.f);
            v.w += fmaxf(sc.w * en.w + sh.w, 0.f);
        }
        *(float4*)(Hs + r * DD + c4) = v;
    }
    __syncthreads();
    {
        int ng = t >> 5, hg = t & 31;
        int r0 = ng * 4, c0 = hg * 4;
        ull acc[4][2];
        float4 bv = *(const float4*)(b1 + c0);
        ull b01 = pk2(bv.x, bv.y), b23 = pk2(bv.z, bv.w);
#pragma unroll
        for (int r = 0; r < 4; r++) { acc[r][0] = b01; acc[r][1] = b23; }
#pragma unroll 4
        for (int k = 0; k < DD; k++) {
            ulonglong2 wv = *(const ulonglong2*)(W1s + k * HIDN + c0);
#pragma unroll
            for (int r = 0; r < 4; r++) {
                float x = Hs[(r0 + r) * DD + k];
                ull xx = pk2(x, x);
                acc[r][0] = fma2(xx, wv.x, acc[r][0]);
                acc[r][1] = fma2(xx, wv.y, acc[r][1]);
            }
        }
#pragma unroll
        for (int r = 0; r < 4; r++) {
            float2 a = upk(acc[r][0]), q = upk(acc[r][1]);
            His[(r0 + r) * 132 + c0 + 0] = fmaxf(a.x, 0.f);
            His[(r0 + r) * 132 + c0 + 1] = fmaxf(a.y, 0.f);
            His[(r0 + r) * 132 + c0 + 2] = fmaxf(q.x, 0.f);
            His[(r0 + r) * 132 + c0 + 3] = fmaxf(q.y, 0.f);
        }
    }
    __syncthreads();
    {
        int node = t >> 3, oc = t & 7;
        int gn = row0 + node;
        if (gn < NN) {
            float acc = b2[oc];
#pragma unroll 8
            for (int k = 0; k < HIDN; k++) acc += His[node * 132 + k] * W2s[k * OUTN + oc];
            out[(size_t)gn * OUTN + oc] = maxa[gn] * tanhf(acc);
        }
    }
}

// ------------------------- launch ---------------------------------------------
extern "C" void kernel_launch(void* const* d_in, const int* in_sizes, int n_in,
                              void* d_out, int out_size) {
    const float* h1      = (const float*)d_in[0];
    const float* h2      = (const float*)d_in[1];
    const float* z       = (const float*)d_in[2];
    const float* efeat   = (const float*)d_in[3];
    const float* maxa    = (const float*)d_in[4];
    const float* Wh_emb  = (const float*)d_in[5];
    const float* bh_emb  = (const float*)d_in[6];
    const float* We_emb  = (const float*)d_in[7];
    const float* be_emb  = (const float*)d_in[8];
    const float* WA      = (const float*)d_in[9];
    const float* bA      = (const float*)d_in[10];
    const float* WB      = (const float*)d_in[11];
    const float* bB      = (const float*)d_in[12];
    const float* WC      = (const float*)d_in[13];
    const float* bC      = (const float*)d_in[14];
    const float* WD      = (const float*)d_in[15];
    const float* bD      = (const float*)d_in[16];
    const float* WE      = (const float*)d_in[17];
    const float* bE      = (const float*)d_in[18];
    const float* bn_h_g  = (const float*)d_in[19];
    const float* bn_h_b  = (const float*)d_in[20];
    const float* bn_e_g  = (const float*)d_in[21];
    const float* bn_e_b  = (const float*)d_in[22];
    const float* W1      = (const float*)d_in[23];
    const float* b1      = (const float*)d_in[24];
    const float* W2      = (const float*)d_in[25];
    const float* b2      = (const float*)d_in[26];
    const int*   src     = (const int*)d_in[27];
    const int*   dst     = (const int*)d_in[28];
    float* out = (float*)d_out;

    cudaFuncSetAttribute(k_matABDE, cudaFuncAttributeMaxDynamicSharedMemorySize, 200 * 1024);
    cudaFuncSetAttribute(k_edge,    cudaFuncAttributeMaxDynamicSharedMemorySize, 64 * 1024);
    cudaFuncSetAttribute(k_head,    cudaFuncAttributeMaxDynamicSharedMemorySize, 96 * 1024);

    const int smem_abde = (DD * 384 + 64 * DD + 384) * 4;                       // ~173 KB
    const int smem_edge = (DD * WSTR + 128 * ESTRB) * 2;                        // 46592
    const int smem_head = (DD * HIDN + 32 * DD + 32 * 132 + HIDN * OUTN) * 4;   // 82432

    k_zero<<<(NN + 255) / 256, 256>>>();
    k_embed_h<<<(NN * DD + 255) / 256, 256>>>(h1, h2, z, Wh_emb, bh_emb);

    k_count<<<EE / 256, 256>>>(dst);
    k_scan1<<<NBS, 256>>>();
    k_scan2<<<1, 256>>>();
    k_scan3<<<NBS, 256>>>();
    k_fill<<<EE / 256, 256>>>(dst);
    k_sortseg<<<(NN + 127) / 128, 128>>>();
    k_permidx<<<EE / 256, 256>>>(src, dst);

    const int ablk = (NN + 63) / 64;   // 782
    const int eblk = EE / 128;         // 6250

    for (int l = 0; l < 4; l++) {
        k_matABDE<<<ablk, 768, smem_abde>>>(WA + l * DD * DD, WB + l * DD * DD,
                                            WD + l * DD * DD, WE + l * DD * DD,
                                            bA + l * DD, bB + l * DD,
                                            bD + l * DD, bE + l * DD,
                                            l >= 1 ? 1 : 0);

        int embed = (l == 0) ? 1 : 0;
        int apply = (l >= 1) ? 1 : 0;
        int write_e = (l >= 1 && l < 3) ? 1 : 0;
        int do_stats = (l < 3) ? 1 : 0;
        k_edge<<<eblk, 256, smem_edge>>>(WC + l * DD * DD, bC + l * DD,
                                         efeat, We_emb, be_emb,
                                         embed, apply, write_e, do_stats);
        if (l < 3)
            k_finalize<<<1, DD>>>(bn_e_g + l * DD, bn_e_b + l * DD, (double)EE, 0);

        k_agg<<<NN / 8, 256>>>();
        k_finalize<<<1, DD>>>(bn_h_g + l * DD, bn_h_b + l * DD, (double)NN, 1);
    }

    k_head<<<(NN + 31) / 32, 256, smem_head>>>(W1, b1, W2, b2, maxa, out);
}

// round 10
// speedup vs baseline: 1.9180x; 1.0677x over previous
#include <cuda_runtime.h>
#include <cuda_bf16.h>
#include <math.h>

#define NN 50000
#define EE 800000
#define DD 96
#define HIDN 128
#define OUTN 8
#define NBS 196    // scan blocks = ceil(NN/256)
#define WSTR 104   // bf16 smem stride (elements) for W^T  — conflict-free (edge)
#define ESTRB 104  // bf16 smem stride (elements) for E tile (edge)
#define XSTR 108   // f32/tf32 smem stride for X tile (matABDE)
#define WS4 392    // f32/tf32 smem stride for concat W (matABDE)

typedef unsigned long long ull;

// ------------------------- device scratch (no allocs allowed) ----------------
__device__ float g_h[(size_t)NN * DD];
__device__ float g_hnew[(size_t)NN * DD];
__device__ float g_A[(size_t)NN * DD];             // f32 (residual-critical)
__device__ __nv_bfloat16 g_B[(size_t)NN * DD];     // gathered tables in bf16
__device__ __nv_bfloat16 g_D[(size_t)NN * DD];
__device__ __nv_bfloat16 g_E[(size_t)NN * DD];
__device__ __nv_bfloat16 g_e[(size_t)EE * DD];     // permuted (CSR dst order)
__device__ __nv_bfloat16 g_enew[(size_t)EE * DD];  // permuted
__device__ int   g_cnt[NN];
__device__ int   g_ptr[NN + 1];
__device__ int   g_woff[NN];
__device__ int   g_eid[EE];
__device__ int   g_srcp[EE];
__device__ int   g_dstp[EE];
__device__ int   g_bsum[256];
__device__ int   g_boff[256];
__device__ double g_esum[DD], g_esq[DD], g_hsum[DD], g_hsq[DD];
__device__ float g_escale[DD], g_eshift[DD], g_hscale[DD], g_hshift[DD];

// ------------------------- helpers -------------------------------------------
__device__ __forceinline__ ull pk2(float lo, float hi) {
    ull r; asm("mov.b64 %0,{%1,%2};" : "=l"(r) : "f"(lo), "f"(hi)); return r;
}
__device__ __forceinline__ ull fma2(ull a, ull b, ull c) {
    ull d; asm("fma.rn.f32x2 %0,%1,%2,%3;" : "=l"(d) : "l"(a), "l"(b), "l"(c)); return d;
}
__device__ __forceinline__ float2 upk(ull v) {
    float2 f; asm("mov.b64 {%0,%1},%2;" : "=f"(f.x), "=f"(f.y) : "l"(v)); return f;
}
__device__ __forceinline__ float tf32r(float x) {
    unsigned u; asm("cvt.rna.tf32.f32 %0,%1;" : "=r"(u) : "f"(x));
    return __uint_as_float(u);
}
#define MMA_TF32(d, a, b0_, b1_) \
    asm volatile("mma.sync.aligned.m16n8k8.row.col.f32.tf32.tf32.f32 " \
        "{%0,%1,%2,%3},{%4,%5,%6,%7},{%8,%9},{%0,%1,%2,%3};" \
        : "+f"(d[0]), "+f"(d[1]), "+f"(d[2]), "+f"(d[3]) \
        : "r"(a[0]), "r"(a[1]), "r"(a[2]), "r"(a[3]), "r"(b0_), "r"(b1_))
#define MMA_BF16(d, a, b0_, b1_) \
    asm volatile("mma.sync.aligned.m16n8k16.row.col.f32.bf16.bf16.f32 " \
        "{%0,%1,%2,%3},{%4,%5,%6,%7},{%8,%9},{%0,%1,%2,%3};" \
        : "+f"(d[0]), "+f"(d[1]), "+f"(d[2]), "+f"(d[3]) \
        : "r"(a[0]), "r"(a[1]), "r"(a[2]), "r"(a[3]), "r"(b0_), "r"(b1_))

__device__ __forceinline__ void bf8_to_f(const uint4& u, float* f) {
    const __nv_bfloat162* p = (const __nv_bfloat162*)&u;
#pragma unroll
    for (int j = 0; j < 4; j++) {
        float2 t = __bfloat1622float2(p[j]);
        f[2 * j] = t.x; f[2 * j + 1] = t.y;
    }
}
__device__ __forceinline__ uint4 f_to_bf8(const float* f) {
    uint4 u;
    __nv_bfloat162* p = (__nv_bfloat162*)&u;
#pragma unroll
    for (int j = 0; j < 4; j++)
        p[j] = __float22bfloat162_rn(make_float2(f[2 * j], f[2 * j + 1]));
    return u;
}

// ------------------------- setup kernels -------------------------------------
__global__ void k_zero() {
    int i = blockIdx.x * blockDim.x + threadIdx.x;
    if (i < NN) g_cnt[i] = 0;
    if (i < DD) { g_esum[i] = 0.0; g_esq[i] = 0.0; g_hsum[i] = 0.0; g_hsq[i] = 0.0; }
}

__global__ void k_embed_h(const float* __restrict__ h1, const float* __restrict__ h2,
                          const float* __restrict__ z,
                          const float* __restrict__ W, const float* __restrict__ b) {
    __shared__ float Ws[26 * DD];
    int t = threadIdx.x;
    for (int i = t; i < 26 * DD; i += blockDim.x) Ws[i] = W[i];
    __syncthreads();
    int idx = blockIdx.x * blockDim.x + t;
    if (idx >= NN * DD) return;
    int r = idx / DD, c = idx - (idx / DD) * DD;
    float acc = b[c];
#pragma unroll
    for (int k = 0; k < 6; k++)  acc += h1[r * 6 + k]  * Ws[k * DD + c];
#pragma unroll
    for (int k = 0; k < 4; k++)  acc += h2[r * 4 + k]  * Ws[(6 + k) * DD + c];
#pragma unroll
    for (int k = 0; k < 16; k++) acc += z[r * 16 + k]  * Ws[(10 + k) * DD + c];
    g_h[idx] = acc;
}

// ------------------------- CSR build (deterministic, parallel scan) -----------
__global__ void k_count(const int* __restrict__ dst) {
    int i = blockIdx.x * blockDim.x + threadIdx.x;
    if (i < EE) atomicAdd(&g_cnt[dst[i]], 1);
}

__global__ void k_scan1() {
    __shared__ int sh[256];
    int t = threadIdx.x, b = blockIdx.x;
    int j = b * 256 + t;
    int v = (j < NN) ? g_cnt[j] : 0;
    sh[t] = v; __syncthreads();
    for (int off = 1; off < 256; off <<= 1) {
        int u = (t >= off) ? sh[t - off] : 0;
        __syncthreads();
        sh[t] += u;
        __syncthreads();
    }
    if (j < NN) g_ptr[j] = sh[t] - v;
    if (t == 255) g_bsum[b] = sh[t];
}

__global__ void k_scan2() {
    __shared__ int sh[256];
    int t = threadIdx.x;
    int v = (t < NBS) ? g_bsum[t] : 0;
    sh[t] = v; __syncthreads();
    for (int off = 1; off < 256; off <<= 1) {
        int u = (t >= off) ? sh[t - off] : 0;
        __syncthreads();
        sh[t] += u;
        __syncthreads();
    }
    g_boff[t] = sh[t] - v;
}

__global__ void k_scan3() {
    int j = blockIdx.x * blockDim.x + threadIdx.x;
    if (j < NN) {
        int p = g_ptr[j] + g_boff[j >> 8];
        g_ptr[j] = p; g_woff[j] = p;
    }
    if (j == 0) g_ptr[NN] = EE;
}

__global__ void k_fill(const int* __restrict__ dst) {
    int i = blockIdx.x * blockDim.x + threadIdx.x;
    if (i < EE) {
        int pos = atomicAdd(&g_woff[dst[i]], 1);
        g_eid[pos] = i;
    }
}

__global__ void k_sortseg() {
    int v = blockIdx.x * blockDim.x + threadIdx.x;
    if (v >= NN) return;
    int lo = g_ptr[v], hi = g_ptr[v + 1];
    for (int i = lo + 1; i < hi; i++) {
        int key = g_eid[i]; int j = i - 1;
        while (j >= lo && g_eid[j] > key) { g_eid[j + 1] = g_eid[j]; j--; }
        g_eid[j + 1] = key;
    }
}

__global__ void k_permidx(const int* __restrict__ src, const int* __restrict__ dst) {
    int p = blockIdx.x * blockDim.x + threadIdx.x;
    if (p < EE) {
        int ei = g_eid[p];
        g_srcp[p] = src[ei];
        g_dstp[p] = dst[ei];
    }
}

// ------------------------- fused node GEMM (tf32 MMA) -------------------------
// [A|B|D|E] = h @ Wcat + bcat.  512 threads, 16 warps (2m x 8n), warp = 32x48.
// A written f32; B/D/E written bf16. Lazy h += relu(bn(hnew)) on staging.
__global__ __launch_bounds__(512) void k_matABDE(const float* __restrict__ WA_,
                                                 const float* __restrict__ WB_,
                                                 const float* __restrict__ WD_,
                                                 const float* __restrict__ WE_,
                                                 const float* __restrict__ bA_,
                                                 const float* __restrict__ bB_,
                                                 const float* __restrict__ bD_,
                                                 const float* __restrict__ bE_,
                                                 int apply) {
    extern __shared__ float dyn[];
    float* Ws = dyn;                     // [96 k][WS4] tf32, 4 matrices along cols
    float* Xs = dyn + DD * WS4;          // [64 rows][XSTR] tf32
    float* Bs = Xs + 64 * XSTR;          // [384] bias (f32)
    int t = threadIdx.x;
    int lane = t & 31, w = t >> 5;
    const float* wsrc[4] = {WA_, WB_, WD_, WE_};
    const float* bsrc[4] = {bA_, bB_, bD_, bE_};
#pragma unroll
    for (int m = 0; m < 4; m++) {
        for (int i = t; i < DD * DD; i += 512) {
            int k = i / DD, c = i - (i / DD) * DD;
            Ws[k * WS4 + m * DD + c] = tf32r(wsrc[m][i]);
        }
    }
    for (int i = t; i < 4 * DD; i += 512) Bs[i] = bsrc[i / DD][i - (i / DD) * DD];
    int row0 = blockIdx.x * 64;
    for (int i = t; i < 64 * 24; i += 512) {
        int r = i / 24, c4 = (i - (i / 24) * 24) * 4;
        int gr = row0 + r;
        float4 v = make_float4(0.f, 0.f, 0.f, 0.f);
        if (gr < NN) {
            size_t idx = (size_t)gr * DD + c4;
            v = *(const float4*)(g_h + idx);
            if (apply) {
                float4 en = *(const float4*)(g_hnew + idx);
                float4 sc = *(const float4*)(g_hscale + c4);
                float4 sh = *(const float4*)(g_hshift + c4);
                v.x += fmaxf(sc.x * en.x + sh.x, 0.f);
                v.y += fmaxf(sc.y * en.y + sh.y, 0.f);
                v.z += fmaxf(sc.z * en.z + sh.z, 0.f);
                v.w += fmaxf(sc.w * en.w + sh.w, 0.f);
                *(float4*)(g_h + idx) = v;
            }
        }
        v.x = tf32r(v.x); v.y = tf32r(v.y); v.z = tf32r(v.z); v.w = tf32r(v.w);
        *(float4*)(Xs + r * XSTR + c4) = v;
    }
    __syncthreads();

    int mg = w >> 3, ng = w & 7;          // 2 x 8 warp grid
    int m0 = mg * 32, n0 = ng * 48;
    int g = lane >> 2, c4 = lane & 3;
    float acc[2][6][4];
#pragma unroll
    for (int i = 0; i < 2; i++)
#pragma unroll
        for (int j = 0; j < 6; j++)
#pragma unroll
            for (int q = 0; q < 4; q++) acc[i][j][q] = 0.f;

#pragma unroll
    for (int k0 = 0; k0 < DD; k0 += 8) {
        unsigned a[2][4];
#pragma unroll
        for (int i = 0; i < 2; i++) {
            int rr = (m0 + i * 16 + g) * XSTR;
            a[i][0] = __float_as_uint(Xs[rr + k0 + c4]);
            a[i][1] = __float_as_uint(Xs[rr + 8 * XSTR + k0 + c4]);
            a[i][2] = __float_as_uint(Xs[rr + k0 + 4 + c4]);
            a[i][3] = __float_as_uint(Xs[rr + 8 * XSTR + k0 + 4 + c4]);
        }
#pragma unroll
        for (int j = 0; j < 6; j++) {
            int col = n0 + 8 * j + g;
            unsigned b0 = __float_as_uint(Ws[(k0 + c4) * WS4 + col]);
            unsigned b1 = __float_as_uint(Ws[(k0 + 4 + c4) * WS4 + col]);
            MMA_TF32(acc[0][j], a[0], b0, b1);
            MMA_TF32(acc[1][j], a[1], b0, b1);
        }
    }

    // epilogue: +bias, write A (f32) or B/D/E (bf16)
    int m = n0 / DD;                      // output matrix id (constant per warp)
    int ncc = n0 - m * DD;                // warp's col base inside the matrix
    __nv_bfloat16* outb = (m == 1) ? g_B : (m == 2) ? g_D : g_E;
#pragma unroll
    for (int i = 0; i < 2; i++) {
#pragma unroll
        for (int half = 0; half < 2; half++) {
            int rl = m0 + i * 16 + half * 8 + g;
            int gr = row0 + rl;
            if (gr < NN) {
#pragma unroll
                for (int j = 0; j < 6; j++) {
                    int col = n0 + 8 * j + 2 * c4;
                    int cc = ncc + 8 * j + 2 * c4;
                    float v0 = acc[i][j][half * 2 + 0] + Bs[col];
                    float v1 = acc[i][j][half * 2 + 1] + Bs[col + 1];
                    if (m == 0) {
                        *(float2*)(g_A + (size_t)gr * DD + cc) = make_float2(v0, v1);
                    } else {
                        *(__nv_bfloat162*)(outb + (size_t)gr * DD + cc) =
                            __float22bfloat162_rn(make_float2(v0, v1));
                    }
                }
            }
        }
    }
}

// ------------------------- edge kernel: bf16 tensor-core GEMM -----------------
__global__ __launch_bounds__(256) void k_edge(const float* __restrict__ W,
                                              const float* __restrict__ b,
                                              const float* __restrict__ efeat,
                                              const float* __restrict__ Wemb,
                                              const float* __restrict__ bemb,
                                              int embed, int apply, int write_e,
                                              int do_stats) {
    extern __shared__ char dync[];
    __nv_bfloat16* Wt = (__nv_bfloat16*)dync;        // [96 cols][WSTR k]
    __nv_bfloat16* Es = Wt + DD * WSTR;              // [128 rows][ESTRB k]
    __shared__ float s_sum[DD], s_sq[DD], bsh[DD];
    __shared__ int s_src[128], s_dst[128];
    __shared__ float s_ef[128 * 4];
    __shared__ float s_wemb[4 * DD];
    __shared__ float s_bemb[DD];
    int t = threadIdx.x;
    int lane = t & 31, w = t >> 5;
    if (t < DD) { s_sum[t] = 0.f; s_sq[t] = 0.f; bsh[t] = b[t]; }
    for (int i = t; i < DD * 24; i += 256) {
        int k = i / 24, c4 = (i - (i / 24) * 24) * 4;
        float4 v = *(const float4*)(W + k * DD + c4);
        Wt[(c4 + 0) * WSTR + k] = __float2bfloat16(v.x);
        Wt[(c4 + 1) * WSTR + k] = __float2bfloat16(v.y);
        Wt[(c4 + 2) * WSTR + k] = __float2bfloat16(v.z);
        Wt[(c4 + 3) * WSTR + k] = __float2bfloat16(v.w);
    }
    int ebase = blockIdx.x * 128;   // EE % 128 == 0
    if (t < 128) { s_src[t] = g_srcp[ebase + t]; s_dst[t] = g_dstp[ebase + t]; }
    if (embed) {
        for (int i = t; i < 4 * DD; i += 256) s_wemb[i] = Wemb[i];
        if (t < DD) s_bemb[t] = bemb[t];
        if (t < 128) {
            int ei = g_eid[ebase + t];
            *(float4*)(s_ef + t * 4) = *(const float4*)(efeat + (size_t)ei * 4);
        }
        __syncthreads();
        for (int i = t; i < 128 * 12; i += 256) {
            int r = i / 12, c8 = (i - (i / 12) * 12) * 8;
            size_t idx = (size_t)(ebase + r) * DD + c8;
            float4 f = *(const float4*)(s_ef + r * 4);
            float v[8];
#pragma unroll
            for (int j = 0; j < 8; j++) {
                int c = c8 + j;
                v[j] = s_bemb[c] + f.x * s_wemb[c] + f.y * s_wemb[DD + c]
                     + f.z * s_wemb[2 * DD + c] + f.w * s_wemb[3 * DD + c];
            }
            uint4 packed = f_to_bf8(v);
            *(uint4*)(g_e + idx) = packed;
            *(uint4*)(Es + r * ESTRB + c8) = packed;
        }
    } else {
        for (int i = t; i < 128 * 12; i += 256) {
            int r = i / 12, c8 = (i - (i / 12) * 12) * 8;
            size_t idx = (size_t)(ebase + r) * DD + c8;
            uint4 ue = *(const uint4*)(g_e + idx);
            float v[8];
            bf8_to_f(ue, v);
            if (apply) {
                uint4 un = *(const uint4*)(g_enew + idx);
                float en[8];
                bf8_to_f(un, en);
                float4 sca = *(const float4*)(g_escale + c8);
                float4 scb = *(const float4*)(g_escale + c8 + 4);
                float4 sha = *(const float4*)(g_eshift + c8);
                float4 shb = *(const float4*)(g_eshift + c8 + 4);
                v[0] += fmaxf(sca.x * en[0] + sha.x, 0.f);
                v[1] += fmaxf(sca.y * en[1] + sha.y, 0.f);
                v[2] += fmaxf(sca.z * en[2] + sha.z, 0.f);
                v[3] += fmaxf(sca.w * en[3] + sha.w, 0.f);
                v[4] += fmaxf(scb.x * en[4] + shb.x, 0.f);
                v[5] += fmaxf(scb.y * en[5] + shb.y, 0.f);
                v[6] += fmaxf(scb.z * en[6] + shb.z, 0.f);
                v[7] += fmaxf(scb.w * en[7] + shb.w, 0.f);
                uint4 packed = f_to_bf8(v);
                if (write_e) *(uint4*)(g_e + idx) = packed;
                *(uint4*)(Es + r * ESTRB + c8) = packed;
            } else {
                *(uint4*)(Es + r * ESTRB + c8) = ue;
            }
        }
    }
    __syncthreads();

    int mg = w >> 1, ng = w & 1;
    int m0 = mg * 32, n0 = ng * 48;
    int g = lane >> 2, c4 = lane & 3;
    float acc[2][6][4];
#pragma unroll
    for (int i = 0; i < 2; i++)
#pragma unroll
        for (int j = 0; j < 6; j++)
#pragma unroll
            for (int q = 0; q < 4; q++) acc[i][j][q] = 0.f;

#pragma unroll
    for (int k0 = 0; k0 < DD; k0 += 16) {
        unsigned a[2][4];
#pragma unroll
        for (int i = 0; i < 2; i++) {
            int rr = (m0 + i * 16 + g) * ESTRB;
            a[i][0] = *(const unsigned*)(Es + rr + k0 + 2 * c4);
            a[i][1] = *(const unsigned*)(Es + rr + 8 * ESTRB + k0 + 2 * c4);
            a[i][2] = *(const unsigned*)(Es + rr + k0 + 8 + 2 * c4);
            a[i][3] = *(const unsigned*)(Es + rr + 8 * ESTRB + k0 + 8 + 2 * c4);
        }
#pragma unroll
        for (int j = 0; j < 6; j++) {
            int col = n0 + 8 * j + g;
            unsigned b0 = *(const unsigned*)(Wt + col * WSTR + k0 + 2 * c4);
            unsigned b1 = *(const unsigned*)(Wt + col * WSTR + k0 + 8 + 2 * c4);
            MMA_BF16(acc[0][j], a[0], b0, b1);
            MMA_BF16(acc[1][j], a[1], b0, b1);
        }
    }

    float cs[6][2], cq[6][2];
#pragma unroll
    for (int j = 0; j < 6; j++) { cs[j][0] = cs[j][1] = 0.f; cq[j][0] = cq[j][1] = 0.f; }
#pragma unroll
    for (int i = 0; i < 2; i++) {
#pragma unroll
        for (int half = 0; half < 2; half++) {
            int rl = m0 + i * 16 + half * 8 + g;
            size_t sb = (size_t)s_src[rl] * DD;
            size_t db = (size_t)s_dst[rl] * DD;
            size_t ob = (size_t)(ebase + rl) * DD;
#pragma unroll
            for (int j = 0; j < 6; j++) {
                int col = n0 + 8 * j + 2 * c4;
                float2 dh = __bfloat1622float2(*(const __nv_bfloat162*)(g_D + sb + col));
                float2 eh = __bfloat1622float2(*(const __nv_bfloat162*)(g_E + db + col));
                float v0 = acc[i][j][half * 2 + 0] + bsh[col]     + dh.x + eh.x;
                float v1 = acc[i][j][half * 2 + 1] + bsh[col + 1] + dh.y + eh.y;
                *(__nv_bfloat162*)(g_enew + ob + col) =
                    __float22bfloat162_rn(make_float2(v0, v1));
                cs[j][0] += v0; cs[j][1] += v1;
                cq[j][0] += v0 * v0; cq[j][1] += v1 * v1;
            }
        }
    }
    if (do_stats) {
#pragma unroll
        for (int off = 16; off >= 4; off >>= 1) {
#pragma unroll
            for (int j = 0; j < 6; j++) {
#pragma unroll
                for (int p = 0; p < 2; p++) {
                    cs[j][p] += __shfl_down_sync(0xffffffffu, cs[j][p], off);
                    cq[j][p] += __shfl_down_sync(0xffffffffu, cq[j][p], off);
                }
            }
        }
        if (lane < 4) {
#pragma unroll
            for (int j = 0; j < 6; j++) {
#pragma unroll
                for (int p = 0; p < 2; p++) {
                    int col = n0 + 8 * j + 2 * lane + p;
                    atomicAdd(&s_sum[col], cs[j][p]);
                    atomicAdd(&s_sq[col], cq[j][p]);
                }
            }
        }
        __syncthreads();
        if (t < DD) {
            atomicAdd(&g_esum[t], (double)s_sum[t]);
            atomicAdd(&g_esq[t], (double)s_sq[t]);
        }
    }
}

// ------------------------- aggregation (CSR, bf16 enew + bf16 Bh) -------------
__global__ __launch_bounds__(256) void k_agg() {
    __shared__ float ssum[DD], ssq[DD];
    int t = threadIdx.x;
    if (t < DD) { ssum[t] = 0.f; ssq[t] = 0.f; }
    __syncthreads();
    int w = t >> 5, ln = t & 31;
    int v = blockIdx.x * 8 + w;      // grid = NN/8 exact
    float n0 = 0, n1 = 0, n2 = 0, d0 = 0, d1 = 0, d2 = 0;
    int p0 = g_ptr[v], p1 = g_ptr[v + 1];
    for (int p = p0; p < p1; p++) {
        int s = g_srcp[p];
        size_t eb = (size_t)p * DD;
        size_t sb = (size_t)s * DD;
        float x0 = __bfloat162float(g_enew[eb + ln]);
        float x1 = __bfloat162float(g_enew[eb + ln + 32]);
        float x2 = __bfloat162float(g_enew[eb + ln + 64]);
        float s0 = __fdividef(1.f, 1.f + __expf(-x0));
        float s1 = __fdividef(1.f, 1.f + __expf(-x1));
        float s2 = __fdividef(1.f, 1.f + __expf(-x2));
        n0 += s0 * __bfloat162float(g_B[sb + ln]);
        n1 += s1 * __bfloat162float(g_B[sb + ln + 32]);
        n2 += s2 * __bfloat162float(g_B[sb + ln + 64]);
        d0 += s0; d1 += s1; d2 += s2;
    }
    size_t vb = (size_t)v * DD;
    float h0 = g_A[vb + ln]      + __fdividef(n0, d0 + 1e-6f);
    float h1 = g_A[vb + ln + 32] + __fdividef(n1, d1 + 1e-6f);
    float h2 = g_A[vb + ln + 64] + __fdividef(n2, d2 + 1e-6f);
    g_hnew[vb + ln] = h0; g_hnew[vb + ln + 32] = h1; g_hnew[vb + ln + 64] = h2;
    atomicAdd(&ssum[ln], h0);      atomicAdd(&ssum[ln + 32], h1); atomicAdd(&ssum[ln + 64], h2);
    atomicAdd(&ssq[ln], h0 * h0);  atomicAdd(&ssq[ln + 32], h1 * h1); atomicAdd(&ssq[ln + 64], h2 * h2);
    __syncthreads();
    if (t < DD) {
        atomicAdd(&g_hsum[t], (double)ssum[t]);
        atomicAdd(&g_hsq[t], (double)ssq[t]);
    }
}

// ------------------------- BN finalize (e + h fused) --------------------------
__global__ void k_finalize2(const float* __restrict__ eg, const float* __restrict__ ebt,
                            const float* __restrict__ hg, const float* __restrict__ hbt,
                            int do_e) {
    int c = threadIdx.x;
    if (c >= DD) return;
    if (do_e) {
        double s = g_esum[c], q = g_esq[c];
        g_esum[c] = 0.0; g_esq[c] = 0.0;
        double m = s / (double)EE;
        double var = q / (double)EE - m * m;
        float sc = eg[c] * rsqrtf((float)var + 1e-5f);
        g_escale[c] = sc;
        g_eshift[c] = ebt[c] - (float)m * sc;
    }
    {
        double s = g_hsum[c], q = g_hsq[c];
        g_hsum[c] = 0.0; g_hsq[c] = 0.0;
        double m = s / (double)NN;
        double var = q / (double)NN - m * m;
        float sc = hg[c] * rsqrtf((float)var + 1e-5f);
        g_hscale[c] = sc;
        g_hshift[c] = hbt[c] - (float)m * sc;
    }
}

// ------------------------- head: relu(h@W1+b1)@W2+b2, tanh, scale -------------
__global__ __launch_bounds__(256) void k_head(const float* __restrict__ W1,
                                              const float* __restrict__ b1,
                                              const float* __restrict__ W2,
                                              const float* __restrict__ b2,
                                              const float* __restrict__ maxa,
                                              float* __restrict__ out) {
    extern __shared__ float dyn[];
    float* W1s = dyn;                 // 96*128
    float* Hs  = W1s + DD * HIDN;     // 32*96
    float* His = Hs + 32 * DD;        // 32*132 (padded)
    float* W2s = His + 32 * 132;      // 128*8
    int t = threadIdx.x;
    for (int i = t; i < DD * HIDN; i += 256) W1s[i] = W1[i];
    for (int i = t; i < HIDN * OUTN; i += 256) W2s[i] = W2[i];
    int row0 = blockIdx.x * 32;
    for (int i = t; i < 32 * 24; i += 256) {
        int r = i / 24, c4 = (i - (i / 24) * 24) * 4;
        int gr = row0 + r;
        float4 v = make_float4(0.f, 0.f, 0.f, 0.f);
        if (gr < NN) {
            size_t idx = (size_t)gr * DD + c4;
            v = *(const float4*)(g_h + idx);
            float4 en = *(const float4*)(g_hnew + idx);
            float4 sc = *(const float4*)(g_hscale + c4);
            float4 sh = *(const float4*)(g_hshift + c4);
            v.x += fmaxf(sc.x * en.x + sh.x, 0.f);
            v.y += fmaxf(sc.y * en.y + sh.y, 0.f);
            v.z += fmaxf(sc.z * en.z + sh.z, 0.f);
            v.w += fmaxf(sc.w * en.w + sh.w, 0.f);
        }
        *(float4*)(Hs + r * DD + c4) = v;
    }
    __syncthreads();
    {
        int ng = t >> 5, hg = t & 31;
        int r0 = ng * 4, c0 = hg * 4;
        ull acc[4][2];
        float4 bv = *(const float4*)(b1 + c0);
        ull b01 = pk2(bv.x, bv.y), b23 = pk2(bv.z, bv.w);
#pragma unroll
        for (int r = 0; r < 4; r++) { acc[r][0] = b01; acc[r][1] = b23; }
#pragma unroll 4
        for (int k = 0; k < DD; k++) {
            ulonglong2 wv = *(const ulonglong2*)(W1s + k * HIDN + c0);
#pragma unroll
            for (int r = 0; r < 4; r++) {
                float x = Hs[(r0 + r) * DD + k];
                ull xx = pk2(x, x);
                acc[r][0] = fma2(xx, wv.x, acc[r][0]);
                acc[r][1] = fma2(xx, wv.y, acc[r][1]);
            }
        }
#pragma unroll
        for (int r = 0; r < 4; r++) {
            float2 a = upk(acc[r][0]), q = upk(acc[r][1]);
            His[(r0 + r) * 132 + c0 + 0] = fmaxf(a.x, 0.f);
            His[(r0 + r) * 132 + c0 + 1] = fmaxf(a.y, 0.f);
            His[(r0 + r) * 132 + c0 + 2] = fmaxf(q.x, 0.f);
            His[(r0 + r) * 132 + c0 + 3] = fmaxf(q.y, 0.f);
        }
    }
    __syncthreads();
    {
        int node = t >> 3, oc = t & 7;
        int gn = row0 + node;
        if (gn < NN) {
            float acc = b2[oc];
#pragma unroll 8
            for (int k = 0; k < HIDN; k++) acc += His[node * 132 + k] * W2s[k * OUTN + oc];
            out[(size_t)gn * OUTN + oc] = maxa[gn] * tanhf(acc);
        }
    }
}

// ------------------------- launch ---------------------------------------------
extern "C" void kernel_launch(void* const* d_in, const int* in_sizes, int n_in,
                              void* d_out, int out_size) {
    const float* h1      = (const float*)d_in[0];
    const float* h2      = (const float*)d_in[1];
    const float* z       = (const float*)d_in[2];
    const float* efeat   = (const float*)d_in[3];
    const float* maxa    = (const float*)d_in[4];
    const float* Wh_emb  = (const float*)d_in[5];
    const float* bh_emb  = (const float*)d_in[6];
    const float* We_emb  = (const float*)d_in[7];
    const float* be_emb  = (const float*)d_in[8];
    const float* WA      = (const float*)d_in[9];
    const float* bA      = (const float*)d_in[10];
    const float* WB      = (const float*)d_in[11];
    const float* bB      = (const float*)d_in[12];
    const float* WC      = (const float*)d_in[13];
    const float* bC      = (const float*)d_in[14];
    const float* WD      = (const float*)d_in[15];
    const float* bD      = (const float*)d_in[16];
    const float* WE      = (const float*)d_in[17];
    const float* bE      = (const float*)d_in[18];
    const float* bn_h_g  = (const float*)d_in[19];
    const float* bn_h_b  = (const float*)d_in[20];
    const float* bn_e_g  = (const float*)d_in[21];
    const float* bn_e_b  = (const float*)d_in[22];
    const float* W1      = (const float*)d_in[23];
    const float* b1      = (const float*)d_in[24];
    const float* W2      = (const float*)d_in[25];
    const float* b2      = (const float*)d_in[26];
    const int*   src     = (const int*)d_in[27];
    const int*   dst     = (const int*)d_in[28];
    float* out = (float*)d_out;

    cudaFuncSetAttribute(k_matABDE, cudaFuncAttributeMaxDynamicSharedMemorySize, 190 * 1024);
    cudaFuncSetAttribute(k_edge,    cudaFuncAttributeMaxDynamicSharedMemorySize, 64 * 1024);
    cudaFuncSetAttribute(k_head,    cudaFuncAttributeMaxDynamicSharedMemorySize, 96 * 1024);

    const int smem_abde = (DD * WS4 + 64 * XSTR + 4 * DD) * 4;                  // 179712
    const int smem_edge = (DD * WSTR + 128 * ESTRB) * 2;                        // 46592
    const int smem_head = (DD * HIDN + 32 * DD + 32 * 132 + HIDN * OUTN) * 4;   // 82432

    k_zero<<<(NN + 255) / 256, 256>>>();
    k_embed_h<<<(NN * DD + 255) / 256, 256>>>(h1, h2, z, Wh_emb, bh_emb);

    k_count<<<EE / 256, 256>>>(dst);
    k_scan1<<<NBS, 256>>>();
    k_scan2<<<1, 256>>>();
    k_scan3<<<NBS, 256>>>();
    k_fill<<<EE / 256, 256>>>(dst);
    k_sortseg<<<(NN + 127) / 128, 128>>>();
    k_permidx<<<EE / 256, 256>>>(src, dst);

    const int ablk = (NN + 63) / 64;   // 782
    const int eblk = EE / 128;         // 6250

    for (int l = 0; l < 4; l++) {
        k_matABDE<<<ablk, 512, smem_abde>>>(WA + l * DD * DD, WB + l * DD * DD,
                                            WD + l * DD * DD, WE + l * DD * DD,
                                            bA + l * DD, bB + l * DD,
                                            bD + l * DD, bE + l * DD,
                                            l >= 1 ? 1 : 0);

        int embed = (l == 0) ? 1 : 0;
        int apply = (l >= 1) ? 1 : 0;
        int write_e = (l >= 1 && l < 3) ? 1 : 0;
        int do_stats = (l < 3) ? 1 : 0;
        k_edge<<<eblk, 256, smem_edge>>>(WC + l * DD * DD, bC + l * DD,
                                         efeat, We_emb, be_emb,
                                         embed, apply, write_e, do_stats);

        k_agg<<<NN / 8, 256>>>();
        k_finalize2<<<1, DD>>>(bn_e_g + l * DD, bn_e_b + l * DD,
                               bn_h_g + l * DD, bn_h_b + l * DD,
                               (l < 3) ? 1 : 0);
    }

    k_head<<<(NN + 31) / 32, 256, smem_head>>>(W1, b1, W2, b2, maxa, out);
}

// round 11
// speedup vs baseline: 2.3703x; 1.2358x over previous
#include <cuda_runtime.h>
#include <cuda_bf16.h>
#include <math.h>

#define NN 50000
#define EE 800000
#define DD 96
#define HIDN 128
#define OUTN 8
#define NBS 196    // scan blocks = ceil(NN/256)
#define WSTR 104   // bf16 smem stride (elements) for W^T  — conflict-free (edge)
#define ESTRB 104  // bf16 smem stride (elements) for E tile (edge)
#define XSTR 108   // f32/tf32 smem stride for X tile (matABDE)
#define WS4 392    // f32/tf32 smem stride for concat W (matABDE)

typedef unsigned long long ull;

// ------------------------- device scratch (no allocs allowed) ----------------
__device__ float g_h[(size_t)NN * DD];
__device__ float g_hnew[(size_t)NN * DD];
__device__ float g_A[(size_t)NN * DD];             // f32 (residual-critical)
__device__ __nv_bfloat16 g_B[(size_t)NN * DD];     // gathered tables in bf16
__device__ __nv_bfloat16 g_D[(size_t)NN * DD];
__device__ __nv_bfloat16 g_E[(size_t)NN * DD];
__device__ __nv_bfloat16 g_e[(size_t)EE * DD];     // permuted (CSR dst order)
__device__ __nv_bfloat16 g_enew[(size_t)EE * DD];  // permuted
__device__ __nv_bfloat16 g_WtC[4 * DD * DD];       // pre-transposed bf16 WC per layer
__device__ int   g_cnt[NN];
__device__ int   g_ptr[NN + 1];
__device__ int   g_woff[NN];
__device__ int   g_eid[EE];
__device__ int   g_srcp[EE];
__device__ int   g_dstp[EE];
__device__ int   g_bsum[256];
__device__ int   g_boff[256];
// layer-indexed stats (double-buffered by layer: no reset races)
__device__ double g_esum[4 * DD], g_esq[4 * DD], g_hsum[4 * DD], g_hsq[4 * DD];

// ------------------------- helpers -------------------------------------------
__device__ __forceinline__ ull pk2(float lo, float hi) {
    ull r; asm("mov.b64 %0,{%1,%2};" : "=l"(r) : "f"(lo), "f"(hi)); return r;
}
__device__ __forceinline__ ull fma2(ull a, ull b, ull c) {
    ull d; asm("fma.rn.f32x2 %0,%1,%2,%3;" : "=l"(d) : "l"(a), "l"(b), "l"(c)); return d;
}
__device__ __forceinline__ float2 upk(ull v) {
    float2 f; asm("mov.b64 {%0,%1},%2;" : "=f"(f.x), "=f"(f.y) : "l"(v)); return f;
}
__device__ __forceinline__ float tf32r(float x) {
    unsigned u; asm("cvt.rna.tf32.f32 %0,%1;" : "=r"(u) : "f"(x));
    return __uint_as_float(u);
}
#define MMA_TF32(d, a, b0_, b1_) \
    asm volatile("mma.sync.aligned.m16n8k8.row.col.f32.tf32.tf32.f32 " \
        "{%0,%1,%2,%3},{%4,%5,%6,%7},{%8,%9},{%0,%1,%2,%3};" \
        : "+f"(d[0]), "+f"(d[1]), "+f"(d[2]), "+f"(d[3]) \
        : "r"(a[0]), "r"(a[1]), "r"(a[2]), "r"(a[3]), "r"(b0_), "r"(b1_))
#define MMA_BF16(d, a, b0_, b1_) \
    asm volatile("mma.sync.aligned.m16n8k16.row.col.f32.bf16.bf16.f32 " \
        "{%0,%1,%2,%3},{%4,%5,%6,%7},{%8,%9},{%0,%1,%2,%3};" \
        : "+f"(d[0]), "+f"(d[1]), "+f"(d[2]), "+f"(d[3]) \
        : "r"(a[0]), "r"(a[1]), "r"(a[2]), "r"(a[3]), "r"(b0_), "r"(b1_))

__device__ __forceinline__ void bf8_to_f(const uint4& u, float* f) {
    const __nv_bfloat162* p = (const __nv_bfloat162*)&u;
#pragma unroll
    for (int j = 0; j < 4; j++) {
        float2 t = __bfloat1622float2(p[j]);
        f[2 * j] = t.x; f[2 * j + 1] = t.y;
    }
}
__device__ __forceinline__ uint4 f_to_bf8(const float* f) {
    uint4 u;
    __nv_bfloat162* p = (__nv_bfloat162*)&u;
#pragma unroll
    for (int j = 0; j < 4; j++)
        p[j] = __float22bfloat162_rn(make_float2(f[2 * j], f[2 * j + 1]));
    return u;
}
// in-block BN finalize: scale/shift from layer-indexed double stats
__device__ __forceinline__ void bn_scales(const double* sum, const double* sq,
                                          const float* gamma, const float* beta,
                                          double count, int c, float& sc, float& sh) {
    double s = sum[c], q = sq[c];
    double m = s / count;
    double var = q / count - m * m;
    sc = gamma[c] * rsqrtf((float)var + 1e-5f);
    sh = beta[c] - (float)m * sc;
}

// ------------------------- setup kernels -------------------------------------
__global__ void k_zero() {
    int i = blockIdx.x * blockDim.x + threadIdx.x;
    if (i < NN) g_cnt[i] = 0;
    if (i < 4 * DD) { g_esum[i] = 0.0; g_esq[i] = 0.0; g_hsum[i] = 0.0; g_hsq[i] = 0.0; }
}

__global__ void k_prepW(const float* __restrict__ WC) {
    int i = blockIdx.x * blockDim.x + threadIdx.x;   // 4*96*96
    if (i < 4 * DD * DD) {
        int l = i / (DD * DD), r = i - l * DD * DD;
        int k = r / DD, n = r - (r / DD) * DD;
        g_WtC[l * DD * DD + n * DD + k] = __float2bfloat16(WC[(size_t)l * DD * DD + k * DD + n]);
    }
}

__global__ void k_embed_h(const float* __restrict__ h1, const float* __restrict__ h2,
                          const float* __restrict__ z,
                          const float* __restrict__ W, const float* __restrict__ b) {
    __shared__ float Ws[26 * DD];
    int t = threadIdx.x;
    for (int i = t; i < 26 * DD; i += blockDim.x) Ws[i] = W[i];
    __syncthreads();
    int idx = blockIdx.x * blockDim.x + t;
    if (idx >= NN * DD) return;
    int r = idx / DD, c = idx - (idx / DD) * DD;
    float acc = b[c];
#pragma unroll
    for (int k = 0; k < 6; k++)  acc += h1[r * 6 + k]  * Ws[k * DD + c];
#pragma unroll
    for (int k = 0; k < 4; k++)  acc += h2[r * 4 + k]  * Ws[(6 + k) * DD + c];
#pragma unroll
    for (int k = 0; k < 16; k++) acc += z[r * 16 + k]  * Ws[(10 + k) * DD + c];
    g_h[idx] = acc;
}

// ------------------------- CSR build (deterministic, parallel scan) -----------
__global__ void k_count(const int* __restrict__ dst) {
    int i = blockIdx.x * blockDim.x + threadIdx.x;
    if (i < EE) atomicAdd(&g_cnt[dst[i]], 1);
}

__global__ void k_scan1() {
    __shared__ int sh[256];
    int t = threadIdx.x, b = blockIdx.x;
    int j = b * 256 + t;
    int v = (j < NN) ? g_cnt[j] : 0;
    sh[t] = v; __syncthreads();
    for (int off = 1; off < 256; off <<= 1) {
        int u = (t >= off) ? sh[t - off] : 0;
        __syncthreads();
        sh[t] += u;
        __syncthreads();
    }
    if (j < NN) g_ptr[j] = sh[t] - v;
    if (t == 255) g_bsum[b] = sh[t];
}

__global__ void k_scan2() {
    __shared__ int sh[256];
    int t = threadIdx.x;
    int v = (t < NBS) ? g_bsum[t] : 0;
    sh[t] = v; __syncthreads();
    for (int off = 1; off < 256; off <<= 1) {
        int u = (t >= off) ? sh[t - off] : 0;
        __syncthreads();
        sh[t] += u;
        __syncthreads();
    }
    g_boff[t] = sh[t] - v;
}

__global__ void k_scan3() {
    int j = blockIdx.x * blockDim.x + threadIdx.x;
    if (j < NN) {
        int p = g_ptr[j] + g_boff[j >> 8];
        g_ptr[j] = p; g_woff[j] = p;
    }
    if (j == 0) g_ptr[NN] = EE;
}

__global__ void k_fill(const int* __restrict__ dst) {
    int i = blockIdx.x * blockDim.x + threadIdx.x;
    if (i < EE) {
        int pos = atomicAdd(&g_woff[dst[i]], 1);
        g_eid[pos] = i;
    }
}

__global__ void k_sortseg() {
    int v = blockIdx.x * blockDim.x + threadIdx.x;
    if (v >= NN) return;
    int lo = g_ptr[v], hi = g_ptr[v + 1];
    for (int i = lo + 1; i < hi; i++) {
        int key = g_eid[i]; int j = i - 1;
        while (j >= lo && g_eid[j] > key) { g_eid[j + 1] = g_eid[j]; j--; }
        g_eid[j + 1] = key;
    }
}

__global__ void k_permidx(const int* __restrict__ src, const int* __restrict__ dst) {
    int p = blockIdx.x * blockDim.x + threadIdx.x;
    if (p < EE) {
        int ei = g_eid[p];
        g_srcp[p] = src[ei];
        g_dstp[p] = dst[ei];
    }
}

// ------------------------- fused node GEMM (tf32 MMA) -------------------------
// [A|B|D|E] = h @ Wcat + bcat.  512 threads, 16 warps (2m x 8n), warp = 32x48.
// In-block BN-h finalize from g_hsum[layer-1]; lazy h update on staging.
__global__ __launch_bounds__(512) void k_matABDE(const float* __restrict__ WA_,
                                                 const float* __restrict__ WB_,
                                                 const float* __restrict__ WD_,
                                                 const float* __restrict__ WE_,
                                                 const float* __restrict__ bA_,
                                                 const float* __restrict__ bB_,
                                                 const float* __restrict__ bD_,
                                                 const float* __restrict__ bE_,
                                                 const float* __restrict__ hg,
                                                 const float* __restrict__ hbt,
                                                 int layer, int apply) {
    extern __shared__ float dyn[];
    float* Ws = dyn;                     // [96 k][WS4] tf32, 4 matrices along cols
    float* Xs = dyn + DD * WS4;          // [64 rows][XSTR] tf32
    float* Bs = Xs + 64 * XSTR;          // [384] bias (f32)
    __shared__ float shsc[DD], shsh[DD];
    int t = threadIdx.x;
    int lane = t & 31, w = t >> 5;
    const float* wsrc[4] = {WA_, WB_, WD_, WE_};
    const float* bsrc[4] = {bA_, bB_, bD_, bE_};
    if (apply && t < DD)
        bn_scales(g_hsum + (layer - 1) * DD, g_hsq + (layer - 1) * DD,
                  hg, hbt, (double)NN, t, shsc[t], shsh[t]);
#pragma unroll
    for (int m = 0; m < 4; m++) {
        for (int i = t; i < DD * DD; i += 512) {
            int k = i / DD, c = i - (i / DD) * DD;
            Ws[k * WS4 + m * DD + c] = tf32r(wsrc[m][i]);
        }
    }
    for (int i = t; i < 4 * DD; i += 512) Bs[i] = bsrc[i / DD][i - (i / DD) * DD];
    __syncthreads();
    int row0 = blockIdx.x * 64;
    for (int i = t; i < 64 * 24; i += 512) {
        int r = i / 24, c4 = (i - (i / 24) * 24) * 4;
        int gr = row0 + r;
        float4 v = make_float4(0.f, 0.f, 0.f, 0.f);
        if (gr < NN) {
            size_t idx = (size_t)gr * DD + c4;
            v = *(const float4*)(g_h + idx);
            if (apply) {
                float4 en = *(const float4*)(g_hnew + idx);
                v.x += fmaxf(shsc[c4 + 0] * en.x + shsh[c4 + 0], 0.f);
                v.y += fmaxf(shsc[c4 + 1] * en.y + shsh[c4 + 1], 0.f);
                v.z += fmaxf(shsc[c4 + 2] * en.z + shsh[c4 + 2], 0.f);
                v.w += fmaxf(shsc[c4 + 3] * en.w + shsh[c4 + 3], 0.f);
                *(float4*)(g_h + idx) = v;
            }
        }
        v.x = tf32r(v.x); v.y = tf32r(v.y); v.z = tf32r(v.z); v.w = tf32r(v.w);
        *(float4*)(Xs + r * XSTR + c4) = v;
    }
    __syncthreads();

    int mg = w >> 3, ng = w & 7;          // 2 x 8 warp grid
    int m0 = mg * 32, n0 = ng * 48;
    int g = lane >> 2, c4 = lane & 3;
    float acc[2][6][4];
#pragma unroll
    for (int i = 0; i < 2; i++)
#pragma unroll
        for (int j = 0; j < 6; j++)
#pragma unroll
            for (int q = 0; q < 4; q++) acc[i][j][q] = 0.f;

#pragma unroll
    for (int k0 = 0; k0 < DD; k0 += 8) {
        unsigned a[2][4];
#pragma unroll
        for (int i = 0; i < 2; i++) {
            int rr = (m0 + i * 16 + g) * XSTR;
            a[i][0] = __float_as_uint(Xs[rr + k0 + c4]);
            a[i][1] = __float_as_uint(Xs[rr + 8 * XSTR + k0 + c4]);
            a[i][2] = __float_as_uint(Xs[rr + k0 + 4 + c4]);
            a[i][3] = __float_as_uint(Xs[rr + 8 * XSTR + k0 + 4 + c4]);
        }
#pragma unroll
        for (int j = 0; j < 6; j++) {
            int col = n0 + 8 * j + g;
            unsigned b0 = __float_as_uint(Ws[(k0 + c4) * WS4 + col]);
            unsigned b1 = __float_as_uint(Ws[(k0 + 4 + c4) * WS4 + col]);
            MMA_TF32(acc[0][j], a[0], b0, b1);
            MMA_TF32(acc[1][j], a[1], b0, b1);
        }
    }

    int m = n0 / DD;
    int ncc = n0 - m * DD;
    __nv_bfloat16* outb = (m == 1) ? g_B : (m == 2) ? g_D : g_E;
#pragma unroll
    for (int i = 0; i < 2; i++) {
#pragma unroll
        for (int half = 0; half < 2; half++) {
            int rl = m0 + i * 16 + half * 8 + g;
            int gr = row0 + rl;
            if (gr < NN) {
#pragma unroll
                for (int j = 0; j < 6; j++) {
                    int col = n0 + 8 * j + 2 * c4;
                    int cc = ncc + 8 * j + 2 * c4;
                    float v0 = acc[i][j][half * 2 + 0] + Bs[col];
                    float v1 = acc[i][j][half * 2 + 1] + Bs[col + 1];
                    if (m == 0) {
                        *(float2*)(g_A + (size_t)gr * DD + cc) = make_float2(v0, v1);
                    } else {
                        *(__nv_bfloat162*)(outb + (size_t)gr * DD + cc) =
                            __float22bfloat162_rn(make_float2(v0, v1));
                    }
                }
            }
        }
    }
}

// ------------------------- edge kernel: bf16 tensor-core GEMM -----------------
// W pre-transposed bf16 in gmem; in-block BN-e finalize from g_esum[layer-1].
__global__ __launch_bounds__(256) void k_edge(const __nv_bfloat16* __restrict__ Wtg,
                                              const float* __restrict__ b,
                                              const float* __restrict__ efeat,
                                              const float* __restrict__ Wemb,
                                              const float* __restrict__ bemb,
                                              const float* __restrict__ eg,
                                              const float* __restrict__ ebt,
                                              int layer, int embed, int apply,
                                              int write_e, int do_stats) {
    extern __shared__ char dync[];
    __nv_bfloat16* Wt = (__nv_bfloat16*)dync;        // [96 cols][WSTR k]
    __nv_bfloat16* Es = Wt + DD * WSTR;              // [128 rows][ESTRB k]
    __shared__ float s_sum[DD], s_sq[DD], bsh[DD];
    __shared__ float s_esc[DD], s_esh[DD];
    __shared__ int s_src[128], s_dst[128];
    __shared__ float s_ef[128 * 4];
    __shared__ float s_wemb[4 * DD];
    __shared__ float s_bemb[DD];
    int t = threadIdx.x;
    int lane = t & 31, w = t >> 5;
    if (t < DD) {
        s_sum[t] = 0.f; s_sq[t] = 0.f; bsh[t] = b[t];
        if (apply)
            bn_scales(g_esum + (layer - 1) * DD, g_esq + (layer - 1) * DD,
                      eg, ebt, (double)EE, t, s_esc[t], s_esh[t]);
    }
    // stage pre-converted W^T (pure copy)
    for (int i = t; i < DD * 12; i += 256) {
        int col = i / 12, kk = (i - (i / 12) * 12) * 8;
        *(uint4*)(Wt + col * WSTR + kk) = *(const uint4*)(Wtg + col * DD + kk);
    }
    int ebase = blockIdx.x * 128;   // EE % 128 == 0
    if (t < 128) { s_src[t] = g_srcp[ebase + t]; s_dst[t] = g_dstp[ebase + t]; }
    if (embed) {
        for (int i = t; i < 4 * DD; i += 256) s_wemb[i] = Wemb[i];
        if (t < DD) s_bemb[t] = bemb[t];
        if (t < 128) {
            int ei = g_eid[ebase + t];
            *(float4*)(s_ef + t * 4) = *(const float4*)(efeat + (size_t)ei * 4);
        }
    }
    __syncthreads();
    if (embed) {
        for (int i = t; i < 128 * 12; i += 256) {
            int r = i / 12, c8 = (i - (i / 12) * 12) * 8;
            size_t idx = (size_t)(ebase + r) * DD + c8;
            float4 f = *(const float4*)(s_ef + r * 4);
            float v[8];
#pragma unroll
            for (int j = 0; j < 8; j++) {
                int c = c8 + j;
                v[j] = s_bemb[c] + f.x * s_wemb[c] + f.y * s_wemb[DD + c]
                     + f.z * s_wemb[2 * DD + c] + f.w * s_wemb[3 * DD + c];
            }
            uint4 packed = f_to_bf8(v);
            *(uint4*)(g_e + idx) = packed;
            *(uint4*)(Es + r * ESTRB + c8) = packed;
        }
    } else {
        for (int i = t; i < 128 * 12; i += 256) {
            int r = i / 12, c8 = (i - (i / 12) * 12) * 8;
            size_t idx = (size_t)(ebase + r) * DD + c8;
            uint4 ue = *(const uint4*)(g_e + idx);
            if (apply) {
                float v[8], en[8];
                bf8_to_f(ue, v);
                uint4 un = *(const uint4*)(g_enew + idx);
                bf8_to_f(un, en);
#pragma unroll
                for (int j = 0; j < 8; j++)
                    v[j] += fmaxf(s_esc[c8 + j] * en[j] + s_esh[c8 + j], 0.f);
                uint4 packed = f_to_bf8(v);
                if (write_e) *(uint4*)(g_e + idx) = packed;
                *(uint4*)(Es + r * ESTRB + c8) = packed;
            } else {
                *(uint4*)(Es + r * ESTRB + c8) = ue;
            }
        }
    }
    __syncthreads();

    int mg = w >> 1, ng = w & 1;
    int m0 = mg * 32, n0 = ng * 48;
    int g = lane >> 2, c4 = lane & 3;
    float acc[2][6][4];
#pragma unroll
    for (int i = 0; i < 2; i++)
#pragma unroll
        for (int j = 0; j < 6; j++)
#pragma unroll
            for (int q = 0; q < 4; q++) acc[i][j][q] = 0.f;

#pragma unroll
    for (int k0 = 0; k0 < DD; k0 += 16) {
        unsigned a[2][4];
#pragma unroll
        for (int i = 0; i < 2; i++) {
            int rr = (m0 + i * 16 + g) * ESTRB;
            a[i][0] = *(const unsigned*)(Es + rr + k0 + 2 * c4);
            a[i][1] = *(const unsigned*)(Es + rr + 8 * ESTRB + k0 + 2 * c4);
            a[i][2] = *(const unsigned*)(Es + rr + k0 + 8 + 2 * c4);
            a[i][3] = *(const unsigned*)(Es + rr + 8 * ESTRB + k0 + 8 + 2 * c4);
        }
#pragma unroll
        for (int j = 0; j < 6; j++) {
            int col = n0 + 8 * j + g;
            unsigned b0 = *(const unsigned*)(Wt + col * WSTR + k0 + 2 * c4);
            unsigned b1 = *(const unsigned*)(Wt + col * WSTR + k0 + 8 + 2 * c4);
            MMA_BF16(acc[0][j], a[0], b0, b1);
            MMA_BF16(acc[1][j], a[1], b0, b1);
        }
    }

    float cs[6][2], cq[6][2];
#pragma unroll
    for (int j = 0; j < 6; j++) { cs[j][0] = cs[j][1] = 0.f; cq[j][0] = cq[j][1] = 0.f; }
#pragma unroll
    for (int i = 0; i < 2; i++) {
#pragma unroll
        for (int half = 0; half < 2; half++) {
            int rl = m0 + i * 16 + half * 8 + g;
            size_t sb = (size_t)s_src[rl] * DD;
            size_t db = (size_t)s_dst[rl] * DD;
            size_t ob = (size_t)(ebase + rl) * DD;
#pragma unroll
            for (int j = 0; j < 6; j++) {
                int col = n0 + 8 * j + 2 * c4;
                float2 dh = __bfloat1622float2(*(const __nv_bfloat162*)(g_D + sb + col));
                float2 eh = __bfloat1622float2(*(const __nv_bfloat162*)(g_E + db + col));
                float v0 = acc[i][j][half * 2 + 0] + bsh[col]     + dh.x + eh.x;
                float v1 = acc[i][j][half * 2 + 1] + bsh[col + 1] + dh.y + eh.y;
                *(__nv_bfloat162*)(g_enew + ob + col) =
                    __float22bfloat162_rn(make_float2(v0, v1));
                cs[j][0] += v0; cs[j][1] += v1;
                cq[j][0] += v0 * v0; cq[j][1] += v1 * v1;
            }
        }
    }
    if (do_stats) {
#pragma unroll
        for (int off = 16; off >= 4; off >>= 1) {
#pragma unroll
            for (int j = 0; j < 6; j++) {
#pragma unroll
                for (int p = 0; p < 2; p++) {
                    cs[j][p] += __shfl_down_sync(0xffffffffu, cs[j][p], off);
                    cq[j][p] += __shfl_down_sync(0xffffffffu, cq[j][p], off);
                }
            }
        }
        if (lane < 4) {
#pragma unroll
            for (int j = 0; j < 6; j++) {
#pragma unroll
                for (int p = 0; p < 2; p++) {
                    int col = n0 + 8 * j + 2 * lane + p;
                    atomicAdd(&s_sum[col], cs[j][p]);
                    atomicAdd(&s_sq[col], cq[j][p]);
                }
            }
        }
        __syncthreads();
        if (t < DD) {
            atomicAdd(&g_esum[layer * DD + t], (double)s_sum[t]);
            atomicAdd(&g_esq[layer * DD + t], (double)s_sq[t]);
        }
    }
}

// ------------------------- aggregation (CSR, unroll x2) -----------------------
__global__ __launch_bounds__(256) void k_agg(int layer) {
    __shared__ float ssum[DD], ssq[DD];
    int t = threadIdx.x;
    if (t < DD) { ssum[t] = 0.f; ssq[t] = 0.f; }
    __syncthreads();
    int w = t >> 5, ln = t & 31;
    int v = blockIdx.x * 8 + w;      // grid = NN/8 exact
    float n0 = 0, n1 = 0, n2 = 0, d0 = 0, d1 = 0, d2 = 0;
    int p0 = g_ptr[v], p1 = g_ptr[v + 1];
    int p = p0;
    for (; p + 1 < p1; p += 2) {
        int sa = g_srcp[p], sb_ = g_srcp[p + 1];
        size_t ea = (size_t)p * DD, eb = (size_t)(p + 1) * DD;
        size_t sba = (size_t)sa * DD, sbb = (size_t)sb_ * DD;
        float xa0 = __bfloat162float(g_enew[ea + ln]);
        float xa1 = __bfloat162float(g_enew[ea + ln + 32]);
        float xa2 = __bfloat162float(g_enew[ea + ln + 64]);
        float xb0 = __bfloat162float(g_enew[eb + ln]);
        float xb1 = __bfloat162float(g_enew[eb + ln + 32]);
        float xb2 = __bfloat162float(g_enew[eb + ln + 64]);
        float ba0 = __bfloat162float(g_B[sba + ln]);
        float ba1 = __bfloat162float(g_B[sba + ln + 32]);
        float ba2 = __bfloat162float(g_B[sba + ln + 64]);
        float bb0 = __bfloat162float(g_B[sbb + ln]);
        float bb1 = __bfloat162float(g_B[sbb + ln + 32]);
        float bb2 = __bfloat162float(g_B[sbb + ln + 64]);
        float sa0 = __fdividef(1.f, 1.f + __expf(-xa0));
        float sa1 = __fdividef(1.f, 1.f + __expf(-xa1));
        float sa2 = __fdividef(1.f, 1.f + __expf(-xa2));
        float sb0 = __fdividef(1.f, 1.f + __expf(-xb0));
        float sb1 = __fdividef(1.f, 1.f + __expf(-xb1));
        float sb2 = __fdividef(1.f, 1.f + __expf(-xb2));
        n0 += sa0 * ba0; n0 += sb0 * bb0;
        n1 += sa1 * ba1; n1 += sb1 * bb1;
        n2 += sa2 * ba2; n2 += sb2 * bb2;
        d0 += sa0; d0 += sb0;
        d1 += sa1; d1 += sb1;
        d2 += sa2; d2 += sb2;
    }
    if (p < p1) {
        int s = g_srcp[p];
        size_t eb = (size_t)p * DD;
        size_t sb = (size_t)s * DD;
        float x0 = __bfloat162float(g_enew[eb + ln]);
        float x1 = __bfloat162float(g_enew[eb + ln + 32]);
        float x2 = __bfloat162float(g_enew[eb + ln + 64]);
        float s0 = __fdividef(1.f, 1.f + __expf(-x0));
        float s1 = __fdividef(1.f, 1.f + __expf(-x1));
        float s2 = __fdividef(1.f, 1.f + __expf(-x2));
        n0 += s0 * __bfloat162float(g_B[sb + ln]);
        n1 += s1 * __bfloat162float(g_B[sb + ln + 32]);
        n2 += s2 * __bfloat162float(g_B[sb + ln + 64]);
        d0 += s0; d1 += s1; d2 += s2;
    }
    size_t vb = (size_t)v * DD;
    float h0 = g_A[vb + ln]      + __fdividef(n0, d0 + 1e-6f);
    float h1 = g_A[vb + ln + 32] + __fdividef(n1, d1 + 1e-6f);
    float h2 = g_A[vb + ln + 64] + __fdividef(n2, d2 + 1e-6f);
    g_hnew[vb + ln] = h0; g_hnew[vb + ln + 32] = h1; g_hnew[vb + ln + 64] = h2;
    atomicAdd(&ssum[ln], h0);      atomicAdd(&ssum[ln + 32], h1); atomicAdd(&ssum[ln + 64], h2);
    atomicAdd(&ssq[ln], h0 * h0);  atomicAdd(&ssq[ln + 32], h1 * h1); atomicAdd(&ssq[ln + 64], h2 * h2);
    __syncthreads();
    if (t < DD) {
        atomicAdd(&g_hsum[layer * DD + t], (double)ssum[t]);
        atomicAdd(&g_hsq[layer * DD + t], (double)ssq[t]);
    }
}

// ------------------------- head: relu(h@W1+b1)@W2+b2, tanh, scale -------------
// In-block BN-h finalize from g_hsum[3].
__global__ __launch_bounds__(256) void k_head(const float* __restrict__ W1,
                                              const float* __restrict__ b1,
                                              const float* __restrict__ W2,
                                              const float* __restrict__ b2,
                                              const float* __restrict__ maxa,
                                              const float* __restrict__ hg,
                                              const float* __restrict__ hbt,
                                              float* __restrict__ out) {
    extern __shared__ float dyn[];
    float* W1s = dyn;                 // 96*128
    float* Hs  = W1s + DD * HIDN;     // 32*96
    float* His = Hs + 32 * DD;        // 32*132 (padded)
    float* W2s = His + 32 * 132;      // 128*8
    __shared__ float hsc[DD], hsh[DD];
    int t = threadIdx.x;
    if (t < DD)
        bn_scales(g_hsum + 3 * DD, g_hsq + 3 * DD, hg, hbt, (double)NN, t, hsc[t], hsh[t]);
    for (int i = t; i < DD * HIDN; i += 256) W1s[i] = W1[i];
    for (int i = t; i < HIDN * OUTN; i += 256) W2s[i] = W2[i];
    __syncthreads();
    int row0 = blockIdx.x * 32;
    for (int i = t; i < 32 * 24; i += 256) {
        int r = i / 24, c4 = (i - (i / 24) * 24) * 4;
        int gr = row0 + r;
        float4 v = make_float4(0.f, 0.f, 0.f, 0.f);
        if (gr < NN) {
            size_t idx = (size_t)gr * DD + c4;
            v = *(const float4*)(g_h + idx);
            float4 en = *(const float4*)(g_hnew + idx);
            v.x += fmaxf(hsc[c4 + 0] * en.x + hsh[c4 + 0], 0.f);
            v.y += fmaxf(hsc[c4 + 1] * en.y + hsh[c4 + 1], 0.f);
            v.z += fmaxf(hsc[c4 + 2] * en.z + hsh[c4 + 2], 0.f);
            v.w += fmaxf(hsc[c4 + 3] * en.w + hsh[c4 + 3], 0.f);
        }
        *(float4*)(Hs + r * DD + c4) = v;
    }
    __syncthreads();
    {
        int ng = t >> 5, hgr = t & 31;
        int r0 = ng * 4, c0 = hgr * 4;
        ull acc[4][2];
        float4 bv = *(const float4*)(b1 + c0);
        ull b01 = pk2(bv.x, bv.y), b23 = pk2(bv.z, bv.w);
#pragma unroll
        for (int r = 0; r < 4; r++) { acc[r][0] = b01; acc[r][1] = b23; }
#pragma unroll 4
        for (int k = 0; k < DD; k++) {
            ulonglong2 wv = *(const ulonglong2*)(W1s + k * HIDN + c0);
#pragma unroll
            for (int r = 0; r < 4; r++) {
                float x = Hs[(r0 + r) * DD + k];
                ull xx = pk2(x, x);
                acc[r][0] = fma2(xx, wv.x, acc[r][0]);
                acc[r][1] = fma2(xx, wv.y, acc[r][1]);
            }
        }
#pragma unroll
        for (int r = 0; r < 4; r++) {
            float2 a = upk(acc[r][0]), q = upk(acc[r][1]);
            His[(r0 + r) * 132 + c0 + 0] = fmaxf(a.x, 0.f);
            His[(r0 + r) * 132 + c0 + 1] = fmaxf(a.y, 0.f);
            His[(r0 + r) * 132 + c0 + 2] = fmaxf(q.x, 0.f);
            His[(r0 + r) * 132 + c0 + 3] = fmaxf(q.y, 0.f);
        }
    }
    __syncthreads();
    {
        int node = t >> 3, oc = t & 7;
        int gn = row0 + node;
        if (gn < NN) {
            float acc = b2[oc];
#pragma unroll 8
            for (int k = 0; k < HIDN; k++) acc += His[node * 132 + k] * W2s[k * OUTN + oc];
            out[(size_t)gn * OUTN + oc] = maxa[gn] * tanhf(acc);
        }
    }
}

// ------------------------- launch ---------------------------------------------
extern "C" void kernel_launch(void* const* d_in, const int* in_sizes, int n_in,
                              void* d_out, int out_size) {
    const float* h1      = (const float*)d_in[0];
    const float* h2      = (const float*)d_in[1];
    const float* z       = (const float*)d_in[2];
    const float* efeat   = (const float*)d_in[3];
    const float* maxa    = (const float*)d_in[4];
    const float* Wh_emb  = (const float*)d_in[5];
    const float* bh_emb  = (const float*)d_in[6];
    const float* We_emb  = (const float*)d_in[7];
    const float* be_emb  = (const float*)d_in[8];
    const float* WA      = (const float*)d_in[9];
    const float* bA      = (const float*)d_in[10];
    const float* WB      = (const float*)d_in[11];
    const float* bB      = (const float*)d_in[12];
    const float* WC      = (const float*)d_in[13];
    const float* bC      = (const float*)d_in[14];
    const float* WD      = (const float*)d_in[15];
    const float* bD      = (const float*)d_in[16];
    const float* WE      = (const float*)d_in[17];
    const float* bE      = (const float*)d_in[18];
    const float* bn_h_g  = (const float*)d_in[19];
    const float* bn_h_b  = (const float*)d_in[20];
    const float* bn_e_g  = (const float*)d_in[21];
    const float* bn_e_b  = (const float*)d_in[22];
    const float* W1      = (const float*)d_in[23];
    const float* b1      = (const float*)d_in[24];
    const float* W2      = (const float*)d_in[25];
    const float* b2      = (const float*)d_in[26];
    const int*   src     = (const int*)d_in[27];
    const int*   dst     = (const int*)d_in[28];
    float* out = (float*)d_out;

    __nv_bfloat16* WtC_base;
    cudaGetSymbolAddress((void**)&WtC_base, g_WtC);

    cudaFuncSetAttribute(k_matABDE, cudaFuncAttributeMaxDynamicSharedMemorySize, 190 * 1024);
    cudaFuncSetAttribute(k_edge,    cudaFuncAttributeMaxDynamicSharedMemorySize, 64 * 1024);
    cudaFuncSetAttribute(k_head,    cudaFuncAttributeMaxDynamicSharedMemorySize, 96 * 1024);

    const int smem_abde = (DD * WS4 + 64 * XSTR + 4 * DD) * 4;                  // 179712
    const int smem_edge = (DD * WSTR + 128 * ESTRB) * 2;                        // 46592
    const int smem_head = (DD * HIDN + 32 * DD + 32 * 132 + HIDN * OUTN) * 4;   // 82432

    k_zero<<<(NN + 255) / 256, 256>>>();
    k_prepW<<<(4 * DD * DD + 255) / 256, 256>>>(WC);
    k_embed_h<<<(NN * DD + 255) / 256, 256>>>(h1, h2, z, Wh_emb, bh_emb);

    k_count<<<EE / 256, 256>>>(dst);
    k_scan1<<<NBS, 256>>>();
    k_scan2<<<1, 256>>>();
    k_scan3<<<NBS, 256>>>();
    k_fill<<<EE / 256, 256>>>(dst);
    k_sortseg<<<(NN + 127) / 128, 128>>>();
    k_permidx<<<EE / 256, 256>>>(src, dst);

    const int ablk = (NN + 63) / 64;   // 782
    const int eblk = EE / 128;         // 6250

    for (int l = 0; l < 4; l++) {
        int lp = (l > 0) ? l - 1 : 0;
        k_matABDE<<<ablk, 512, smem_abde>>>(WA + l * DD * DD, WB + l * DD * DD,
                                            WD + l * DD * DD, WE + l * DD * DD,
                                            bA + l * DD, bB + l * DD,
                                            bD + l * DD, bE + l * DD,
                                            bn_h_g + lp * DD, bn_h_b + lp * DD,
                                            l, l >= 1 ? 1 : 0);

        int embed = (l == 0) ? 1 : 0;
        int apply = (l >= 1) ? 1 : 0;
        int write_e = (l >= 1 && l < 3) ? 1 : 0;
        int do_stats = (l < 3) ? 1 : 0;
        k_edge<<<eblk, 256, smem_edge>>>(WtC_base + l * DD * DD, bC + l * DD,
                                         efeat, We_emb, be_emb,
                                         bn_e_g + lp * DD, bn_e_b + lp * DD,
                                         l, embed, apply, write_e, do_stats);

        k_agg<<<NN / 8, 256>>>(l);
    }

    k_head<<<(NN + 31) / 32, 256, smem_head>>>(W1, b1, W2, b2, maxa,
                                               bn_h_g + 3 * DD, bn_h_b + 3 * DD, out);
}

// round 12
// speedup vs baseline: 2.3730x; 1.0011x over previous
#include <cuda_runtime.h>
#include <cuda_bf16.h>
#include <math.h>

#define NN 50000
#define EE 800000
#define DD 96
#define HIDN 128
#define OUTN 8
#define NBS 196    // scan blocks = ceil(NN/256)
#define WSTR 104   // bf16 smem stride (elements) for W^T  — conflict-free (edge)
#define ESTRB 104  // bf16 smem stride (elements) for E tile (edge)
#define XSTR 108   // f32/tf32 smem stride for X tile (mat kernels)
#define WS2 200    // f32/tf32 smem stride for 2-matrix concat W (mat kernels)
#define EMB_BLKS 18750  // (NN*DD+255)/256

typedef unsigned long long ull;

// ------------------------- device scratch (no allocs allowed) ----------------
__device__ float g_h[(size_t)NN * DD];
__device__ float g_hnew[(size_t)NN * DD];
__device__ float g_A[(size_t)NN * DD];             // f32 (residual-critical)
__device__ __nv_bfloat16 g_B[(size_t)NN * DD];     // gathered tables in bf16
__device__ __nv_bfloat16 g_D[(size_t)NN * DD];
__device__ __nv_bfloat16 g_E[(size_t)NN * DD];
__device__ __nv_bfloat16 g_e[(size_t)EE * DD];     // permuted (CSR dst order)
__device__ __nv_bfloat16 g_enew[(size_t)EE * DD];  // permuted
__device__ __nv_bfloat16 g_WtC[4 * DD * DD];       // pre-transposed bf16 WC per layer
__device__ float g_WDE[4 * DD * 192];              // tf32-prerounded [WD|WE] per layer
__device__ float g_WAB[4 * DD * 192];              // tf32-prerounded [WA|WB] per layer
__device__ int   g_cnt[NN];
__device__ int   g_ptr[NN + 1];
__device__ int   g_woff[NN];
__device__ int   g_eid[EE];
__device__ int   g_srcp[EE];
__device__ int   g_dstp[EE];
__device__ int   g_bsum[256];
__device__ int   g_boff[256];
// layer-indexed stats (no reset races)
__device__ double g_esum[4 * DD], g_esq[4 * DD], g_hsum[4 * DD], g_hsq[4 * DD];

// ------------------------- helpers -------------------------------------------
__device__ __forceinline__ ull pk2(float lo, float hi) {
    ull r; asm("mov.b64 %0,{%1,%2};" : "=l"(r) : "f"(lo), "f"(hi)); return r;
}
__device__ __forceinline__ ull fma2(ull a, ull b, ull c) {
    ull d; asm("fma.rn.f32x2 %0,%1,%2,%3;" : "=l"(d) : "l"(a), "l"(b), "l"(c)); return d;
}
__device__ __forceinline__ float2 upk(ull v) {
    float2 f; asm("mov.b64 {%0,%1},%2;" : "=f"(f.x), "=f"(f.y) : "l"(v)); return f;
}
__device__ __forceinline__ float tf32r(float x) {
    unsigned u; asm("cvt.rna.tf32.f32 %0,%1;" : "=r"(u) : "f"(x));
    return __uint_as_float(u);
}
#define MMA_TF32(d, a, b0_, b1_) \
    asm volatile("mma.sync.aligned.m16n8k8.row.col.f32.tf32.tf32.f32 " \
        "{%0,%1,%2,%3},{%4,%5,%6,%7},{%8,%9},{%0,%1,%2,%3};" \
        : "+f"(d[0]), "+f"(d[1]), "+f"(d[2]), "+f"(d[3]) \
        : "r"(a[0]), "r"(a[1]), "r"(a[2]), "r"(a[3]), "r"(b0_), "r"(b1_))
#define MMA_BF16(d, a, b0_, b1_) \
    asm volatile("mma.sync.aligned.m16n8k16.row.col.f32.bf16.bf16.f32 " \
        "{%0,%1,%2,%3},{%4,%5,%6,%7},{%8,%9},{%0,%1,%2,%3};" \
        : "+f"(d[0]), "+f"(d[1]), "+f"(d[2]), "+f"(d[3]) \
        : "r"(a[0]), "r"(a[1]), "r"(a[2]), "r"(a[3]), "r"(b0_), "r"(b1_))

__device__ __forceinline__ void bf8_to_f(const uint4& u, float* f) {
    const __nv_bfloat162* p = (const __nv_bfloat162*)&u;
#pragma unroll
    for (int j = 0; j < 4; j++) {
        float2 t = __bfloat1622float2(p[j]);
        f[2 * j] = t.x; f[2 * j + 1] = t.y;
    }
}
__device__ __forceinline__ uint4 f_to_bf8(const float* f) {
    uint4 u;
    __nv_bfloat162* p = (__nv_bfloat162*)&u;
#pragma unroll
    for (int j = 0; j < 4; j++)
        p[j] = __float22bfloat162_rn(make_float2(f[2 * j], f[2 * j + 1]));
    return u;
}
__device__ __forceinline__ void bn_scales(const double* sum, const double* sq,
                                          const float* gamma, const float* beta,
                                          double count, int c, float& sc, float& sh) {
    double s = sum[c], q = sq[c];
    double m = s / count;
    double var = q / count - m * m;
    sc = gamma[c] * rsqrtf((float)var + 1e-5f);
    sh = beta[c] - (float)m * sc;
}

// ------------------------- setup ----------------------------------------------
__global__ void k_zero() {
    int i = blockIdx.x * blockDim.x + threadIdx.x;
    if (i < NN) g_cnt[i] = 0;
    if (i < 4 * DD) { g_esum[i] = 0.0; g_esq[i] = 0.0; g_hsum[i] = 0.0; g_hsq[i] = 0.0; }
}

// embed_h (blocks < EMB_BLKS) + weight prep (rest): tf32-preround ABDE, bf16 WtC
__global__ void k_prep(const float* __restrict__ h1, const float* __restrict__ h2,
                       const float* __restrict__ z,
                       const float* __restrict__ Wh, const float* __restrict__ bh,
                       const float* __restrict__ WA, const float* __restrict__ WB,
                       const float* __restrict__ WC, const float* __restrict__ WD,
                       const float* __restrict__ WE) {
    int t = threadIdx.x;
    if (blockIdx.x < EMB_BLKS) {
        __shared__ float Ws[26 * DD];
        for (int i = t; i < 26 * DD; i += 256) Ws[i] = Wh[i];
        __syncthreads();
        int idx = blockIdx.x * 256 + t;
        if (idx >= NN * DD) return;
        int r = idx / DD, c = idx - (idx / DD) * DD;
        float acc = bh[c];
#pragma unroll
        for (int k = 0; k < 6; k++)  acc += h1[r * 6 + k]  * Ws[k * DD + c];
#pragma unroll
        for (int k = 0; k < 4; k++)  acc += h2[r * 4 + k]  * Ws[(6 + k) * DD + c];
#pragma unroll
        for (int k = 0; k < 16; k++) acc += z[r * 16 + k]  * Ws[(10 + k) * DD + c];
        g_h[idx] = acc;
        return;
    }
    int j = (blockIdx.x - EMB_BLKS) * 256 + t;
    if (j < 73728) {                         // WDE concat, tf32 bits
        int l = j / 18432, r = j - l * 18432;
        int k = r / 192, c = r - k * 192;
        int m = c / DD, cc = c - m * DD;
        const float* src = m ? WE : WD;
        g_WDE[j] = tf32r(src[(size_t)l * DD * DD + k * DD + cc]);
    } else if (j < 147456) {                 // WAB concat
        int i = j - 73728;
        int l = i / 18432, r = i - l * 18432;
        int k = r / 192, c = r - k * 192;
        int m = c / DD, cc = c - m * DD;
        const float* src = m ? WB : WA;
        g_WAB[i] = tf32r(src[(size_t)l * DD * DD + k * DD + cc]);
    } else if (j < 184320) {                 // WtC transposed bf16
        int i = j - 147456;
        int l = i / 9216, r = i - l * 9216;
        int k = r / DD, n = r - k * DD;
        g_WtC[l * DD * DD + n * DD + k] = __float2bfloat16(WC[(size_t)l * DD * DD + k * DD + n]);
    }
}

// ------------------------- CSR build ------------------------------------------
__global__ void k_count(const int* __restrict__ dst) {
    int i = blockIdx.x * blockDim.x + threadIdx.x;
    if (i < EE) atomicAdd(&g_cnt[dst[i]], 1);
}

__global__ void k_scan1() {
    __shared__ int sh[256];
    int t = threadIdx.x, b = blockIdx.x;
    int j = b * 256 + t;
    int v = (j < NN) ? g_cnt[j] : 0;
    sh[t] = v; __syncthreads();
    for (int off = 1; off < 256; off <<= 1) {
        int u = (t >= off) ? sh[t - off] : 0;
        __syncthreads();
        sh[t] += u;
        __syncthreads();
    }
    if (j < NN) g_ptr[j] = sh[t] - v;
    if (t == 255) g_bsum[b] = sh[t];
}

__global__ void k_scan2() {
    __shared__ int sh[256];
    int t = threadIdx.x;
    int v = (t < NBS) ? g_bsum[t] : 0;
    sh[t] = v; __syncthreads();
    for (int off = 1; off < 256; off <<= 1) {
        int u = (t >= off) ? sh[t - off] : 0;
        __syncthreads();
        sh[t] += u;
        __syncthreads();
    }
    g_boff[t] = sh[t] - v;
}

__global__ void k_scan3() {
    int j = blockIdx.x * blockDim.x + threadIdx.x;
    if (j < NN) {
        int p = g_ptr[j] + g_boff[j >> 8];
        g_ptr[j] = p; g_woff[j] = p;
    }
    if (j == 0) g_ptr[NN] = EE;
}

__global__ void k_fill(const int* __restrict__ dst) {
    int i = blockIdx.x * blockDim.x + threadIdx.x;
    if (i < EE) {
        int pos = atomicAdd(&g_woff[dst[i]], 1);
        g_eid[pos] = i;
    }
}

// sort each node's segment + emit permuted src/dst (merged)
__global__ void k_sortperm(const int* __restrict__ src, const int* __restrict__ dst) {
    int v = blockIdx.x * blockDim.x + threadIdx.x;
    if (v >= NN) return;
    int lo = g_ptr[v], hi = g_ptr[v + 1];
    for (int i = lo + 1; i < hi; i++) {
        int key = g_eid[i]; int j = i - 1;
        while (j >= lo && g_eid[j] > key) { g_eid[j + 1] = g_eid[j]; j--; }
        g_eid[j + 1] = key;
    }
    for (int i = lo; i < hi; i++) {
        int ei = g_eid[i];
        g_srcp[i] = src[ei];
        g_dstp[i] = dst[ei];
    }
}

// ------------------------- node GEMM (tf32 MMA), 2-matrix variant -------------
// out = h @ [W0|W1] + [b0|b1].  256 threads, 8 warps (2m x 4n), warp = 32x48.
// isAB=0: outputs D,E (bf16) and applies lazy h update (writes g_h).
// isAB=1: outputs A (f32), B (bf16); no apply (h already updated by matDE).
__global__ __launch_bounds__(256) void k_mat2(const float* __restrict__ Wcat,
                                              const float* __restrict__ b0_,
                                              const float* __restrict__ b1_,
                                              const float* __restrict__ hg,
                                              const float* __restrict__ hbt,
                                              int layer, int apply, int isAB) {
    extern __shared__ float dyn[];
    float* Ws = dyn;                     // [96 k][WS2] tf32 bits (pre-rounded)
    float* Xs = dyn + DD * WS2;          // [64 rows][XSTR] tf32
    float* Bs = Xs + 64 * XSTR;          // [192]
    __shared__ float shsc[DD], shsh[DD];
    int t = threadIdx.x;
    int lane = t & 31, w = t >> 5;
    if (apply && t < DD)
        bn_scales(g_hsum + (layer - 1) * DD, g_hsq + (layer - 1) * DD,
                  hg, hbt, (double)NN, t, shsc[t], shsh[t]);
    for (int i = t; i < DD * 48; i += 256) {
        int k = i / 48, c4 = (i - (i / 48) * 48) * 4;
        *(float4*)(Ws + k * WS2 + c4) = *(const float4*)(Wcat + k * 192 + c4);
    }
    for (int i = t; i < 192; i += 256) Bs[i] = (i < DD) ? b0_[i] : b1_[i - DD];
    __syncthreads();
    int row0 = blockIdx.x * 64;
    for (int i = t; i < 64 * 24; i += 256) {
        int r = i / 24, c4 = (i - (i / 24) * 24) * 4;
        int gr = row0 + r;
        float4 v = make_float4(0.f, 0.f, 0.f, 0.f);
        if (gr < NN) {
            size_t idx = (size_t)gr * DD + c4;
            v = *(const float4*)(g_h + idx);
            if (apply) {
                float4 en = *(const float4*)(g_hnew + idx);
                v.x += fmaxf(shsc[c4 + 0] * en.x + shsh[c4 + 0], 0.f);
                v.y += fmaxf(shsc[c4 + 1] * en.y + shsh[c4 + 1], 0.f);
                v.z += fmaxf(shsc[c4 + 2] * en.z + shsh[c4 + 2], 0.f);
                v.w += fmaxf(shsc[c4 + 3] * en.w + shsh[c4 + 3], 0.f);
                *(float4*)(g_h + idx) = v;
            }
        }
        v.x = tf32r(v.x); v.y = tf32r(v.y); v.z = tf32r(v.z); v.w = tf32r(v.w);
        *(float4*)(Xs + r * XSTR + c4) = v;
    }
    __syncthreads();

    int mg = w >> 2, ng = w & 3;          // 2 x 4 warp grid, 192 cols
    int m0 = mg * 32, n0 = ng * 48;
    int g = lane >> 2, c4 = lane & 3;
    float acc[2][6][4];
#pragma unroll
    for (int i = 0; i < 2; i++)
#pragma unroll
        for (int j = 0; j < 6; j++)
#pragma unroll
            for (int q = 0; q < 4; q++) acc[i][j][q] = 0.f;

#pragma unroll
    for (int k0 = 0; k0 < DD; k0 += 8) {
        unsigned a[2][4];
#pragma unroll
        for (int i = 0; i < 2; i++) {
            int rr = (m0 + i * 16 + g) * XSTR;
            a[i][0] = __float_as_uint(Xs[rr + k0 + c4]);
            a[i][1] = __float_as_uint(Xs[rr + 8 * XSTR + k0 + c4]);
            a[i][2] = __float_as_uint(Xs[rr + k0 + 4 + c4]);
            a[i][3] = __float_as_uint(Xs[rr + 8 * XSTR + k0 + 4 + c4]);
        }
#pragma unroll
        for (int j = 0; j < 6; j++) {
            int col = n0 + 8 * j + g;
            unsigned b0 = __float_as_uint(Ws[(k0 + c4) * WS2 + col]);
            unsigned b1 = __float_as_uint(Ws[(k0 + 4 + c4) * WS2 + col]);
            MMA_TF32(acc[0][j], a[0], b0, b1);
            MMA_TF32(acc[1][j], a[1], b0, b1);
        }
    }

    int m = n0 / DD;                      // 0 or 1 (which matrix)
    int ncc = n0 - m * DD;
    __nv_bfloat16* outb = isAB ? g_B : (m == 0 ? g_D : g_E);
    int is_f32 = (isAB && m == 0);
#pragma unroll
    for (int i = 0; i < 2; i++) {
#pragma unroll
        for (int half = 0; half < 2; half++) {
            int rl = m0 + i * 16 + half * 8 + g;
            int gr = row0 + rl;
            if (gr < NN) {
#pragma unroll
                for (int j = 0; j < 6; j++) {
                    int col = n0 + 8 * j + 2 * c4;
                    int cc = ncc + 8 * j + 2 * c4;
                    float v0 = acc[i][j][half * 2 + 0] + Bs[col];
                    float v1 = acc[i][j][half * 2 + 1] + Bs[col + 1];
                    if (is_f32) {
                        *(float2*)(g_A + (size_t)gr * DD + cc) = make_float2(v0, v1);
                    } else {
                        *(__nv_bfloat162*)(outb + (size_t)gr * DD + cc) =
                            __float22bfloat162_rn(make_float2(v0, v1));
                    }
                }
            }
        }
    }
}

// ------------------------- edge kernel: bf16 tensor-core GEMM -----------------
__global__ __launch_bounds__(256) void k_edge(const __nv_bfloat16* __restrict__ Wtg,
                                              const float* __restrict__ b,
                                              const float* __restrict__ efeat,
                                              const float* __restrict__ Wemb,
                                              const float* __restrict__ bemb,
                                              const float* __restrict__ eg,
                                              const float* __restrict__ ebt,
                                              int layer, int embed, int apply,
                                              int write_e, int do_stats) {
    extern __shared__ char dync[];
    __nv_bfloat16* Wt = (__nv_bfloat16*)dync;        // [96 cols][WSTR k]
    __nv_bfloat16* Es = Wt + DD * WSTR;              // [128 rows][ESTRB k]
    __shared__ float s_sum[DD], s_sq[DD], bsh[DD];
    __shared__ float s_esc[DD], s_esh[DD];
    __shared__ int s_src[128], s_dst[128];
    __shared__ float s_ef[128 * 4];
    __shared__ float s_wemb[4 * DD];
    __shared__ float s_bemb[DD];
    int t = threadIdx.x;
    int lane = t & 31, w = t >> 5;
    if (t < DD) {
        s_sum[t] = 0.f; s_sq[t] = 0.f; bsh[t] = b[t];
        if (apply)
            bn_scales(g_esum + (layer - 1) * DD, g_esq + (layer - 1) * DD,
                      eg, ebt, (double)EE, t, s_esc[t], s_esh[t]);
    }
    for (int i = t; i < DD * 12; i += 256) {
        int col = i / 12, kk = (i - (i / 12) * 12) * 8;
        *(uint4*)(Wt + col * WSTR + kk) = *(const uint4*)(Wtg + col * DD + kk);
    }
    int ebase = blockIdx.x * 128;   // EE % 128 == 0
    if (t < 128) { s_src[t] = g_srcp[ebase + t]; s_dst[t] = g_dstp[ebase + t]; }
    if (embed) {
        for (int i = t; i < 4 * DD; i += 256) s_wemb[i] = Wemb[i];
        if (t < DD) s_bemb[t] = bemb[t];
        if (t < 128) {
            int ei = g_eid[ebase + t];
            *(float4*)(s_ef + t * 4) = *(const float4*)(efeat + (size_t)ei * 4);
        }
    }
    __syncthreads();
    if (embed) {
        for (int i = t; i < 128 * 12; i += 256) {
            int r = i / 12, c8 = (i - (i / 12) * 12) * 8;
            size_t idx = (size_t)(ebase + r) * DD + c8;
            float4 f = *(const float4*)(s_ef + r * 4);
            float v[8];
#pragma unroll
            for (int j = 0; j < 8; j++) {
                int c = c8 + j;
                v[j] = s_bemb[c] + f.x * s_wemb[c] + f.y * s_wemb[DD + c]
                     + f.z * s_wemb[2 * DD + c] + f.w * s_wemb[3 * DD + c];
            }
            uint4 packed = f_to_bf8(v);
            *(uint4*)(g_e + idx) = packed;
            *(uint4*)(Es + r * ESTRB + c8) = packed;
        }
    } else {
        for (int i = t; i < 128 * 12; i += 256) {
            int r = i / 12, c8 = (i - (i / 12) * 12) * 8;
            size_t idx = (size_t)(ebase + r) * DD + c8;
            uint4 ue = *(const uint4*)(g_e + idx);
            if (apply) {
                float v[8], en[8];
                bf8_to_f(ue, v);
                uint4 un = *(const uint4*)(g_enew + idx);
                bf8_to_f(un, en);
#pragma unroll
                for (int j = 0; j < 8; j++)
                    v[j] += fmaxf(s_esc[c8 + j] * en[j] + s_esh[c8 + j], 0.f);
                uint4 packed = f_to_bf8(v);
                if (write_e) *(uint4*)(g_e + idx) = packed;
                *(uint4*)(Es + r * ESTRB + c8) = packed;
            } else {
                *(uint4*)(Es + r * ESTRB + c8) = ue;
            }
        }
    }
    __syncthreads();

    int mg = w >> 1, ng = w & 1;
    int m0 = mg * 32, n0 = ng * 48;
    int g = lane >> 2, c4 = lane & 3;
    float acc[2][6][4];
#pragma unroll
    for (int i = 0; i < 2; i++)
#pragma unroll
        for (int j = 0; j < 6; j++)
#pragma unroll
            for (int q = 0; q < 4; q++) acc[i][j][q] = 0.f;

#pragma unroll
    for (int k0 = 0; k0 < DD; k0 += 16) {
        unsigned a[2][4];
#pragma unroll
        for (int i = 0; i < 2; i++) {
            int rr = (m0 + i * 16 + g) * ESTRB;
            a[i][0] = *(const unsigned*)(Es + rr + k0 + 2 * c4);
            a[i][1] = *(const unsigned*)(Es + rr + 8 * ESTRB + k0 + 2 * c4);
            a[i][2] = *(const unsigned*)(Es + rr + k0 + 8 + 2 * c4);
            a[i][3] = *(const unsigned*)(Es + rr + 8 * ESTRB + k0 + 8 + 2 * c4);
        }
#pragma unroll
        for (int j = 0; j < 6; j++) {
            int col = n0 + 8 * j + g;
            unsigned b0 = *(const unsigned*)(Wt + col * WSTR + k0 + 2 * c4);
            unsigned b1 = *(const unsigned*)(Wt + col * WSTR + k0 + 8 + 2 * c4);
            MMA_BF16(acc[0][j], a[0], b0, b1);
            MMA_BF16(acc[1][j], a[1], b0, b1);
        }
    }

    float cs[6][2], cq[6][2];
#pragma unroll
    for (int j = 0; j < 6; j++) { cs[j][0] = cs[j][1] = 0.f; cq[j][0] = cq[j][1] = 0.f; }
#pragma unroll
    for (int i = 0; i < 2; i++) {
#pragma unroll
        for (int half = 0; half < 2; half++) {
            int rl = m0 + i * 16 + half * 8 + g;
            size_t sb = (size_t)s_src[rl] * DD;
            size_t db = (size_t)s_dst[rl] * DD;
            size_t ob = (size_t)(ebase + rl) * DD;
#pragma unroll
            for (int j = 0; j < 6; j++) {
                int col = n0 + 8 * j + 2 * c4;
                float2 dh = __bfloat1622float2(*(const __nv_bfloat162*)(g_D + sb + col));
                float2 eh = __bfloat1622float2(*(const __nv_bfloat162*)(g_E + db + col));
                float v0 = acc[i][j][half * 2 + 0] + bsh[col]     + dh.x + eh.x;
                float v1 = acc[i][j][half * 2 + 1] + bsh[col + 1] + dh.y + eh.y;
                *(__nv_bfloat162*)(g_enew + ob + col) =
                    __float22bfloat162_rn(make_float2(v0, v1));
                cs[j][0] += v0; cs[j][1] += v1;
                cq[j][0] += v0 * v0; cq[j][1] += v1 * v1;
            }
        }
    }
    if (do_stats) {
#pragma unroll
        for (int off = 16; off >= 4; off >>= 1) {
#pragma unroll
            for (int j = 0; j < 6; j++) {
#pragma unroll
                for (int p = 0; p < 2; p++) {
                    cs[j][p] += __shfl_down_sync(0xffffffffu, cs[j][p], off);
                    cq[j][p] += __shfl_down_sync(0xffffffffu, cq[j][p], off);
                }
            }
        }
        if (lane < 4) {
#pragma unroll
            for (int j = 0; j < 6; j++) {
#pragma unroll
                for (int p = 0; p < 2; p++) {
                    int col = n0 + 8 * j + 2 * lane + p;
                    atomicAdd(&s_sum[col], cs[j][p]);
                    atomicAdd(&s_sq[col], cq[j][p]);
                }
            }
        }
        __syncthreads();
        if (t < DD) {
            atomicAdd(&g_esum[layer * DD + t], (double)s_sum[t]);
            atomicAdd(&g_esq[layer * DD + t], (double)s_sq[t]);
        }
    }
}

// ------------------------- aggregation (CSR, unroll x2) -----------------------
__global__ __launch_bounds__(256) void k_agg(int layer) {
    __shared__ float ssum[DD], ssq[DD];
    int t = threadIdx.x;
    if (t < DD) { ssum[t] = 0.f; ssq[t] = 0.f; }
    __syncthreads();
    int w = t >> 5, ln = t & 31;
    int v = blockIdx.x * 8 + w;
    float n0 = 0, n1 = 0, n2 = 0, d0 = 0, d1 = 0, d2 = 0;
    int p0 = g_ptr[v], p1 = g_ptr[v + 1];
    int p = p0;
    for (; p + 1 < p1; p += 2) {
        int sa = g_srcp[p], sb_ = g_srcp[p + 1];
        size_t ea = (size_t)p * DD, eb = (size_t)(p + 1) * DD;
        size_t sba = (size_t)sa * DD, sbb = (size_t)sb_ * DD;
        float xa0 = __bfloat162float(g_enew[ea + ln]);
        float xa1 = __bfloat162float(g_enew[ea + ln + 32]);
        float xa2 = __bfloat162float(g_enew[ea + ln + 64]);
        float xb0 = __bfloat162float(g_enew[eb + ln]);
        float xb1 = __bfloat162float(g_enew[eb + ln + 32]);
        float xb2 = __bfloat162float(g_enew[eb + ln + 64]);
        float ba0 = __bfloat162float(g_B[sba + ln]);
        float ba1 = __bfloat162float(g_B[sba + ln + 32]);
        float ba2 = __bfloat162float(g_B[sba + ln + 64]);
        float bb0 = __bfloat162float(g_B[sbb + ln]);
        float bb1 = __bfloat162float(g_B[sbb + ln + 32]);
        float bb2 = __bfloat162float(g_B[sbb + ln + 64]);
        float sa0 = __fdividef(1.f, 1.f + __expf(-xa0));
        float sa1 = __fdividef(1.f, 1.f + __expf(-xa1));
        float sa2 = __fdividef(1.f, 1.f + __expf(-xa2));
        float sb0 = __fdividef(1.f, 1.f + __expf(-xb0));
        float sb1 = __fdividef(1.f, 1.f + __expf(-xb1));
        float sb2 = __fdividef(1.f, 1.f + __expf(-xb2));
        n0 += sa0 * ba0; n0 += sb0 * bb0;
        n1 += sa1 * ba1; n1 += sb1 * bb1;
        n2 += sa2 * ba2; n2 += sb2 * bb2;
        d0 += sa0; d0 += sb0;
        d1 += sa1; d1 += sb1;
        d2 += sa2; d2 += sb2;
    }
    if (p < p1) {
        int s = g_srcp[p];
        size_t eb = (size_t)p * DD;
        size_t sb = (size_t)s * DD;
        float x0 = __bfloat162float(g_enew[eb + ln]);
        float x1 = __bfloat162float(g_enew[eb + ln + 32]);
        float x2 = __bfloat162float(g_enew[eb + ln + 64]);
        float s0 = __fdividef(1.f, 1.f + __expf(-x0));
        float s1 = __fdividef(1.f, 1.f + __expf(-x1));
        float s2 = __fdividef(1.f, 1.f + __expf(-x2));
        n0 += s0 * __bfloat162float(g_B[sb + ln]);
        n1 += s1 * __bfloat162float(g_B[sb + ln + 32]);
        n2 += s2 * __bfloat162float(g_B[sb + ln + 64]);
        d0 += s0; d1 += s1; d2 += s2;
    }
    size_t vb = (size_t)v * DD;
    float h0 = g_A[vb + ln]      + __fdividef(n0, d0 + 1e-6f);
    float h1 = g_A[vb + ln + 32] + __fdividef(n1, d1 + 1e-6f);
    float h2 = g_A[vb + ln + 64] + __fdividef(n2, d2 + 1e-6f);
    g_hnew[vb + ln] = h0; g_hnew[vb + ln + 32] = h1; g_hnew[vb + ln + 64] = h2;
    atomicAdd(&ssum[ln], h0);      atomicAdd(&ssum[ln + 32], h1); atomicAdd(&ssum[ln + 64], h2);
    atomicAdd(&ssq[ln], h0 * h0);  atomicAdd(&ssq[ln + 32], h1 * h1); atomicAdd(&ssq[ln + 64], h2 * h2);
    __syncthreads();
    if (t < DD) {
        atomicAdd(&g_hsum[layer * DD + t], (double)ssum[t]);
        atomicAdd(&g_hsq[layer * DD + t], (double)ssq[t]);
    }
}

// ------------------------- head -----------------------------------------------
__global__ __launch_bounds__(256) void k_head(const float* __restrict__ W1,
                                              const float* __restrict__ b1,
                                              const float* __restrict__ W2,
                                              const float* __restrict__ b2,
                                              const float* __restrict__ maxa,
                                              const float* __restrict__ hg,
                                              const float* __restrict__ hbt,
                                              float* __restrict__ out) {
    extern __shared__ float dyn[];
    float* W1s = dyn;
    float* Hs  = W1s + DD * HIDN;
    float* His = Hs + 32 * DD;
    float* W2s = His + 32 * 132;
    __shared__ float hsc[DD], hsh[DD];
    int t = threadIdx.x;
    if (t < DD)
        bn_scales(g_hsum + 3 * DD, g_hsq + 3 * DD, hg, hbt, (double)NN, t, hsc[t], hsh[t]);
    for (int i = t; i < DD * HIDN; i += 256) W1s[i] = W1[i];
    for (int i = t; i < HIDN * OUTN; i += 256) W2s[i] = W2[i];
    __syncthreads();
    int row0 = blockIdx.x * 32;
    for (int i = t; i < 32 * 24; i += 256) {
        int r = i / 24, c4 = (i - (i / 24) * 24) * 4;
        int gr = row0 + r;
        float4 v = make_float4(0.f, 0.f, 0.f, 0.f);
        if (gr < NN) {
            size_t idx = (size_t)gr * DD + c4;
            v = *(const float4*)(g_h + idx);
            float4 en = *(const float4*)(g_hnew + idx);
            v.x += fmaxf(hsc[c4 + 0] * en.x + hsh[c4 + 0], 0.f);
            v.y += fmaxf(hsc[c4 + 1] * en.y + hsh[c4 + 1], 0.f);
            v.z += fmaxf(hsc[c4 + 2] * en.z + hsh[c4 + 2], 0.f);
            v.w += fmaxf(hsc[c4 + 3] * en.w + hsh[c4 + 3], 0.f);
        }
        *(float4*)(Hs + r * DD + c4) = v;
    }
    __syncthreads();
    {
        int ng = t >> 5, hgr = t & 31;
        int r0 = ng * 4, c0 = hgr * 4;
        ull acc[4][2];
        float4 bv = *(const float4*)(b1 + c0);
        ull b01 = pk2(bv.x, bv.y), b23 = pk2(bv.z, bv.w);
#pragma unroll
        for (int r = 0; r < 4; r++) { acc[r][0] = b01; acc[r][1] = b23; }
#pragma unroll 4
        for (int k = 0; k < DD; k++) {
            ulonglong2 wv = *(const ulonglong2*)(W1s + k * HIDN + c0);
#pragma unroll
            for (int r = 0; r < 4; r++) {
                float x = Hs[(r0 + r) * DD + k];
                ull xx = pk2(x, x);
                acc[r][0] = fma2(xx, wv.x, acc[r][0]);
                acc[r][1] = fma2(xx, wv.y, acc[r][1]);
            }
        }
#pragma unroll
        for (int r = 0; r < 4; r++) {
            float2 a = upk(acc[r][0]), q = upk(acc[r][1]);
            His[(r0 + r) * 132 + c0 + 0] = fmaxf(a.x, 0.f);
            His[(r0 + r) * 132 + c0 + 1] = fmaxf(a.y, 0.f);
            His[(r0 + r) * 132 + c0 + 2] = fmaxf(q.x, 0.f);
            His[(r0 + r) * 132 + c0 + 3] = fmaxf(q.y, 0.f);
        }
    }
    __syncthreads();
    {
        int node = t >> 3, oc = t & 7;
        int gn = row0 + node;
        if (gn < NN) {
            float acc = b2[oc];
#pragma unroll 8
            for (int k = 0; k < HIDN; k++) acc += His[node * 132 + k] * W2s[k * OUTN + oc];
            out[(size_t)gn * OUTN + oc] = maxa[gn] * tanhf(acc);
        }
    }
}

// ------------------------- launch ---------------------------------------------
extern "C" void kernel_launch(void* const* d_in, const int* in_sizes, int n_in,
                              void* d_out, int out_size) {
    const float* h1      = (const float*)d_in[0];
    const float* h2      = (const float*)d_in[1];
    const float* z       = (const float*)d_in[2];
    const float* efeat   = (const float*)d_in[3];
    const float* maxa    = (const float*)d_in[4];
    const float* Wh_emb  = (const float*)d_in[5];
    const float* bh_emb  = (const float*)d_in[6];
    const float* We_emb  = (const float*)d_in[7];
    const float* be_emb  = (const float*)d_in[8];
    const float* WA      = (const float*)d_in[9];
    const float* bA      = (const float*)d_in[10];
    const float* WB      = (const float*)d_in[11];
    const float* bB      = (const float*)d_in[12];
    const float* WC      = (const float*)d_in[13];
    const float* bC      = (const float*)d_in[14];
    const float* WD      = (const float*)d_in[15];
    const float* bD      = (const float*)d_in[16];
    const float* WE      = (const float*)d_in[17];
    const float* bE      = (const float*)d_in[18];
    const float* bn_h_g  = (const float*)d_in[19];
    const float* bn_h_b  = (const float*)d_in[20];
    const float* bn_e_g  = (const float*)d_in[21];
    const float* bn_e_b  = (const float*)d_in[22];
    const float* W1      = (const float*)d_in[23];
    const float* b1      = (const float*)d_in[24];
    const float* W2      = (const float*)d_in[25];
    const float* b2      = (const float*)d_in[26];
    const int*   src     = (const int*)d_in[27];
    const int*   dst     = (const int*)d_in[28];
    float* out = (float*)d_out;

    static cudaStream_t s1 = nullptr;
    static cudaEvent_t ev0, evCSR, evDE[4], evAB[4];
    if (!s1) {
        cudaStreamCreateWithFlags(&s1, cudaStreamNonBlocking);
        cudaEventCreateWithFlags(&ev0, cudaEventDisableTiming);
        cudaEventCreateWithFlags(&evCSR, cudaEventDisableTiming);
        for (int i = 0; i < 4; i++) {
            cudaEventCreateWithFlags(&evDE[i], cudaEventDisableTiming);
            cudaEventCreateWithFlags(&evAB[i], cudaEventDisableTiming);
        }
    }

    float *WDE_base, *WAB_base;
    __nv_bfloat16* WtC_base;
    cudaGetSymbolAddress((void**)&WDE_base, g_WDE);
    cudaGetSymbolAddress((void**)&WAB_base, g_WAB);
    cudaGetSymbolAddress((void**)&WtC_base, g_WtC);

    cudaFuncSetAttribute(k_mat2, cudaFuncAttributeMaxDynamicSharedMemorySize, 110 * 1024);
    cudaFuncSetAttribute(k_edge, cudaFuncAttributeMaxDynamicSharedMemorySize, 64 * 1024);
    cudaFuncSetAttribute(k_head, cudaFuncAttributeMaxDynamicSharedMemorySize, 96 * 1024);

    const int smem_mat2 = (DD * WS2 + 64 * XSTR + 192) * 4;                     // 105216
    const int smem_edge = (DD * WSTR + 128 * ESTRB) * 2;                        // 46592
    const int smem_head = (DD * HIDN + 32 * DD + 32 * 132 + HIDN * OUTN) * 4;   // 82432

    // main: zero, then fork CSR chain onto s1 while main does prep
    k_zero<<<(NN + 255) / 256, 256>>>();
    cudaEventRecord(ev0, 0);
    cudaStreamWaitEvent(s1, ev0, 0);
    k_count<<<EE / 256, 256, 0, s1>>>(dst);
    k_scan1<<<NBS, 256, 0, s1>>>();
    k_scan2<<<1, 256, 0, s1>>>();
    k_scan3<<<NBS, 256, 0, s1>>>();
    k_fill<<<EE / 256, 256, 0, s1>>>(dst);
    k_sortperm<<<(NN + 127) / 128, 128, 0, s1>>>(src, dst);
    cudaEventRecord(evCSR, s1);

    const int prep_blks = EMB_BLKS + (184320 + 255) / 256;
    k_prep<<<prep_blks, 256>>>(h1, h2, z, Wh_emb, bh_emb, WA, WB, WC, WD, WE);

    const int ablk = (NN + 63) / 64;   // 782
    const int eblk = EE / 128;         // 6250

    for (int l = 0; l < 4; l++) {
        int lp = (l > 0) ? l - 1 : 0;
        // matDE on main (applies lazy h update)
        k_mat2<<<ablk, 256, smem_mat2>>>(WDE_base + l * DD * 192,
                                         bD + l * DD, bE + l * DD,
                                         bn_h_g + lp * DD, bn_h_b + lp * DD,
                                         l, l >= 1 ? 1 : 0, 0);
        cudaEventRecord(evDE[l], 0);
        // matAB on s1, concurrent with edge
        cudaStreamWaitEvent(s1, evDE[l], 0);
        k_mat2<<<ablk, 256, smem_mat2, s1>>>(WAB_base + l * DD * 192,
                                             bA + l * DD, bB + l * DD,
                                             bn_h_g, bn_h_b, l, 0, 1);
        cudaEventRecord(evAB[l], s1);

        if (l == 0) cudaStreamWaitEvent(0, evCSR, 0);
        int embed = (l == 0) ? 1 : 0;
        int apply = (l >= 1) ? 1 : 0;
        int write_e = (l >= 1 && l < 3) ? 1 : 0;
        int do_stats = (l < 3) ? 1 : 0;
        k_edge<<<eblk, 256, smem_edge>>>(WtC_base + l * DD * DD, bC + l * DD,
                                         efeat, We_emb, be_emb,
                                         bn_e_g + lp * DD, bn_e_b + lp * DD,
                                         l, embed, apply, write_e, do_stats);

        cudaStreamWaitEvent(0, evAB[l], 0);
        k_agg<<<NN / 8, 256>>>(l);
    }

    k_head<<<(NN + 31) / 32, 256, smem_head>>>(W1, b1, W2, b2, maxa,
                                               bn_h_g + 3 * DD, bn_h_b + 3 * DD, out);
}

// round 13
// speedup vs baseline: 2.3947x; 1.0092x over previous
#include <cuda_runtime.h>
#include <cuda_bf16.h>
#include <math.h>

#define NN 50000
#define EE 800000
#define DD 96
#define HIDN 128
#define OUTN 8
#define NBS 196    // scan blocks = ceil(NN/256)
#define WSTR 104   // bf16 smem stride (elements) for W^T  — conflict-free (edge)
#define ESTRB 104  // bf16 smem stride (elements) for E tile (edge)
#define XSTR 108   // f32/tf32 smem stride for X tile (mat kernels)
#define WS2 200    // f32/tf32 smem stride for 2-matrix concat W (mat kernels)
#define EMB_BLKS 18750  // (NN*DD+255)/256

typedef unsigned long long ull;

// ------------------------- device scratch (no allocs allowed) ----------------
__device__ float g_h[(size_t)NN * DD];
__device__ float g_hnew[(size_t)NN * DD];
__device__ float g_A[(size_t)NN * DD];             // f32 (residual-critical)
__device__ __nv_bfloat16 g_B[(size_t)NN * DD];     // gathered tables in bf16
__device__ __nv_bfloat16 g_D[(size_t)NN * DD];
__device__ __nv_bfloat16 g_E[(size_t)NN * DD];
__device__ __nv_bfloat16 g_e[(size_t)EE * DD];     // permuted (CSR dst order)
__device__ __nv_bfloat16 g_enew[(size_t)EE * DD];  // permuted
__device__ __nv_bfloat16 g_WtC[4 * DD * DD];       // pre-transposed bf16 WC per layer
__device__ float g_WDE[4 * DD * 192];              // tf32-prerounded [WD|WE] per layer
__device__ float g_WAB[4 * DD * 192];              // tf32-prerounded [WA|WB] per layer
__device__ int   g_cnt[NN];
__device__ int   g_ptr[NN + 1];
__device__ int   g_woff[NN];
__device__ int   g_eid[EE];
__device__ int   g_srcp[EE];
__device__ int   g_dstp[EE];
__device__ int   g_bsum[256];
__device__ int   g_boff[256];
// layer-indexed stats (no reset races)
__device__ double g_esum[4 * DD], g_esq[4 * DD], g_hsum[4 * DD], g_hsq[4 * DD];

// ------------------------- helpers -------------------------------------------
__device__ __forceinline__ ull pk2(float lo, float hi) {
    ull r; asm("mov.b64 %0,{%1,%2};" : "=l"(r) : "f"(lo), "f"(hi)); return r;
}
__device__ __forceinline__ ull fma2(ull a, ull b, ull c) {
    ull d; asm("fma.rn.f32x2 %0,%1,%2,%3;" : "=l"(d) : "l"(a), "l"(b), "l"(c)); return d;
}
__device__ __forceinline__ float2 upk(ull v) {
    float2 f; asm("mov.b64 {%0,%1},%2;" : "=f"(f.x), "=f"(f.y) : "l"(v)); return f;
}
__device__ __forceinline__ float tf32r(float x) {
    unsigned u; asm("cvt.rna.tf32.f32 %0,%1;" : "=r"(u) : "f"(x));
    return __uint_as_float(u);
}
#define MMA_TF32(d, a, b0_, b1_) \
    asm volatile("mma.sync.aligned.m16n8k8.row.col.f32.tf32.tf32.f32 " \
        "{%0,%1,%2,%3},{%4,%5,%6,%7},{%8,%9},{%0,%1,%2,%3};" \
        : "+f"(d[0]), "+f"(d[1]), "+f"(d[2]), "+f"(d[3]) \
        : "r"(a[0]), "r"(a[1]), "r"(a[2]), "r"(a[3]), "r"(b0_), "r"(b1_))
#define MMA_BF16(d, a, b0_, b1_) \
    asm volatile("mma.sync.aligned.m16n8k16.row.col.f32.bf16.bf16.f32 " \
        "{%0,%1,%2,%3},{%4,%5,%6,%7},{%8,%9},{%0,%1,%2,%3};" \
        : "+f"(d[0]), "+f"(d[1]), "+f"(d[2]), "+f"(d[3]) \
        : "r"(a[0]), "r"(a[1]), "r"(a[2]), "r"(a[3]), "r"(b0_), "r"(b1_))

__device__ __forceinline__ void bf8_to_f(const uint4& u, float* f) {
    const __nv_bfloat162* p = (const __nv_bfloat162*)&u;
#pragma unroll
    for (int j = 0; j < 4; j++) {
        float2 t = __bfloat1622float2(p[j]);
        f[2 * j] = t.x; f[2 * j + 1] = t.y;
    }
}
__device__ __forceinline__ uint4 f_to_bf8(const float* f) {
    uint4 u;
    __nv_bfloat162* p = (__nv_bfloat162*)&u;
#pragma unroll
    for (int j = 0; j < 4; j++)
        p[j] = __float22bfloat162_rn(make_float2(f[2 * j], f[2 * j + 1]));
    return u;
}
__device__ __forceinline__ void bn_scales(const double* sum, const double* sq,
                                          const float* gamma, const float* beta,
                                          double count, int c, float& sc, float& sh) {
    double s = sum[c], q = sq[c];
    double m = s / count;
    double var = q / count - m * m;
    sc = gamma[c] * rsqrtf((float)var + 1e-5f);
    sh = beta[c] - (float)m * sc;
}

// ------------------------- setup ----------------------------------------------
__global__ void k_zero() {
    int i = blockIdx.x * blockDim.x + threadIdx.x;
    if (i < NN) g_cnt[i] = 0;
    if (i < 4 * DD) { g_esum[i] = 0.0; g_esq[i] = 0.0; g_hsum[i] = 0.0; g_hsq[i] = 0.0; }
}

// embed_h (blocks < EMB_BLKS) + weight prep (rest): tf32-preround ABDE, bf16 WtC
__global__ void k_prep(const float* __restrict__ h1, const float* __restrict__ h2,
                       const float* __restrict__ z,
                       const float* __restrict__ Wh, const float* __restrict__ bh,
                       const float* __restrict__ WA, const float* __restrict__ WB,
                       const float* __restrict__ WC, const float* __restrict__ WD,
                       const float* __restrict__ WE) {
    int t = threadIdx.x;
    if (blockIdx.x < EMB_BLKS) {
        __shared__ float Ws[26 * DD];
        for (int i = t; i < 26 * DD; i += 256) Ws[i] = Wh[i];
        __syncthreads();
        int idx = blockIdx.x * 256 + t;
        if (idx >= NN * DD) return;
        int r = idx / DD, c = idx - (idx / DD) * DD;
        float acc = bh[c];
#pragma unroll
        for (int k = 0; k < 6; k++)  acc += h1[r * 6 + k]  * Ws[k * DD + c];
#pragma unroll
        for (int k = 0; k < 4; k++)  acc += h2[r * 4 + k]  * Ws[(6 + k) * DD + c];
#pragma unroll
        for (int k = 0; k < 16; k++) acc += z[r * 16 + k]  * Ws[(10 + k) * DD + c];
        g_h[idx] = acc;
        return;
    }
    int j = (blockIdx.x - EMB_BLKS) * 256 + t;
    if (j < 73728) {                         // WDE concat, tf32 bits
        int l = j / 18432, r = j - l * 18432;
        int k = r / 192, c = r - k * 192;
        int m = c / DD, cc = c - m * DD;
        const float* src = m ? WE : WD;
        g_WDE[j] = tf32r(src[(size_t)l * DD * DD + k * DD + cc]);
    } else if (j < 147456) {                 // WAB concat
        int i = j - 73728;
        int l = i / 18432, r = i - l * 18432;
        int k = r / 192, c = r - k * 192;
        int m = c / DD, cc = c - m * DD;
        const float* src = m ? WB : WA;
        g_WAB[i] = tf32r(src[(size_t)l * DD * DD + k * DD + cc]);
    } else if (j < 184320) {                 // WtC transposed bf16
        int i = j - 147456;
        int l = i / 9216, r = i - l * 9216;
        int k = r / DD, n = r - k * DD;
        g_WtC[l * DD * DD + n * DD + k] = __float2bfloat16(WC[(size_t)l * DD * DD + k * DD + n]);
    }
}

// ------------------------- CSR build ------------------------------------------
__global__ void k_count(const int* __restrict__ dst) {
    int i = blockIdx.x * blockDim.x + threadIdx.x;
    if (i < EE) atomicAdd(&g_cnt[dst[i]], 1);
}

__global__ void k_scan1() {
    __shared__ int sh[256];
    int t = threadIdx.x, b = blockIdx.x;
    int j = b * 256 + t;
    int v = (j < NN) ? g_cnt[j] : 0;
    sh[t] = v; __syncthreads();
    for (int off = 1; off < 256; off <<= 1) {
        int u = (t >= off) ? sh[t - off] : 0;
        __syncthreads();
        sh[t] += u;
        __syncthreads();
    }
    if (j < NN) g_ptr[j] = sh[t] - v;
    if (t == 255) g_bsum[b] = sh[t];
}

__global__ void k_scan2() {
    __shared__ int sh[256];
    int t = threadIdx.x;
    int v = (t < NBS) ? g_bsum[t] : 0;
    sh[t] = v; __syncthreads();
    for (int off = 1; off < 256; off <<= 1) {
        int u = (t >= off) ? sh[t - off] : 0;
        __syncthreads();
        sh[t] += u;
        __syncthreads();
    }
    g_boff[t] = sh[t] - v;
}

__global__ void k_scan3() {
    int j = blockIdx.x * blockDim.x + threadIdx.x;
    if (j < NN) {
        int p = g_ptr[j] + g_boff[j >> 8];
        g_ptr[j] = p; g_woff[j] = p;
    }
    if (j == 0) g_ptr[NN] = EE;
}

__global__ void k_fill(const int* __restrict__ dst) {
    int i = blockIdx.x * blockDim.x + threadIdx.x;
    if (i < EE) {
        int pos = atomicAdd(&g_woff[dst[i]], 1);
        g_eid[pos] = i;
    }
}

// sort each node's segment + emit permuted src/dst (merged)
__global__ void k_sortperm(const int* __restrict__ src, const int* __restrict__ dst) {
    int v = blockIdx.x * blockDim.x + threadIdx.x;
    if (v >= NN) return;
    int lo = g_ptr[v], hi = g_ptr[v + 1];
    for (int i = lo + 1; i < hi; i++) {
        int key = g_eid[i]; int j = i - 1;
        while (j >= lo && g_eid[j] > key) { g_eid[j + 1] = g_eid[j]; j--; }
        g_eid[j + 1] = key;
    }
    for (int i = lo; i < hi; i++) {
        int ei = g_eid[i];
        g_srcp[i] = src[ei];
        g_dstp[i] = dst[ei];
    }
}

// ------------------------- node GEMM (tf32 MMA), 2-matrix variant -------------
__global__ __launch_bounds__(256) void k_mat2(const float* __restrict__ Wcat,
                                              const float* __restrict__ b0_,
                                              const float* __restrict__ b1_,
                                              const float* __restrict__ hg,
                                              const float* __restrict__ hbt,
                                              int layer, int apply, int isAB) {
    extern __shared__ float dyn[];
    float* Ws = dyn;                     // [96 k][WS2] tf32 bits (pre-rounded)
    float* Xs = dyn + DD * WS2;          // [64 rows][XSTR] tf32
    float* Bs = Xs + 64 * XSTR;          // [192]
    __shared__ float shsc[DD], shsh[DD];
    int t = threadIdx.x;
    int lane = t & 31, w = t >> 5;
    if (apply && t < DD)
        bn_scales(g_hsum + (layer - 1) * DD, g_hsq + (layer - 1) * DD,
                  hg, hbt, (double)NN, t, shsc[t], shsh[t]);
    for (int i = t; i < DD * 48; i += 256) {
        int k = i / 48, c4 = (i - (i / 48) * 48) * 4;
        *(float4*)(Ws + k * WS2 + c4) = *(const float4*)(Wcat + k * 192 + c4);
    }
    for (int i = t; i < 192; i += 256) Bs[i] = (i < DD) ? b0_[i] : b1_[i - DD];
    __syncthreads();
    int row0 = blockIdx.x * 64;
    for (int i = t; i < 64 * 24; i += 256) {
        int r = i / 24, c4 = (i - (i / 24) * 24) * 4;
        int gr = row0 + r;
        float4 v = make_float4(0.f, 0.f, 0.f, 0.f);
        if (gr < NN) {
            size_t idx = (size_t)gr * DD + c4;
            v = *(const float4*)(g_h + idx);
            if (apply) {
                float4 en = *(const float4*)(g_hnew + idx);
                v.x += fmaxf(shsc[c4 + 0] * en.x + shsh[c4 + 0], 0.f);
                v.y += fmaxf(shsc[c4 + 1] * en.y + shsh[c4 + 1], 0.f);
                v.z += fmaxf(shsc[c4 + 2] * en.z + shsh[c4 + 2], 0.f);
                v.w += fmaxf(shsc[c4 + 3] * en.w + shsh[c4 + 3], 0.f);
                *(float4*)(g_h + idx) = v;
            }
        }
        v.x = tf32r(v.x); v.y = tf32r(v.y); v.z = tf32r(v.z); v.w = tf32r(v.w);
        *(float4*)(Xs + r * XSTR + c4) = v;
    }
    __syncthreads();

    int mg = w >> 2, ng = w & 3;          // 2 x 4 warp grid, 192 cols
    int m0 = mg * 32, n0 = ng * 48;
    int g = lane >> 2, c4 = lane & 3;
    float acc[2][6][4];
#pragma unroll
    for (int i = 0; i < 2; i++)
#pragma unroll
        for (int j = 0; j < 6; j++)
#pragma unroll
            for (int q = 0; q < 4; q++) acc[i][j][q] = 0.f;

#pragma unroll
    for (int k0 = 0; k0 < DD; k0 += 8) {
        unsigned a[2][4];
#pragma unroll
        for (int i = 0; i < 2; i++) {
            int rr = (m0 + i * 16 + g) * XSTR;
            a[i][0] = __float_as_uint(Xs[rr + k0 + c4]);
            a[i][1] = __float_as_uint(Xs[rr + 8 * XSTR + k0 + c4]);
            a[i][2] = __float_as_uint(Xs[rr + k0 + 4 + c4]);
            a[i][3] = __float_as_uint(Xs[rr + 8 * XSTR + k0 + 4 + c4]);
        }
#pragma unroll
        for (int j = 0; j < 6; j++) {
            int col = n0 + 8 * j + g;
            unsigned b0 = __float_as_uint(Ws[(k0 + c4) * WS2 + col]);
            unsigned b1 = __float_as_uint(Ws[(k0 + 4 + c4) * WS2 + col]);
            MMA_TF32(acc[0][j], a[0], b0, b1);
            MMA_TF32(acc[1][j], a[1], b0, b1);
        }
    }

    int m = n0 / DD;
    int ncc = n0 - m * DD;
    __nv_bfloat16* outb = isAB ? g_B : (m == 0 ? g_D : g_E);
    int is_f32 = (isAB && m == 0);
#pragma unroll
    for (int i = 0; i < 2; i++) {
#pragma unroll
        for (int half = 0; half < 2; half++) {
            int rl = m0 + i * 16 + half * 8 + g;
            int gr = row0 + rl;
            if (gr < NN) {
#pragma unroll
                for (int j = 0; j < 6; j++) {
                    int col = n0 + 8 * j + 2 * c4;
                    int cc = ncc + 8 * j + 2 * c4;
                    float v0 = acc[i][j][half * 2 + 0] + Bs[col];
                    float v1 = acc[i][j][half * 2 + 1] + Bs[col + 1];
                    if (is_f32) {
                        *(float2*)(g_A + (size_t)gr * DD + cc) = make_float2(v0, v1);
                    } else {
                        *(__nv_bfloat162*)(outb + (size_t)gr * DD + cc) =
                            __float22bfloat162_rn(make_float2(v0, v1));
                    }
                }
            }
        }
    }
}

// ------------------------- edge kernel: bf16 MMA + staged gathers -------------
__global__ __launch_bounds__(256) void k_edge(const __nv_bfloat16* __restrict__ Wtg,
                                              const float* __restrict__ b,
                                              const float* __restrict__ efeat,
                                              const float* __restrict__ Wemb,
                                              const float* __restrict__ bemb,
                                              const float* __restrict__ eg,
                                              const float* __restrict__ ebt,
                                              int layer, int embed, int apply,
                                              int write_e, int do_stats) {
    extern __shared__ char dync[];
    __nv_bfloat16* Wt = (__nv_bfloat16*)dync;        // [96 cols][WSTR k]  (phase 1)
    __nv_bfloat16* Es = Wt + DD * WSTR;              // [128 rows][ESTRB k] (phase 1)
    __nv_bfloat16* Ds  = (__nv_bfloat16*)dync;       // [128][ESTRB] gathered Dh (phase 2)
    __nv_bfloat16* Eh2 = Ds + 128 * ESTRB;           // [128][ESTRB] gathered Eh (phase 2)
    __shared__ float s_sum[DD], s_sq[DD], bsh[DD];
    __shared__ float s_esc[DD], s_esh[DD];
    __shared__ int s_src[128], s_dst[128];
    __shared__ float s_ef[128 * 4];
    __shared__ float s_wemb[4 * DD];
    __shared__ float s_bemb[DD];
    int t = threadIdx.x;
    int lane = t & 31, w = t >> 5;
    if (t < DD) {
        s_sum[t] = 0.f; s_sq[t] = 0.f; bsh[t] = b[t];
        if (apply)
            bn_scales(g_esum + (layer - 1) * DD, g_esq + (layer - 1) * DD,
                      eg, ebt, (double)EE, t, s_esc[t], s_esh[t]);
    }
    for (int i = t; i < DD * 12; i += 256) {
        int col = i / 12, kk = (i - (i / 12) * 12) * 8;
        *(uint4*)(Wt + col * WSTR + kk) = *(const uint4*)(Wtg + col * DD + kk);
    }
    int ebase = blockIdx.x * 128;   // EE % 128 == 0
    if (t < 128) { s_src[t] = g_srcp[ebase + t]; s_dst[t] = g_dstp[ebase + t]; }
    if (embed) {
        for (int i = t; i < 4 * DD; i += 256) s_wemb[i] = Wemb[i];
        if (t < DD) s_bemb[t] = bemb[t];
        if (t < 128) {
            int ei = g_eid[ebase + t];
            *(float4*)(s_ef + t * 4) = *(const float4*)(efeat + (size_t)ei * 4);
        }
    }
    __syncthreads();
    if (embed) {
        for (int i = t; i < 128 * 12; i += 256) {
            int r = i / 12, c8 = (i - (i / 12) * 12) * 8;
            size_t idx = (size_t)(ebase + r) * DD + c8;
            float4 f = *(const float4*)(s_ef + r * 4);
            float v[8];
#pragma unroll
            for (int j = 0; j < 8; j++) {
                int c = c8 + j;
                v[j] = s_bemb[c] + f.x * s_wemb[c] + f.y * s_wemb[DD + c]
                     + f.z * s_wemb[2 * DD + c] + f.w * s_wemb[3 * DD + c];
            }
            uint4 packed = f_to_bf8(v);
            *(uint4*)(g_e + idx) = packed;
            *(uint4*)(Es + r * ESTRB + c8) = packed;
        }
    } else {
        for (int i = t; i < 128 * 12; i += 256) {
            int r = i / 12, c8 = (i - (i / 12) * 12) * 8;
            size_t idx = (size_t)(ebase + r) * DD + c8;
            uint4 ue = *(const uint4*)(g_e + idx);
            if (apply) {
                float v[8], en[8];
                bf8_to_f(ue, v);
                uint4 un = *(const uint4*)(g_enew + idx);
                bf8_to_f(un, en);
#pragma unroll
                for (int j = 0; j < 8; j++)
                    v[j] += fmaxf(s_esc[c8 + j] * en[j] + s_esh[c8 + j], 0.f);
                uint4 packed = f_to_bf8(v);
                if (write_e) *(uint4*)(g_e + idx) = packed;
                *(uint4*)(Es + r * ESTRB + c8) = packed;
            } else {
                *(uint4*)(Es + r * ESTRB + c8) = ue;
            }
        }
    }
    __syncthreads();

    int mg = w >> 1, ng = w & 1;
    int m0 = mg * 32, n0 = ng * 48;
    int g = lane >> 2, c4 = lane & 3;
    float acc[2][6][4];
#pragma unroll
    for (int i = 0; i < 2; i++)
#pragma unroll
        for (int j = 0; j < 6; j++)
#pragma unroll
            for (int q = 0; q < 4; q++) acc[i][j][q] = 0.f;

#pragma unroll
    for (int k0 = 0; k0 < DD; k0 += 16) {
        unsigned a[2][4];
#pragma unroll
        for (int i = 0; i < 2; i++) {
            int rr = (m0 + i * 16 + g) * ESTRB;
            a[i][0] = *(const unsigned*)(Es + rr + k0 + 2 * c4);
            a[i][1] = *(const unsigned*)(Es + rr + 8 * ESTRB + k0 + 2 * c4);
            a[i][2] = *(const unsigned*)(Es + rr + k0 + 8 + 2 * c4);
            a[i][3] = *(const unsigned*)(Es + rr + 8 * ESTRB + k0 + 8 + 2 * c4);
        }
#pragma unroll
        for (int j = 0; j < 6; j++) {
            int col = n0 + 8 * j + g;
            unsigned b0 = *(const unsigned*)(Wt + col * WSTR + k0 + 2 * c4);
            unsigned b1 = *(const unsigned*)(Wt + col * WSTR + k0 + 8 + 2 * c4);
            MMA_BF16(acc[0][j], a[0], b0, b1);
            MMA_BF16(acc[1][j], a[1], b0, b1);
        }
    }
    __syncthreads();   // Wt/Es dead; recycle smem for gathered rows

    // cooperative gather staging: high-MLP 16B loads, dst rows L1-deduped
    for (int i = t; i < 128 * 12; i += 256) {
        int r = i / 12, c8 = (i - (i / 12) * 12) * 8;
        uint4 dv = *(const uint4*)(g_D + (size_t)s_src[r] * DD + c8);
        uint4 ev = *(const uint4*)(g_E + (size_t)s_dst[r] * DD + c8);
        *(uint4*)(Ds  + r * ESTRB + c8) = dv;
        *(uint4*)(Eh2 + r * ESTRB + c8) = ev;
    }
    __syncthreads();

    float cs[6][2], cq[6][2];
#pragma unroll
    for (int j = 0; j < 6; j++) { cs[j][0] = cs[j][1] = 0.f; cq[j][0] = cq[j][1] = 0.f; }
#pragma unroll
    for (int i = 0; i < 2; i++) {
#pragma unroll
        for (int half = 0; half < 2; half++) {
            int rl = m0 + i * 16 + half * 8 + g;
            size_t ob = (size_t)(ebase + rl) * DD;
#pragma unroll
            for (int j = 0; j < 6; j++) {
                int col = n0 + 8 * j + 2 * c4;
                float2 dh = __bfloat1622float2(*(const __nv_bfloat162*)(Ds  + rl * ESTRB + col));
                float2 eh = __bfloat1622float2(*(const __nv_bfloat162*)(Eh2 + rl * ESTRB + col));
                float v0 = acc[i][j][half * 2 + 0] + bsh[col]     + dh.x + eh.x;
                float v1 = acc[i][j][half * 2 + 1] + bsh[col + 1] + dh.y + eh.y;
                *(__nv_bfloat162*)(g_enew + ob + col) =
                    __float22bfloat162_rn(make_float2(v0, v1));
                cs[j][0] += v0; cs[j][1] += v1;
                cq[j][0] += v0 * v0; cq[j][1] += v1 * v1;
            }
        }
    }
    if (do_stats) {
#pragma unroll
        for (int off = 16; off >= 4; off >>= 1) {
#pragma unroll
            for (int j = 0; j < 6; j++) {
#pragma unroll
                for (int p = 0; p < 2; p++) {
                    cs[j][p] += __shfl_down_sync(0xffffffffu, cs[j][p], off);
                    cq[j][p] += __shfl_down_sync(0xffffffffu, cq[j][p], off);
                }
            }
        }
        if (lane < 4) {
#pragma unroll
            for (int j = 0; j < 6; j++) {
#pragma unroll
                for (int p = 0; p < 2; p++) {
                    int col = n0 + 8 * j + 2 * lane + p;
                    atomicAdd(&s_sum[col], cs[j][p]);
                    atomicAdd(&s_sq[col], cq[j][p]);
                }
            }
        }
        __syncthreads();
        if (t < DD) {
            atomicAdd(&g_esum[layer * DD + t], (double)s_sum[t]);
            atomicAdd(&g_esq[layer * DD + t], (double)s_sq[t]);
        }
    }
}

// ------------------------- aggregation (CSR, unroll x2) -----------------------
__global__ __launch_bounds__(256) void k_agg(int layer) {
    __shared__ float ssum[DD], ssq[DD];
    int t = threadIdx.x;
    if (t < DD) { ssum[t] = 0.f; ssq[t] = 0.f; }
    __syncthreads();
    int w = t >> 5, ln = t & 31;
    int v = blockIdx.x * 8 + w;
    float n0 = 0, n1 = 0, n2 = 0, d0 = 0, d1 = 0, d2 = 0;
    int p0 = g_ptr[v], p1 = g_ptr[v + 1];
    int p = p0;
    for (; p + 1 < p1; p += 2) {
        int sa = g_srcp[p], sb_ = g_srcp[p + 1];
        size_t ea = (size_t)p * DD, eb = (size_t)(p + 1) * DD;
        size_t sba = (size_t)sa * DD, sbb = (size_t)sb_ * DD;
        float xa0 = __bfloat162float(g_enew[ea + ln]);
        float xa1 = __bfloat162float(g_enew[ea + ln + 32]);
        float xa2 = __bfloat162float(g_enew[ea + ln + 64]);
        float xb0 = __bfloat162float(g_enew[eb + ln]);
        float xb1 = __bfloat162float(g_enew[eb + ln + 32]);
        float xb2 = __bfloat162float(g_enew[eb + ln + 64]);
        float ba0 = __bfloat162float(g_B[sba + ln]);
        float ba1 = __bfloat162float(g_B[sba + ln + 32]);
        float ba2 = __bfloat162float(g_B[sba + ln + 64]);
        float bb0 = __bfloat162float(g_B[sbb + ln]);
        float bb1 = __bfloat162float(g_B[sbb + ln + 32]);
        float bb2 = __bfloat162float(g_B[sbb + ln + 64]);
        float sa0 = __fdividef(1.f, 1.f + __expf(-xa0));
        float sa1 = __fdividef(1.f, 1.f + __expf(-xa1));
        float sa2 = __fdividef(1.f, 1.f + __expf(-xa2));
        float sb0 = __fdividef(1.f, 1.f + __expf(-xb0));
        float sb1 = __fdividef(1.f, 1.f + __expf(-xb1));
        float sb2 = __fdividef(1.f, 1.f + __expf(-xb2));
        n0 += sa0 * ba0; n0 += sb0 * bb0;
        n1 += sa1 * ba1; n1 += sb1 * bb1;
        n2 += sa2 * ba2; n2 += sb2 * bb2;
        d0 += sa0; d0 += sb0;
        d1 += sa1; d1 += sb1;
        d2 += sa2; d2 += sb2;
    }
    if (p < p1) {
        int s = g_srcp[p];
        size_t eb = (size_t)p * DD;
        size_t sb = (size_t)s * DD;
        float x0 = __bfloat162float(g_enew[eb + ln]);
        float x1 = __bfloat162float(g_enew[eb + ln + 32]);
        float x2 = __bfloat162float(g_enew[eb + ln + 64]);
        float s0 = __fdividef(1.f, 1.f + __expf(-x0));
        float s1 = __fdividef(1.f, 1.f + __expf(-x1));
        float s2 = __fdividef(1.f, 1.f + __expf(-x2));
        n0 += s0 * __bfloat162float(g_B[sb + ln]);
        n1 += s1 * __bfloat162float(g_B[sb + ln + 32]);
        n2 += s2 * __bfloat162float(g_B[sb + ln + 64]);
        d0 += s0; d1 += s1; d2 += s2;
    }
    size_t vb = (size_t)v * DD;
    float h0 = g_A[vb + ln]      + __fdividef(n0, d0 + 1e-6f);
    float h1 = g_A[vb + ln + 32] + __fdividef(n1, d1 + 1e-6f);
    float h2 = g_A[vb + ln + 64] + __fdividef(n2, d2 + 1e-6f);
    g_hnew[vb + ln] = h0; g_hnew[vb + ln + 32] = h1; g_hnew[vb + ln + 64] = h2;
    atomicAdd(&ssum[ln], h0);      atomicAdd(&ssum[ln + 32], h1); atomicAdd(&ssum[ln + 64], h2);
    atomicAdd(&ssq[ln], h0 * h0);  atomicAdd(&ssq[ln + 32], h1 * h1); atomicAdd(&ssq[ln + 64], h2 * h2);
    __syncthreads();
    if (t < DD) {
        atomicAdd(&g_hsum[layer * DD + t], (double)ssum[t]);
        atomicAdd(&g_hsq[layer * DD + t], (double)ssq[t]);
    }
}

// ------------------------- head -----------------------------------------------
__global__ __launch_bounds__(256) void k_head(const float* __restrict__ W1,
                                              const float* __restrict__ b1,
                                              const float* __restrict__ W2,
                                              const float* __restrict__ b2,
                                              const float* __restrict__ maxa,
                                              const float* __restrict__ hg,
                                              const float* __restrict__ hbt,
                                              float* __restrict__ out) {
    extern __shared__ float dyn[];
    float* W1s = dyn;
    float* Hs  = W1s + DD * HIDN;
    float* His = Hs + 32 * DD;
    float* W2s = His + 32 * 132;
    __shared__ float hsc[DD], hsh[DD];
    int t = threadIdx.x;
    if (t < DD)
        bn_scales(g_hsum + 3 * DD, g_hsq + 3 * DD, hg, hbt, (double)NN, t, hsc[t], hsh[t]);
    for (int i = t; i < DD * HIDN; i += 256) W1s[i] = W1[i];
    for (int i = t; i < HIDN * OUTN; i += 256) W2s[i] = W2[i];
    __syncthreads();
    int row0 = blockIdx.x * 32;
    for (int i = t; i < 32 * 24; i += 256) {
        int r = i / 24, c4 = (i - (i / 24) * 24) * 4;
        int gr = row0 + r;
        float4 v = make_float4(0.f, 0.f, 0.f, 0.f);
        if (gr < NN) {
            size_t idx = (size_t)gr * DD + c4;
            v = *(const float4*)(g_h + idx);
            float4 en = *(const float4*)(g_hnew + idx);
            v.x += fmaxf(hsc[c4 + 0] * en.x + hsh[c4 + 0], 0.f);
            v.y += fmaxf(hsc[c4 + 1] * en.y + hsh[c4 + 1], 0.f);
            v.z += fmaxf(hsc[c4 + 2] * en.z + hsh[c4 + 2], 0.f);
            v.w += fmaxf(hsc[c4 + 3] * en.w + hsh[c4 + 3], 0.f);
        }
        *(float4*)(Hs + r * DD + c4) = v;
    }
    __syncthreads();
    {
        int ng = t >> 5, hgr = t & 31;
        int r0 = ng * 4, c0 = hgr * 4;
        ull acc[4][2];
        float4 bv = *(const float4*)(b1 + c0);
        ull b01 = pk2(bv.x, bv.y), b23 = pk2(bv.z, bv.w);
#pragma unroll
        for (int r = 0; r < 4; r++) { acc[r][0] = b01; acc[r][1] = b23; }
#pragma unroll 4
        for (int k = 0; k < DD; k++) {
            ulonglong2 wv = *(const ulonglong2*)(W1s + k * HIDN + c0);
#pragma unroll
            for (int r = 0; r < 4; r++) {
                float x = Hs[(r0 + r) * DD + k];
                ull xx = pk2(x, x);
                acc[r][0] = fma2(xx, wv.x, acc[r][0]);
                acc[r][1] = fma2(xx, wv.y, acc[r][1]);
            }
        }
#pragma unroll
        for (int r = 0; r < 4; r++) {
            float2 a = upk(acc[r][0]), q = upk(acc[r][1]);
            His[(r0 + r) * 132 + c0 + 0] = fmaxf(a.x, 0.f);
            His[(r0 + r) * 132 + c0 + 1] = fmaxf(a.y, 0.f);
            His[(r0 + r) * 132 + c0 + 2] = fmaxf(q.x, 0.f);
            His[(r0 + r) * 132 + c0 + 3] = fmaxf(q.y, 0.f);
        }
    }
    __syncthreads();
    {
        int node = t >> 3, oc = t & 7;
        int gn = row0 + node;
        if (gn < NN) {
            float acc = b2[oc];
#pragma unroll 8
            for (int k = 0; k < HIDN; k++) acc += His[node * 132 + k] * W2s[k * OUTN + oc];
            out[(size_t)gn * OUTN + oc] = maxa[gn] * tanhf(acc);
        }
    }
}

// ------------------------- launch ---------------------------------------------
extern "C" void kernel_launch(void* const* d_in, const int* in_sizes, int n_in,
                              void* d_out, int out_size) {
    const float* h1      = (const float*)d_in[0];
    const float* h2      = (const float*)d_in[1];
    const float* z       = (const float*)d_in[2];
    const float* efeat   = (const float*)d_in[3];
    const float* maxa    = (const float*)d_in[4];
    const float* Wh_emb  = (const float*)d_in[5];
    const float* bh_emb  = (const float*)d_in[6];
    const float* We_emb  = (const float*)d_in[7];
    const float* be_emb  = (const float*)d_in[8];
    const float* WA      = (const float*)d_in[9];
    const float* bA      = (const float*)d_in[10];
    const float* WB      = (const float*)d_in[11];
    const float* bB      = (const float*)d_in[12];
    const float* WC      = (const float*)d_in[13];
    const float* bC      = (const float*)d_in[14];
    const float* WD      = (const float*)d_in[15];
    const float* bD      = (const float*)d_in[16];
    const float* WE      = (const float*)d_in[17];
    const float* bE      = (const float*)d_in[18];
    const float* bn_h_g  = (const float*)d_in[19];
    const float* bn_h_b  = (const float*)d_in[20];
    const float* bn_e_g  = (const float*)d_in[21];
    const float* bn_e_b  = (const float*)d_in[22];
    const float* W1      = (const float*)d_in[23];
    const float* b1      = (const float*)d_in[24];
    const float* W2      = (const float*)d_in[25];
    const float* b2      = (const float*)d_in[26];
    const int*   src     = (const int*)d_in[27];
    const int*   dst     = (const int*)d_in[28];
    float* out = (float*)d_out;

    static cudaStream_t s1 = nullptr;
    static cudaEvent_t ev0, evCSR, evDE[4], evAB[4];
    if (!s1) {
        cudaStreamCreateWithFlags(&s1, cudaStreamNonBlocking);
        cudaEventCreateWithFlags(&ev0, cudaEventDisableTiming);
        cudaEventCreateWithFlags(&evCSR, cudaEventDisableTiming);
        for (int i = 0; i < 4; i++) {
            cudaEventCreateWithFlags(&evDE[i], cudaEventDisableTiming);
            cudaEventCreateWithFlags(&evAB[i], cudaEventDisableTiming);
        }
    }

    float *WDE_base, *WAB_base;
    __nv_bfloat16* WtC_base;
    cudaGetSymbolAddress((void**)&WDE_base, g_WDE);
    cudaGetSymbolAddress((void**)&WAB_base, g_WAB);
    cudaGetSymbolAddress((void**)&WtC_base, g_WtC);

    cudaFuncSetAttribute(k_mat2, cudaFuncAttributeMaxDynamicSharedMemorySize, 110 * 1024);
    cudaFuncSetAttribute(k_edge, cudaFuncAttributeMaxDynamicSharedMemorySize, 64 * 1024);
    cudaFuncSetAttribute(k_head, cudaFuncAttributeMaxDynamicSharedMemorySize, 96 * 1024);

    const int smem_mat2 = (DD * WS2 + 64 * XSTR + 192) * 4;                     // 105216
    int smem_edge = (DD * WSTR + 128 * ESTRB) * 2;                              // 46592 (phase 1)
    int smem_p2   = 2 * 128 * ESTRB * 2;                                        // 53248 (phase 2)
    if (smem_p2 > smem_edge) smem_edge = smem_p2;
    const int smem_head = (DD * HIDN + 32 * DD + 32 * 132 + HIDN * OUTN) * 4;   // 82432

    // main: zero, then fork CSR chain onto s1 while main does prep
    k_zero<<<(NN + 255) / 256, 256>>>();
    cudaEventRecord(ev0, 0);
    cudaStreamWaitEvent(s1, ev0, 0);
    k_count<<<EE / 256, 256, 0, s1>>>(dst);
    k_scan1<<<NBS, 256, 0, s1>>>();
    k_scan2<<<1, 256, 0, s1>>>();
    k_scan3<<<NBS, 256, 0, s1>>>();
    k_fill<<<EE / 256, 256, 0, s1>>>(dst);
    k_sortperm<<<(NN + 127) / 128, 128, 0, s1>>>(src, dst);
    cudaEventRecord(evCSR, s1);

    const int prep_blks = EMB_BLKS + (184320 + 255) / 256;
    k_prep<<<prep_blks, 256>>>(h1, h2, z, Wh_emb, bh_emb, WA, WB, WC, WD, WE);

    const int ablk = (NN + 63) / 64;   // 782
    const int eblk = EE / 128;         // 6250

    for (int l = 0; l < 4; l++) {
        int lp = (l > 0) ? l - 1 : 0;
        k_mat2<<<ablk, 256, smem_mat2>>>(WDE_base + l * DD * 192,
                                         bD + l * DD, bE + l * DD,
                                         bn_h_g + lp * DD, bn_h_b + lp * DD,
                                         l, l >= 1 ? 1 : 0, 0);
        cudaEventRecord(evDE[l], 0);
        cudaStreamWaitEvent(s1, evDE[l], 0);
        k_mat2<<<ablk, 256, smem_mat2, s1>>>(WAB_base + l * DD * 192,
                                             bA + l * DD, bB + l * DD,
                                             bn_h_g, bn_h_b, l, 0, 1);
        cudaEventRecord(evAB[l], s1);

        if (l == 0) cudaStreamWaitEvent(0, evCSR, 0);
        int embed = (l == 0) ? 1 : 0;
        int apply = (l >= 1) ? 1 : 0;
        int write_e = (l >= 1 && l < 3) ? 1 : 0;
        int do_stats = (l < 3) ? 1 : 0;
        k_edge<<<eblk, 256, smem_edge>>>(WtC_base + l * DD * DD, bC + l * DD,
                                         efeat, We_emb, be_emb,
                                         bn_e_g + lp * DD, bn_e_b + lp * DD,
                                         l, embed, apply, write_e, do_stats);

        cudaStreamWaitEvent(0, evAB[l], 0);
        k_agg<<<NN / 8, 256>>>(l);
    }

    k_head<<<(NN + 31) / 32, 256, smem_head>>>(W1, b1, W2, b2, maxa,
                                               bn_h_g + 3 * DD, bn_h_b + 3 * DD, out);
}